// round 5
// baseline (speedup 1.0000x reference)
#include <cuda_runtime.h>
#include <cstdint>

#define BB 4
#define TT 2048
#define DD 512
#define HH 8
#define DK 64
#define BHN (BB*HH)          // 32
#define MROWS (BB*TT)        // 8192

// ---------------- scratch ----------------
__device__ unsigned long long g_qb[BHN*TT];
__device__ unsigned long long g_kb[BHN*TT];
__device__ unsigned long long g_vb[BHN*TT];
__device__ unsigned long long g_vT[BHN*DK*(TT/64)];   // [bh][d][w] bits over 64 k
__device__ unsigned char      g_xs[BB*TT*DD];         // scrambled X bytes

// ---------------- helpers ----------------
__device__ __forceinline__ unsigned long long pk2(float lo, float hi) {
    unsigned long long r;
    asm("mov.b64 %0, {%1,%2};" : "=l"(r) : "f"(lo), "f"(hi));
    return r;
}
__device__ __forceinline__ void unpk2(unsigned long long v, float& lo, float& hi) {
    asm("mov.b64 {%0,%1}, %2;" : "=f"(lo), "=f"(hi) : "l"(v));
}
__device__ __forceinline__ void fma2(unsigned long long& d, unsigned long long a,
                                     unsigned long long b) {
    asm("fma.rn.f32x2 %0, %1, %2, %0;" : "+l"(d) : "l"(a), "l"(b));
}
__device__ __forceinline__ unsigned expand4(unsigned x) {   // 4 bits -> 4 bytes
    return (x * 0x00204081u) & 0x01010101u;
}
__device__ __forceinline__ void mma_s8(int* c, unsigned a0, unsigned a1, unsigned a2,
                                       unsigned a3, unsigned b0, unsigned b1) {
    asm volatile(
        "mma.sync.aligned.m16n8k32.row.col.s32.s8.s8.s32 "
        "{%0,%1,%2,%3}, {%4,%5,%6,%7}, {%8,%9}, {%0,%1,%2,%3};"
        : "+r"(c[0]), "+r"(c[1]), "+r"(c[2]), "+r"(c[3])
        : "r"(a0), "r"(a1), "r"(a2), "r"(a3), "r"(b0), "r"(b1));
}

// =====================================================================
// Fused q/k/v projection + spike + bitpack.
// Warp layout: warp w (0..7) owns n-stripe w*16..w*16+16 over ALL 128 m.
// Lane owns m = lane*4..+4 (pairs along m). Per kk: A = 1x LDS.128,
// W = 8x broadcast LDS.128 (pre-duplicated pairs) -> crossbar 12 wf/warp/kk
// vs 16 FMA-cycles -> FMA-bound. acc order over k unchanged (bit-exact).
// =====================================================================
__global__ __launch_bounds__(256, 2) void qkv_proj_kernel(
    const float* __restrict__ Aq, const float* __restrict__ Ak,
    const float* __restrict__ Av,
    const float* __restrict__ Wq, const float* __restrict__ Wk,
    const float* __restrict__ Wv,
    const float* __restrict__ bq, const float* __restrict__ bk,
    const float* __restrict__ bv, int DIN)
{
    __shared__ float Ash[16][132];                 // [k][m]
    __shared__ unsigned long long Wd[16][136];     // [k][n] duplicated pairs
    __shared__ unsigned short stage[128][12];      // [m][warp] 16-bit spike chunks

    const int tid  = threadIdx.x;
    const int lane = tid & 31;
    const int wrp  = tid >> 5;                     // 0..7

    int idx = blockIdx.x;
    int which, m0, n0, K;
    const float *A, *W, *bias;
    if (idx < 512) {
        which = 1 + (idx & 1);
        int s = idx >> 1;
        m0 = (s >> 2) << 7; n0 = (s & 3) << 7; K = DD;
    } else {
        which = 0;
        int s = idx - 512;
        m0 = (s >> 2) << 7; n0 = (s & 3) << 7; K = DIN;
    }
    A    = (which == 0) ? Aq : (which == 1) ? Ak : Av;
    W    = (which == 0) ? Wq : (which == 1) ? Wk : Wv;
    bias = (which == 0) ? bq : (which == 1) ? bk : bv;

    unsigned long long acc[2][16];
#pragma unroll
    for (int mp = 0; mp < 2; mp++)
#pragma unroll
        for (int n = 0; n < 16; n++) acc[mp][n] = 0ull;

    const int amm = tid >> 1, akoff = (tid & 1) * 8;
    const int wkk = tid >> 4, wnoff = (tid & 15) * 8;

    for (int k0 = 0; k0 < K; k0 += 16) {
        // ---- A tile -> Ash[k][m] ----
        if (K == DD) {
            const float4* ap = (const float4*)(A + (size_t)(m0 + amm) * DD + k0 + akoff);
            float4 v0 = ap[0], v1 = ap[1];
            Ash[akoff + 0][amm] = v0.x; Ash[akoff + 1][amm] = v0.y;
            Ash[akoff + 2][amm] = v0.z; Ash[akoff + 3][amm] = v0.w;
            Ash[akoff + 4][amm] = v1.x; Ash[akoff + 5][amm] = v1.y;
            Ash[akoff + 6][amm] = v1.z; Ash[akoff + 7][amm] = v1.w;
        } else {
#pragma unroll
            for (int j = 0; j < 8; j++) {
                int kk = k0 + akoff + j;
                Ash[akoff + j][amm] = (kk < K) ? A[(size_t)(m0 + amm) * K + kk] : 0.f;
            }
        }
        // ---- W tile -> Wd[k][n] duplicated ----
        if (k0 + wkk < K) {
            const float4* wp = (const float4*)(W + (size_t)(k0 + wkk) * DD + n0 + wnoff);
            float4 w0 = wp[0], w1 = wp[1];
            Wd[wkk][wnoff + 0] = pk2(w0.x, w0.x);
            Wd[wkk][wnoff + 1] = pk2(w0.y, w0.y);
            Wd[wkk][wnoff + 2] = pk2(w0.z, w0.z);
            Wd[wkk][wnoff + 3] = pk2(w0.w, w0.w);
            Wd[wkk][wnoff + 4] = pk2(w1.x, w1.x);
            Wd[wkk][wnoff + 5] = pk2(w1.y, w1.y);
            Wd[wkk][wnoff + 6] = pk2(w1.z, w1.z);
            Wd[wkk][wnoff + 7] = pk2(w1.w, w1.w);
        } else {
#pragma unroll
            for (int j = 0; j < 8; j++) Wd[wkk][wnoff + j] = 0ull;
        }
        __syncthreads();
#pragma unroll
        for (int kk = 0; kk < 16; ++kk) {
            ulonglong2 a = *(const ulonglong2*)&Ash[kk][lane * 4];
            unsigned long long wn[16];
#pragma unroll
            for (int i = 0; i < 8; i++) {
                ulonglong2 t = *(const ulonglong2*)&Wd[kk][wrp * 16 + 2 * i];
                wn[2 * i] = t.x; wn[2 * i + 1] = t.y;
            }
#pragma unroll
            for (int n = 0; n < 16; n++) {
                fma2(acc[0][n], a.x, wn[n]);
                fma2(acc[1][n], a.y, wn[n]);
            }
        }
        __syncthreads();
    }

    // ---- spike -> 16-bit chunks in stage[m][warp] ----
#pragma unroll
    for (int r = 0; r < 4; r++) {
        int mp = r >> 1, sel = r & 1;
        unsigned bits = 0;
#pragma unroll
        for (int n = 0; n < 16; n++) {
            float lo, hi; unpk2(acc[mp][n], lo, hi);
            float v = sel ? hi : lo;
            float bn = bias[n0 + wrp * 16 + n];
            if (v + bn >= 1.0f) bits |= 1u << n;
        }
        stage[lane * 4 + r][wrp] = (unsigned short)bits;
    }
    __syncthreads();

    // ---- repack: u64 per (row, head-half) ----
    {
        int row = tid >> 1, hf = tid & 1;
        unsigned long long bits = *(const unsigned long long*)&stage[row][hf * 4];
        int m = m0 + row;
        int b = m >> 11, t = m & 2047;
        int head = (n0 >> 6) + hf;
        unsigned long long* dst = (which == 0) ? g_qb : (which == 1) ? g_kb : g_vb;
        dst[(size_t)((b << 3) + head) * TT + t] = bits;
    }
}

// ---------------- v bit transpose ----------------
__global__ void vtrans_kernel()
{
    int bx = blockIdx.x;
    int bh = bx >> 5, w = bx & 31;
    int tid = threadIdx.x;
    int lane = tid & 31, warp = tid >> 5;
    __shared__ unsigned sh[64][2];
    unsigned long long r = g_vb[(size_t)bh * TT + w * 64 + tid];
#pragma unroll 8
    for (int d = 0; d < 64; d++) {
        unsigned b = __ballot_sync(0xffffffffu, (unsigned)((r >> d) & 1ull));
        if (lane == 0) sh[d][warp] = b;
    }
    __syncthreads();
    g_vT[(size_t)(bh * 64 + tid) * 32 + w] =
        (unsigned long long)sh[tid][0] | ((unsigned long long)sh[tid][1] << 32);
}

// =====================================================================
// Attention: QK popcount -> s8 cnt tile -> PV via IMMA (exact).
// =====================================================================
__global__ __launch_bounds__(128) void attn_kernel(const float* __restrict__ scale_p)
{
    const int tid = threadIdx.x;
    const int lane = tid & 31;
    const int warpid = tid >> 5;
    const int g = lane >> 2, tg = lane & 3;
    const int rowA = warpid * 16 + g;

    int bx = blockIdx.x;
    int bh = bx & 31;
    int tq = 31 - (bx >> 5);          // big tiles first

    __shared__ unsigned long long qsh[64];
    __shared__ unsigned long long ksh[64];
    __shared__ unsigned char csh[64 * 68];

    const float scale = *scale_p;
    const size_t base = (size_t)bh * TT;

    if (tid < 64) qsh[tid] = g_qb[base + (size_t)tq * 64 + tid];

    int acc[8][4];
#pragma unroll
    for (int nt = 0; nt < 8; nt++)
#pragma unroll
        for (int r = 0; r < 4; r++) acc[nt][r] = 0;

    const int tQ = tid >> 1;
    const int khalf = tid & 1;

    for (int w = 0; w <= tq; ++w) {
        __syncthreads();
        if (tid < 64) ksh[tid] = g_kb[base + (size_t)w * 64 + tid];
        unsigned long long vt[8];
#pragma unroll
        for (int nt = 0; nt < 8; ++nt)
            vt[nt] = g_vT[((size_t)bh * 64 + nt * 8 + g) * 32 + w];
        __syncthreads();

        {
            unsigned long long q = qsh[tQ];
            const bool diag = (w == tq);
#pragma unroll 2
            for (int k4 = 0; k4 < 32; k4 += 4) {
                unsigned pack = 0;
#pragma unroll
                for (int j = 0; j < 4; ++j) {
                    int kc = khalf * 32 + k4 + j;
                    int c = __popcll(q & ksh[kc]);
                    if (diag && kc > tQ) c = 0;
                    pack |= (unsigned)c << (8 * j);
                }
                *(unsigned*)&csh[tQ * 68 + khalf * 32 + k4] = pack;
            }
        }
        __syncthreads();

#pragma unroll
        for (int s = 0; s < 2; ++s) {
            unsigned a0 = *(const unsigned*)&csh[rowA * 68 + s * 32 + tg * 4];
            unsigned a1 = *(const unsigned*)&csh[(rowA + 8) * 68 + s * 32 + tg * 4];
            unsigned a2 = *(const unsigned*)&csh[rowA * 68 + s * 32 + 16 + tg * 4];
            unsigned a3 = *(const unsigned*)&csh[(rowA + 8) * 68 + s * 32 + 16 + tg * 4];
#pragma unroll
            for (int nt = 0; nt < 8; ++nt) {
                unsigned b0 = expand4((unsigned)(vt[nt] >> (s * 32 + tg * 4)) & 0xFu);
                unsigned b1 = expand4((unsigned)(vt[nt] >> (s * 32 + 16 + tg * 4)) & 0xFu);
                mma_s8(acc[nt], a0, a1, a2, a3, b0, b1);
            }
        }
    }

    __syncthreads();
#pragma unroll
    for (int nt = 0; nt < 8; ++nt) {
        int d0 = nt * 8 + tg * 2;
        csh[d0 * 68 + rowA]           = ((float)acc[nt][0] * scale >= 1.0f) ? 1 : 0;
        csh[(d0 + 1) * 68 + rowA]     = ((float)acc[nt][1] * scale >= 1.0f) ? 1 : 0;
        csh[d0 * 68 + rowA + 8]       = ((float)acc[nt][2] * scale >= 1.0f) ? 1 : 0;
        csh[(d0 + 1) * 68 + rowA + 8] = ((float)acc[nt][3] * scale >= 1.0f) ? 1 : 0;
    }
    __syncthreads();
    {
        int d = tid >> 1, hf = tid & 1;
        size_t b = (size_t)(bh >> 3), h = (size_t)(bh & 7);
        size_t off = (b << 20) + (h << 17) + ((size_t)d << 11)
                   + (size_t)tq * 64 + (size_t)hf * 32;
#pragma unroll
        for (int q4 = 0; q4 < 32; q4 += 4) {
            unsigned v = *(const unsigned*)&csh[d * 68 + hf * 32 + q4];
            *(unsigned*)(g_xs + off + q4) = v;
        }
    }
}

// =====================================================================
// Output projection: same warp-broadcast GEMM body, binary A from g_xs.
// =====================================================================
__global__ __launch_bounds__(256, 2) void out_proj_kernel(
    const float* __restrict__ W, const float* __restrict__ bias,
    float* __restrict__ out)
{
    __shared__ float Ash[16][132];
    __shared__ unsigned long long Wd[16][136];

    const int tid  = threadIdx.x;
    const int lane = tid & 31;
    const int wrp  = tid >> 5;
    const int m0 = blockIdx.y * 128, n0 = blockIdx.x * 128;

    unsigned long long acc[2][16];
#pragma unroll
    for (int mp = 0; mp < 2; mp++)
#pragma unroll
        for (int n = 0; n < 16; n++) acc[mp][n] = 0ull;

    const int amm = tid >> 1, akoff = (tid & 1) * 8;
    const int wkk = tid >> 4, wnoff = (tid & 15) * 8;

    for (int k0 = 0; k0 < DD; k0 += 16) {
        unsigned long long xu =
            *(const unsigned long long*)(g_xs + (size_t)(m0 + amm) * DD + k0 + akoff);
#pragma unroll
        for (int j = 0; j < 8; j++)
            Ash[akoff + j][amm] = (float)(int)((xu >> (8 * j)) & 1ull);
        {
            const float4* wp = (const float4*)(W + (size_t)(k0 + wkk) * DD + n0 + wnoff);
            float4 w0 = wp[0], w1 = wp[1];
            Wd[wkk][wnoff + 0] = pk2(w0.x, w0.x);
            Wd[wkk][wnoff + 1] = pk2(w0.y, w0.y);
            Wd[wkk][wnoff + 2] = pk2(w0.z, w0.z);
            Wd[wkk][wnoff + 3] = pk2(w0.w, w0.w);
            Wd[wkk][wnoff + 4] = pk2(w1.x, w1.x);
            Wd[wkk][wnoff + 5] = pk2(w1.y, w1.y);
            Wd[wkk][wnoff + 6] = pk2(w1.z, w1.z);
            Wd[wkk][wnoff + 7] = pk2(w1.w, w1.w);
        }
        __syncthreads();
#pragma unroll
        for (int kk = 0; kk < 16; ++kk) {
            ulonglong2 a = *(const ulonglong2*)&Ash[kk][lane * 4];
            unsigned long long wn[16];
#pragma unroll
            for (int i = 0; i < 8; i++) {
                ulonglong2 t = *(const ulonglong2*)&Wd[kk][wrp * 16 + 2 * i];
                wn[2 * i] = t.x; wn[2 * i + 1] = t.y;
            }
#pragma unroll
            for (int n = 0; n < 16; n++) {
                fma2(acc[0][n], a.x, wn[n]);
                fma2(acc[1][n], a.y, wn[n]);
            }
        }
        __syncthreads();
    }

    // ---- spike + store ----
#pragma unroll
    for (int r = 0; r < 4; r++) {
        int mp = r >> 1, sel = r & 1;
        int m = m0 + lane * 4 + r;
#pragma unroll
        for (int c4 = 0; c4 < 4; c4++) {
            float4 b4 = *(const float4*)&bias[n0 + wrp * 16 + c4 * 4];
            float v[4];
#pragma unroll
            for (int j = 0; j < 2; j++) {
                float lo, hi;
                unpk2(acc[mp][c4 * 4 + 2 * j], lo, hi);
                float x0 = sel ? 0.f : lo;   // lo/hi here pair over m!
                (void)x0;
                v[2 * j]     = sel ? hi : lo;
                unpk2(acc[mp][c4 * 4 + 2 * j + 1], lo, hi);
                v[2 * j + 1] = sel ? hi : lo;
            }
            float4 rr;
            rr.x = (v[0] + b4.x >= 1.0f) ? 1.0f : 0.0f;
            rr.y = (v[1] + b4.y >= 1.0f) ? 1.0f : 0.0f;
            rr.z = (v[2] + b4.z >= 1.0f) ? 1.0f : 0.0f;
            rr.w = (v[3] + b4.w >= 1.0f) ? 1.0f : 0.0f;
            *(float4*)&out[(size_t)m * DD + n0 + wrp * 16 + c4 * 4] = rr;
        }
    }
}

// ---------------- launch ----------------
extern "C" void kernel_launch(void* const* d_in, const int* in_sizes, int n_in,
                              void* d_out, int out_size)
{
    const float* query = (const float*)d_in[0];
    const float* key   = (const float*)d_in[1];
    const float* value = (const float*)d_in[2];
    const float* scale = (const float*)d_in[3];
    const float* Wq = (const float*)d_in[4];  const float* bq = (const float*)d_in[5];
    const float* Wk = (const float*)d_in[6];  const float* bk = (const float*)d_in[7];
    const float* Wv = (const float*)d_in[8];  const float* bv = (const float*)d_in[9];
    const float* Wo = (const float*)d_in[10]; const float* bo = (const float*)d_in[11];
    float* out = (float*)d_out;

    const int DIN = in_sizes[0] / MROWS;   // 100

    qkv_proj_kernel<<<768, 256>>>(query, key, value, Wq, Wk, Wv, bq, bk, bv, DIN);
    vtrans_kernel<<<BHN * (TT / 64), 64>>>();
    attn_kernel<<<BHN * (TT / 64), 128>>>(scale);
    out_proj_kernel<<<dim3(4, 64), 256>>>(Wo, bo, out);
}

// round 6
// speedup vs baseline: 1.1926x; 1.1926x over previous
#include <cuda_runtime.h>
#include <cstdint>

#define BB 4
#define TT 2048
#define DD 512
#define HH 8
#define DK 64
#define BHN (BB*HH)          // 32
#define MROWS (BB*TT)        // 8192
#define AST 24               // smem k-stride (bf16 units): conflict-free + 16B-aligned rows

// ---------------- scratch ----------------
__device__ unsigned long long g_qb[BHN*TT];
__device__ unsigned long long g_kb[BHN*TT];
__device__ unsigned long long g_vb[BHN*TT];
__device__ unsigned long long g_vT[BHN*DK*(TT/64)];   // [bh][d][w] bits over 64 k
__device__ unsigned char      g_xs[BB*TT*DD];         // scrambled X bytes

// ---------------- helpers ----------------
__device__ __forceinline__ unsigned expand4(unsigned x) {   // 4 bits -> 4 bytes
    return (x * 0x00204081u) & 0x01010101u;
}
__device__ __forceinline__ void mma_s8(int* c, unsigned a0, unsigned a1, unsigned a2,
                                       unsigned a3, unsigned b0, unsigned b1) {
    asm volatile(
        "mma.sync.aligned.m16n8k32.row.col.s32.s8.s8.s32 "
        "{%0,%1,%2,%3}, {%4,%5,%6,%7}, {%8,%9}, {%0,%1,%2,%3};"
        : "+r"(c[0]), "+r"(c[1]), "+r"(c[2]), "+r"(c[3])
        : "r"(a0), "r"(a1), "r"(a2), "r"(a3), "r"(b0), "r"(b1));
}
__device__ __forceinline__ void mma_bf16(float* c, unsigned a0, unsigned a1,
                                         unsigned a2, unsigned a3,
                                         unsigned b0, unsigned b1) {
    asm volatile(
        "mma.sync.aligned.m16n8k16.row.col.f32.bf16.bf16.f32 "
        "{%0,%1,%2,%3}, {%4,%5,%6,%7}, {%8,%9}, {%0,%1,%2,%3};"
        : "+f"(c[0]), "+f"(c[1]), "+f"(c[2]), "+f"(c[3])
        : "r"(a0), "r"(a1), "r"(a2), "r"(a3), "r"(b0), "r"(b1));
}
// exact 3-way bf16 split by truncation: a = b0 + b1 + b2 (+ residual < 2^-24|a|)
__device__ __forceinline__ void split3(float a, unsigned short& s0,
                                       unsigned short& s1, unsigned short& s2) {
    unsigned u0 = __float_as_uint(a);
    s0 = (unsigned short)(u0 >> 16);
    float r1 = a - __uint_as_float(u0 & 0xFFFF0000u);
    unsigned u1 = __float_as_uint(r1);
    s1 = (unsigned short)(u1 >> 16);
    float r2 = r1 - __uint_as_float(u1 & 0xFFFF0000u);
    s2 = (unsigned short)(__float_as_uint(r2) >> 16);
}

// =====================================================================
// qkv projection via bf16x6 MMA emulation. Block tile 128m x 64n, 256 thr,
// 8 warps (4m x 2n), warp tile m32 x n32. k-chunk 16.
// grid 1536: [0,512)=k, [512,1024)=v, [1024,1536)=q (light tail).
// n varies fastest within each GEMM -> A tile L2 reuse.
// =====================================================================
__global__ __launch_bounds__(256, 2) void qkv_mma_kernel(
    const float* __restrict__ Aq, const float* __restrict__ Ak,
    const float* __restrict__ Av,
    const float* __restrict__ Wq, const float* __restrict__ Wk,
    const float* __restrict__ Wv,
    const float* __restrict__ bq, const float* __restrict__ bk,
    const float* __restrict__ bv, int DIN)
{
    __shared__ unsigned short Asp[3][128][AST];   // 18 KB
    __shared__ unsigned short Wsp[3][64][AST];    //  9 KB
    __shared__ unsigned char  sbyte[128][64];     //  8 KB

    const int tid  = threadIdx.x;
    const int lane = tid & 31;
    const int g    = lane >> 2, tg = lane & 3;
    const int wrp  = tid >> 5;
    const int mw   = wrp >> 1, nw = wrp & 1;      // warp grid 4m x 2n

    int idx = blockIdx.x;
    int which = idx >> 9;                          // 0=k,1=v,2=q
    int s = idx & 511;
    int n0 = (s & 7) * 64, m0 = (s >> 3) * 128;
    const float* A    = (which == 0) ? Ak : (which == 1) ? Av : Aq;
    const float* W    = (which == 0) ? Wk : (which == 1) ? Wv : Wq;
    const float* bias = (which == 0) ? bk : (which == 1) ? bv : bq;
    const int K = (which == 2) ? DIN : DD;

    float C[2][4][4];
#pragma unroll
    for (int mt = 0; mt < 2; mt++)
#pragma unroll
        for (int nt = 0; nt < 4; nt++)
#pragma unroll
            for (int r = 0; r < 4; r++) C[mt][nt][r] = 0.f;

    const int arow = tid >> 1, akq = (tid & 1) * 8;   // A loader map
    const int wn = tid >> 2, wkq = (tid & 3) * 4;     // W loader map

    const int nchunks = (K + 15) >> 4;
    for (int ch = 0; ch < nchunks; ++ch) {
        const int k0 = ch << 4;
        __syncthreads();
        // ---- A loader: 8 fp32 -> 3 bf16 splits each ----
        {
            float v[8];
            if (K == DD) {
                const float4* ap = (const float4*)(A + (size_t)(m0 + arow) * DD + k0 + akq);
                float4 x = ap[0], y = ap[1];
                v[0]=x.x; v[1]=x.y; v[2]=x.z; v[3]=x.w;
                v[4]=y.x; v[5]=y.y; v[6]=y.z; v[7]=y.w;
            } else {
#pragma unroll
                for (int j = 0; j < 8; j++) {
                    int k = k0 + akq + j;
                    v[j] = (k < K) ? A[(size_t)(m0 + arow) * K + k] : 0.f;
                }
            }
            unsigned short b0[8], b1[8], b2[8];
#pragma unroll
            for (int j = 0; j < 8; j++) split3(v[j], b0[j], b1[j], b2[j]);
#pragma unroll
            for (int j = 0; j < 8; j++) {
                Asp[0][arow][akq + j] = b0[j];
                Asp[1][arow][akq + j] = b1[j];
                Asp[2][arow][akq + j] = b2[j];
            }
        }
        // ---- W loader: 4 fp32 down a column -> splits, stored [n][k] ----
        {
#pragma unroll
            for (int j = 0; j < 4; j++) {
                int k = k0 + wkq + j;
                float wv = (k < K) ? W[(size_t)k * DD + n0 + wn] : 0.f;
                unsigned short t0, t1, t2;
                split3(wv, t0, t1, t2);
                Wsp[0][wn][wkq + j] = t0;
                Wsp[1][wn][wkq + j] = t1;
                Wsp[2][wn][wkq + j] = t2;
            }
        }
        __syncthreads();
        // ---- fragments ----
        unsigned af[3][2][4];
#pragma unroll
        for (int sp = 0; sp < 3; sp++)
#pragma unroll
            for (int mt = 0; mt < 2; mt++) {
                int r0 = mw * 32 + mt * 16 + g;
                af[sp][mt][0] = *(const unsigned*)&Asp[sp][r0][tg * 2];
                af[sp][mt][1] = *(const unsigned*)&Asp[sp][r0 + 8][tg * 2];
                af[sp][mt][2] = *(const unsigned*)&Asp[sp][r0][tg * 2 + 8];
                af[sp][mt][3] = *(const unsigned*)&Asp[sp][r0 + 8][tg * 2 + 8];
            }
#pragma unroll
        for (int j = 0; j < 3; j++) {
            unsigned bf[4][2];
#pragma unroll
            for (int nt = 0; nt < 4; nt++) {
                int nr = nw * 32 + nt * 8 + g;
                bf[nt][0] = *(const unsigned*)&Wsp[j][nr][tg * 2];
                bf[nt][1] = *(const unsigned*)&Wsp[j][nr][tg * 2 + 8];
            }
#pragma unroll
            for (int i = 0; i < 3; i++) {
                if (i + j > 2) break;
#pragma unroll
                for (int mt = 0; mt < 2; mt++)
#pragma unroll
                    for (int nt = 0; nt < 4; nt++)
                        mma_bf16(C[mt][nt], af[i][mt][0], af[i][mt][1],
                                 af[i][mt][2], af[i][mt][3],
                                 bf[nt][0], bf[nt][1]);
            }
        }
    }

    // ---- epilogue: bias + spike -> bytes -> bitpack u64 per (row, head) ----
    __syncthreads();
#pragma unroll
    for (int mt = 0; mt < 2; mt++)
#pragma unroll
        for (int nt = 0; nt < 4; nt++) {
            int row = mw * 32 + mt * 16 + g;
            int col = nw * 32 + nt * 8 + tg * 2;
            float2 bb = *(const float2*)&bias[n0 + col];
            sbyte[row][col]         = (C[mt][nt][0] + bb.x >= 1.0f) ? 1 : 0;
            sbyte[row][col + 1]     = (C[mt][nt][1] + bb.y >= 1.0f) ? 1 : 0;
            sbyte[row + 8][col]     = (C[mt][nt][2] + bb.x >= 1.0f) ? 1 : 0;
            sbyte[row + 8][col + 1] = (C[mt][nt][3] + bb.y >= 1.0f) ? 1 : 0;
        }
    __syncthreads();
    if (tid < 128) {
        unsigned long long bits = 0ull;
#pragma unroll
        for (int q = 0; q < 8; q++) {
            unsigned long long u = *(const unsigned long long*)&sbyte[tid][8 * q];
#pragma unroll
            for (int j = 0; j < 8; j++)
                bits |= ((u >> (8 * j)) & 1ull) << (8 * q + j);
        }
        int m = m0 + tid;
        int b = m >> 11, t = m & 2047;
        int head = n0 >> 6;
        unsigned long long* dst = (which == 2) ? g_qb : (which == 0) ? g_kb : g_vb;
        dst[(size_t)((b << 3) + head) * TT + t] = bits;
    }
}

// =====================================================================
// Output projection: A binary (no split) x W 3-split -> 3 passes.
// =====================================================================
__global__ __launch_bounds__(256, 2) void out_mma_kernel(
    const float* __restrict__ W, const float* __restrict__ bias,
    float* __restrict__ out)
{
    __shared__ unsigned short Asp[128][AST];      // 6 KB
    __shared__ unsigned short Wsp[3][64][AST];    // 9 KB

    const int tid  = threadIdx.x;
    const int lane = tid & 31;
    const int g    = lane >> 2, tg = lane & 3;
    const int wrp  = tid >> 5;
    const int mw   = wrp >> 1, nw = wrp & 1;

    int s = blockIdx.x;
    int n0 = (s & 7) * 64, m0 = (s >> 3) * 128;

    float C[2][4][4];
#pragma unroll
    for (int mt = 0; mt < 2; mt++)
#pragma unroll
        for (int nt = 0; nt < 4; nt++)
#pragma unroll
            for (int r = 0; r < 4; r++) C[mt][nt][r] = 0.f;

    const int arow = tid >> 1, akq = (tid & 1) * 8;
    const int wn = tid >> 2, wkq = (tid & 3) * 4;

    for (int ch = 0; ch < 32; ++ch) {
        const int k0 = ch << 4;
        __syncthreads();
        {
            unsigned long long u =
                *(const unsigned long long*)(g_xs + (size_t)(m0 + arow) * DD + k0 + akq);
#pragma unroll
            for (int j = 0; j < 8; j++)
                Asp[arow][akq + j] =
                    (unsigned short)(((u >> (8 * j)) & 1ull) ? 0x3F80u : 0u);
        }
        {
#pragma unroll
            for (int j = 0; j < 4; j++) {
                int k = k0 + wkq + j;
                float wv = W[(size_t)k * DD + n0 + wn];
                unsigned short t0, t1, t2;
                split3(wv, t0, t1, t2);
                Wsp[0][wn][wkq + j] = t0;
                Wsp[1][wn][wkq + j] = t1;
                Wsp[2][wn][wkq + j] = t2;
            }
        }
        __syncthreads();
        unsigned af[2][4];
#pragma unroll
        for (int mt = 0; mt < 2; mt++) {
            int r0 = mw * 32 + mt * 16 + g;
            af[mt][0] = *(const unsigned*)&Asp[r0][tg * 2];
            af[mt][1] = *(const unsigned*)&Asp[r0 + 8][tg * 2];
            af[mt][2] = *(const unsigned*)&Asp[r0][tg * 2 + 8];
            af[mt][3] = *(const unsigned*)&Asp[r0 + 8][tg * 2 + 8];
        }
#pragma unroll
        for (int j = 0; j < 3; j++) {
            unsigned bf[4][2];
#pragma unroll
            for (int nt = 0; nt < 4; nt++) {
                int nr = nw * 32 + nt * 8 + g;
                bf[nt][0] = *(const unsigned*)&Wsp[j][nr][tg * 2];
                bf[nt][1] = *(const unsigned*)&Wsp[j][nr][tg * 2 + 8];
            }
#pragma unroll
            for (int mt = 0; mt < 2; mt++)
#pragma unroll
                for (int nt = 0; nt < 4; nt++)
                    mma_bf16(C[mt][nt], af[mt][0], af[mt][1], af[mt][2], af[mt][3],
                             bf[nt][0], bf[nt][1]);
        }
    }

    // ---- epilogue: bias + spike -> fp32 out ----
#pragma unroll
    for (int mt = 0; mt < 2; mt++)
#pragma unroll
        for (int nt = 0; nt < 4; nt++) {
            int row = m0 + mw * 32 + mt * 16 + g;
            int col = n0 + nw * 32 + nt * 8 + tg * 2;
            float2 bb = *(const float2*)&bias[col];
            float2 r0, r1;
            r0.x = (C[mt][nt][0] + bb.x >= 1.0f) ? 1.0f : 0.0f;
            r0.y = (C[mt][nt][1] + bb.y >= 1.0f) ? 1.0f : 0.0f;
            r1.x = (C[mt][nt][2] + bb.x >= 1.0f) ? 1.0f : 0.0f;
            r1.y = (C[mt][nt][3] + bb.y >= 1.0f) ? 1.0f : 0.0f;
            *(float2*)&out[(size_t)row * DD + col] = r0;
            *(float2*)&out[(size_t)(row + 8) * DD + col] = r1;
        }
}

// ---------------- v bit transpose ----------------
__global__ void vtrans_kernel()
{
    int bx = blockIdx.x;
    int bh = bx >> 5, w = bx & 31;
    int tid = threadIdx.x;
    int lane = tid & 31, warp = tid >> 5;
    __shared__ unsigned sh[64][2];
    unsigned long long r = g_vb[(size_t)bh * TT + w * 64 + tid];
#pragma unroll 8
    for (int d = 0; d < 64; d++) {
        unsigned b = __ballot_sync(0xffffffffu, (unsigned)((r >> d) & 1ull));
        if (lane == 0) sh[d][warp] = b;
    }
    __syncthreads();
    g_vT[(size_t)(bh * 64 + tid) * 32 + w] =
        (unsigned long long)sh[tid][0] | ((unsigned long long)sh[tid][1] << 32);
}

// =====================================================================
// Attention: QK popcount -> s8 cnt tile -> PV via IMMA (exact). Unchanged.
// =====================================================================
__global__ __launch_bounds__(128) void attn_kernel(const float* __restrict__ scale_p)
{
    const int tid = threadIdx.x;
    const int lane = tid & 31;
    const int warpid = tid >> 5;
    const int g = lane >> 2, tg = lane & 3;
    const int rowA = warpid * 16 + g;

    int bx = blockIdx.x;
    int bh = bx & 31;
    int tq = 31 - (bx >> 5);          // big tiles first

    __shared__ unsigned long long qsh[64];
    __shared__ unsigned long long ksh[64];
    __shared__ unsigned char csh[64 * 68];

    const float scale = *scale_p;
    const size_t base = (size_t)bh * TT;

    if (tid < 64) qsh[tid] = g_qb[base + (size_t)tq * 64 + tid];

    int acc[8][4];
#pragma unroll
    for (int nt = 0; nt < 8; nt++)
#pragma unroll
        for (int r = 0; r < 4; r++) acc[nt][r] = 0;

    const int tQ = tid >> 1;
    const int khalf = tid & 1;

    for (int w = 0; w <= tq; ++w) {
        __syncthreads();
        if (tid < 64) ksh[tid] = g_kb[base + (size_t)w * 64 + tid];
        unsigned long long vt[8];
#pragma unroll
        for (int nt = 0; nt < 8; ++nt)
            vt[nt] = g_vT[((size_t)bh * 64 + nt * 8 + g) * 32 + w];
        __syncthreads();

        {
            unsigned long long q = qsh[tQ];
            const bool diag = (w == tq);
#pragma unroll 2
            for (int k4 = 0; k4 < 32; k4 += 4) {
                unsigned pack = 0;
#pragma unroll
                for (int j = 0; j < 4; ++j) {
                    int kc = khalf * 32 + k4 + j;
                    int c = __popcll(q & ksh[kc]);
                    if (diag && kc > tQ) c = 0;
                    pack |= (unsigned)c << (8 * j);
                }
                *(unsigned*)&csh[tQ * 68 + khalf * 32 + k4] = pack;
            }
        }
        __syncthreads();

#pragma unroll
        for (int s = 0; s < 2; ++s) {
            unsigned a0 = *(const unsigned*)&csh[rowA * 68 + s * 32 + tg * 4];
            unsigned a1 = *(const unsigned*)&csh[(rowA + 8) * 68 + s * 32 + tg * 4];
            unsigned a2 = *(const unsigned*)&csh[rowA * 68 + s * 32 + 16 + tg * 4];
            unsigned a3 = *(const unsigned*)&csh[(rowA + 8) * 68 + s * 32 + 16 + tg * 4];
#pragma unroll
            for (int nt = 0; nt < 8; ++nt) {
                unsigned b0 = expand4((unsigned)(vt[nt] >> (s * 32 + tg * 4)) & 0xFu);
                unsigned b1 = expand4((unsigned)(vt[nt] >> (s * 32 + 16 + tg * 4)) & 0xFu);
                mma_s8(acc[nt], a0, a1, a2, a3, b0, b1);
            }
        }
    }

    __syncthreads();
#pragma unroll
    for (int nt = 0; nt < 8; ++nt) {
        int d0 = nt * 8 + tg * 2;
        csh[d0 * 68 + rowA]           = ((float)acc[nt][0] * scale >= 1.0f) ? 1 : 0;
        csh[(d0 + 1) * 68 + rowA]     = ((float)acc[nt][1] * scale >= 1.0f) ? 1 : 0;
        csh[d0 * 68 + rowA + 8]       = ((float)acc[nt][2] * scale >= 1.0f) ? 1 : 0;
        csh[(d0 + 1) * 68 + rowA + 8] = ((float)acc[nt][3] * scale >= 1.0f) ? 1 : 0;
    }
    __syncthreads();
    {
        int d = tid >> 1, hf = tid & 1;
        size_t b = (size_t)(bh >> 3), h = (size_t)(bh & 7);
        size_t off = (b << 20) + (h << 17) + ((size_t)d << 11)
                   + (size_t)tq * 64 + (size_t)hf * 32;
#pragma unroll
        for (int q4 = 0; q4 < 32; q4 += 4) {
            unsigned v = *(const unsigned*)&csh[d * 68 + hf * 32 + q4];
            *(unsigned*)(g_xs + off + q4) = v;
        }
    }
}

// ---------------- launch ----------------
extern "C" void kernel_launch(void* const* d_in, const int* in_sizes, int n_in,
                              void* d_out, int out_size)
{
    const float* query = (const float*)d_in[0];
    const float* key   = (const float*)d_in[1];
    const float* value = (const float*)d_in[2];
    const float* scale = (const float*)d_in[3];
    const float* Wq = (const float*)d_in[4];  const float* bq = (const float*)d_in[5];
    const float* Wk = (const float*)d_in[6];  const float* bk = (const float*)d_in[7];
    const float* Wv = (const float*)d_in[8];  const float* bv = (const float*)d_in[9];
    const float* Wo = (const float*)d_in[10]; const float* bo = (const float*)d_in[11];
    float* out = (float*)d_out;

    const int DIN = in_sizes[0] / MROWS;   // 100

    qkv_mma_kernel<<<1536, 256>>>(query, key, value, Wq, Wk, Wv, bq, bk, bv, DIN);
    vtrans_kernel<<<BHN * (TT / 64), 64>>>();
    attn_kernel<<<BHN * (TT / 64), 128>>>(scale);
    out_mma_kernel<<<512, 256>>>(Wo, bo, out);
}

// round 8
// speedup vs baseline: 1.5259x; 1.2795x over previous
#include <cuda_runtime.h>
#include <cstdint>

#define BB 4
#define TT 2048
#define DD 512
#define HH 8
#define DK 64
#define BHN (BB*HH)          // 32
#define MROWS (BB*TT)        // 8192
#define SROW 40              // smem row stride (bf16 units) = 80B: 16B-aligned + LDSM conflict-free

// ---------------- scratch ----------------
__device__ unsigned long long g_qb[BHN*TT];
__device__ unsigned long long g_kb[BHN*TT];
__device__ unsigned long long g_vb[BHN*TT];
__device__ unsigned long long g_vT[BHN*DK*(TT/64)];
__device__ unsigned char      g_xs[BB*TT*DD];
__device__ unsigned short     g_wsp[4*3*512*512];    // pre-split W: [w][sp][n][k], 6 MB

// ---------------- helpers ----------------
__device__ __forceinline__ unsigned expand4(unsigned x) {
    return (x * 0x00204081u) & 0x01010101u;
}
__device__ __forceinline__ void mma_s8(int* c, unsigned a0, unsigned a1, unsigned a2,
                                       unsigned a3, unsigned b0, unsigned b1) {
    asm volatile(
        "mma.sync.aligned.m16n8k32.row.col.s32.s8.s8.s32 "
        "{%0,%1,%2,%3}, {%4,%5,%6,%7}, {%8,%9}, {%0,%1,%2,%3};"
        : "+r"(c[0]), "+r"(c[1]), "+r"(c[2]), "+r"(c[3])
        : "r"(a0), "r"(a1), "r"(a2), "r"(a3), "r"(b0), "r"(b1));
}
__device__ __forceinline__ void mma_bf16(float* c, unsigned a0, unsigned a1,
                                         unsigned a2, unsigned a3,
                                         unsigned b0, unsigned b1) {
    asm volatile(
        "mma.sync.aligned.m16n8k16.row.col.f32.bf16.bf16.f32 "
        "{%0,%1,%2,%3}, {%4,%5,%6,%7}, {%8,%9}, {%0,%1,%2,%3};"
        : "+f"(c[0]), "+f"(c[1]), "+f"(c[2]), "+f"(c[3])
        : "r"(a0), "r"(a1), "r"(a2), "r"(a3), "r"(b0), "r"(b1));
}
__device__ __forceinline__ void split3(float a, unsigned short& s0,
                                       unsigned short& s1, unsigned short& s2) {
    unsigned u0 = __float_as_uint(a);
    s0 = (unsigned short)(u0 >> 16);
    float r1 = a - __uint_as_float(u0 & 0xFFFF0000u);
    unsigned u1 = __float_as_uint(r1);
    s1 = (unsigned short)(u1 >> 16);
    float r2 = r1 - __uint_as_float(u1 & 0xFFFF0000u);
    s2 = (unsigned short)(__float_as_uint(r2) >> 16);
}
__device__ __forceinline__ void ldsm4(unsigned& r0, unsigned& r1, unsigned& r2,
                                      unsigned& r3, unsigned addr) {
    asm volatile("ldmatrix.sync.aligned.m8n8.x4.shared.b16 {%0,%1,%2,%3}, [%4];"
                 : "=r"(r0), "=r"(r1), "=r"(r2), "=r"(r3) : "r"(addr));
}
__device__ __forceinline__ void cpa16(unsigned dst, const void* src) {
    asm volatile("cp.async.cg.shared.global [%0], [%1], 16;" :: "r"(dst), "l"(src));
}
__device__ __forceinline__ void cp_commit_wait() {
    asm volatile("cp.async.commit_group;");
    asm volatile("cp.async.wait_group 0;" ::: "memory");
}

// =====================================================================
// prep: split W (transposed to [n][k]) into g_wsp. No local arrays.
// =====================================================================
__global__ void prep_w_kernel(const float* __restrict__ Wq, const float* __restrict__ Wk,
                              const float* __restrict__ Wv, const float* __restrict__ Wo)
{
    __shared__ float sh[64][68];
    int w = blockIdx.z;
    const float* W = (w == 0) ? Wq : (w == 1) ? Wk : (w == 2) ? Wv : Wo;
    int k0 = blockIdx.x * 64, n0 = blockIdx.y * 64;
    int t = threadIdx.x;
#pragma unroll
    for (int r = 0; r < 4; r++) {
        int row = (t >> 4) * 4 + r;
        int col = (t & 15) * 4;
        float4 v = *(const float4*)&W[(size_t)(k0 + row) * DD + n0 + col];
        sh[row][col] = v.x; sh[row][col+1] = v.y; sh[row][col+2] = v.z; sh[row][col+3] = v.w;
    }
    __syncthreads();
#pragma unroll
    for (int r = 0; r < 4; r++) {
        int n = (t >> 4) * 4 + r;
        int k4 = (t & 15) * 4;
        unsigned short a0, a1, a2, b0, b1, b2, c0, c1, c2, d0, d1, d2;
        split3(sh[k4 + 0][n], a0, a1, a2);
        split3(sh[k4 + 1][n], b0, b1, b2);
        split3(sh[k4 + 2][n], c0, c1, c2);
        split3(sh[k4 + 3][n], d0, d1, d2);
        size_t base = ((size_t)(w * 3) * 512 + (n0 + n)) * 512 + k0 + k4;
        const size_t P = (size_t)512 * 512;
        *(uint2*)&g_wsp[base] =
            make_uint2((unsigned)a0 | ((unsigned)b0 << 16),
                       (unsigned)c0 | ((unsigned)d0 << 16));
        *(uint2*)&g_wsp[base + P] =
            make_uint2((unsigned)a1 | ((unsigned)b1 << 16),
                       (unsigned)c1 | ((unsigned)d1 << 16));
        *(uint2*)&g_wsp[base + 2 * P] =
            make_uint2((unsigned)a2 | ((unsigned)b2 << 16),
                       (unsigned)c2 | ((unsigned)d2 << 16));
    }
}

// =====================================================================
// qkv GEMM: A split in-kernel (registers only), W pre-split via cp.async,
// LDSM fragments, k-chunk 32. Block 128m x 64n, 8 warps (4m x 2n).
// grid 1536: [0,512)=k, [512,1024)=v, [1024,1536)=q.
// =====================================================================
__global__ __launch_bounds__(256, 2) void qkv_mma_kernel(
    const float* __restrict__ Aq, const float* __restrict__ Ak,
    const float* __restrict__ Av,
    const float* __restrict__ bq, const float* __restrict__ bk,
    const float* __restrict__ bv, int DIN)
{
    __shared__ char smemraw[46080];   // A planes: [0,30720) 3x128xSROW u16; W: [30720,46080)

    const int tid  = threadIdx.x;
    const int lane = tid & 31;
    const int g    = lane >> 2, tg = lane & 3;
    const int wrp  = tid >> 5;
    const int mw   = wrp >> 1, nw = wrp & 1;

    int idx = blockIdx.x;
    int which = idx >> 9;                          // 0=k,1=v,2=q
    int s2 = idx & 511;
    int n0 = (s2 & 7) * 64, m0 = (s2 >> 3) * 128;

    const float* A    = (which == 0) ? Ak : (which == 1) ? Av : Aq;
    const float* bias = (which == 0) ? bk : (which == 1) ? bv : bq;
    const int KA = (which == 2) ? DIN : DD;        // real input K
    const int KS = (which == 2) ? 128 : DD;        // padded loop K
    const int wsel = (which == 0) ? 1 : (which == 1) ? 2 : 0;   // g_wsp order [q,k,v,o]
    const unsigned short* gW = g_wsp + (size_t)wsel * 3 * 512 * 512;

    const unsigned sbase = (unsigned)__cvta_generic_to_shared(smemraw);
    const unsigned wbase = sbase + 30720;

    float C[2][4][4];
#pragma unroll
    for (int mt = 0; mt < 2; mt++)
#pragma unroll
        for (int nt = 0; nt < 4; nt++)
#pragma unroll
            for (int r = 0; r < 4; r++) C[mt][nt][r] = 0.f;

    const int arow = tid >> 1, akh = (tid & 1) * 16;   // A loader: 16 k per thread
    const int arow_l = lane & 15;
    const int ak8 = (lane >> 4) * 8;
    const int brow = (lane & 7) + ((lane & 16) >> 1);
    const int bk8 = (lane & 8);

    const int nch = KS >> 5;
    for (int ch = 0; ch < nch; ++ch) {
        const int k0 = ch << 5;
        __syncthreads();
        // ---- A: load 16 fp32, split in registers, 2x STS.128 per plane ----
        {
            float v0,v1,v2,v3,v4,v5,v6,v7,v8,v9,va,vb,vc,vd,ve,vf;
            if (which != 2) {
                const float4* ap = (const float4*)(A + (size_t)(m0 + arow) * DD + k0 + akh);
                float4 x0 = ap[0], x1 = ap[1], x2 = ap[2], x3 = ap[3];
                v0=x0.x; v1=x0.y; v2=x0.z; v3=x0.w; v4=x1.x; v5=x1.y; v6=x1.z; v7=x1.w;
                v8=x2.x; v9=x2.y; va=x2.z; vb=x2.w; vc=x3.x; vd=x3.y; ve=x3.z; vf=x3.w;
            } else {
                const float* ar = A + (size_t)(m0 + arow) * KA;
                int kb = k0 + akh;
                v0 = (kb+0 < KA) ? ar[kb+0] : 0.f;  v1 = (kb+1 < KA) ? ar[kb+1] : 0.f;
                v2 = (kb+2 < KA) ? ar[kb+2] : 0.f;  v3 = (kb+3 < KA) ? ar[kb+3] : 0.f;
                v4 = (kb+4 < KA) ? ar[kb+4] : 0.f;  v5 = (kb+5 < KA) ? ar[kb+5] : 0.f;
                v6 = (kb+6 < KA) ? ar[kb+6] : 0.f;  v7 = (kb+7 < KA) ? ar[kb+7] : 0.f;
                v8 = (kb+8 < KA) ? ar[kb+8] : 0.f;  v9 = (kb+9 < KA) ? ar[kb+9] : 0.f;
                va = (kb+10 < KA) ? ar[kb+10] : 0.f; vb = (kb+11 < KA) ? ar[kb+11] : 0.f;
                vc = (kb+12 < KA) ? ar[kb+12] : 0.f; vd = (kb+13 < KA) ? ar[kb+13] : 0.f;
                ve = (kb+14 < KA) ? ar[kb+14] : 0.f; vf = (kb+15 < KA) ? ar[kb+15] : 0.f;
            }
            unsigned short h0[16], h1[16], h2[16];   // constant-indexed only
            split3(v0,h0[0],h1[0],h2[0]);   split3(v1,h0[1],h1[1],h2[1]);
            split3(v2,h0[2],h1[2],h2[2]);   split3(v3,h0[3],h1[3],h2[3]);
            split3(v4,h0[4],h1[4],h2[4]);   split3(v5,h0[5],h1[5],h2[5]);
            split3(v6,h0[6],h1[6],h2[6]);   split3(v7,h0[7],h1[7],h2[7]);
            split3(v8,h0[8],h1[8],h2[8]);   split3(v9,h0[9],h1[9],h2[9]);
            split3(va,h0[10],h1[10],h2[10]); split3(vb,h0[11],h1[11],h2[11]);
            split3(vc,h0[12],h1[12],h2[12]); split3(vd,h0[13],h1[13],h2[13]);
            split3(ve,h0[14],h1[14],h2[14]); split3(vf,h0[15],h1[15],h2[15]);
            unsigned short* base0 = (unsigned short*)smemraw + arow * SROW + akh;
            const int PL = 128 * SROW;
#pragma unroll
            for (int sp = 0; sp < 3; sp++) {
                unsigned short* hh = (sp == 0) ? h0 : (sp == 1) ? h1 : h2;  // unroll-resolved
                uint4 u0, u1;
                u0.x = (unsigned)hh[0] | ((unsigned)hh[1] << 16);
                u0.y = (unsigned)hh[2] | ((unsigned)hh[3] << 16);
                u0.z = (unsigned)hh[4] | ((unsigned)hh[5] << 16);
                u0.w = (unsigned)hh[6] | ((unsigned)hh[7] << 16);
                u1.x = (unsigned)hh[8] | ((unsigned)hh[9] << 16);
                u1.y = (unsigned)hh[10] | ((unsigned)hh[11] << 16);
                u1.z = (unsigned)hh[12] | ((unsigned)hh[13] << 16);
                u1.w = (unsigned)hh[14] | ((unsigned)hh[15] << 16);
                *(uint4*)(base0 + sp * PL)     = u0;
                *(uint4*)(base0 + sp * PL + 8) = u1;
            }
        }
        // ---- W: cp.async 3x16B per thread ----
#pragma unroll
        for (int i = 0; i < 3; i++) {
            int u = tid + 256 * i;
            int sp = u >> 8, row = (u >> 2) & 63, part = u & 3;
            unsigned dst = wbase + (((sp * 64 + row) * SROW) + part * 8) * 2;
            cpa16(dst, gW + ((size_t)sp * 512 + n0 + row) * 512 + k0 + part * 8);
        }
        cp_commit_wait();
        __syncthreads();

#pragma unroll
        for (int s = 0; s < 2; ++s) {
            unsigned af[3][2][4];
#pragma unroll
            for (int sp = 0; sp < 3; sp++)
#pragma unroll
                for (int mt = 0; mt < 2; mt++) {
                    unsigned a = sbase +
                        (((sp * 128 + mw * 32 + mt * 16 + arow_l) * SROW) +
                         s * 16 + ak8) * 2;
                    ldsm4(af[sp][mt][0], af[sp][mt][1], af[sp][mt][2], af[sp][mt][3], a);
                }
#pragma unroll
            for (int j = 0; j < 3; j++) {
                unsigned bfr[2][4];
#pragma unroll
                for (int np = 0; np < 2; np++) {
                    unsigned a = wbase +
                        (((j * 64 + nw * 32 + np * 16 + brow) * SROW) +
                         s * 16 + bk8) * 2;
                    ldsm4(bfr[np][0], bfr[np][1], bfr[np][2], bfr[np][3], a);
                }
#pragma unroll
                for (int i = 0; i < 3; i++) {
                    if (i + j > 2) break;
#pragma unroll
                    for (int mt = 0; mt < 2; mt++)
#pragma unroll
                        for (int np = 0; np < 2; np++) {
                            mma_bf16(C[mt][np * 2], af[i][mt][0], af[i][mt][1],
                                     af[i][mt][2], af[i][mt][3],
                                     bfr[np][0], bfr[np][1]);
                            mma_bf16(C[mt][np * 2 + 1], af[i][mt][0], af[i][mt][1],
                                     af[i][mt][2], af[i][mt][3],
                                     bfr[np][2], bfr[np][3]);
                        }
                }
            }
        }
    }

    // ---- epilogue: bias + spike -> bytes (overlay smem) -> bitpack ----
    __syncthreads();
    unsigned char* sbyte = (unsigned char*)smemraw;   // [128][64]
#pragma unroll
    for (int mt = 0; mt < 2; mt++)
#pragma unroll
        for (int nt = 0; nt < 4; nt++) {
            int row = mw * 32 + mt * 16 + g;
            int col = nw * 32 + nt * 8 + tg * 2;
            float2 bb = *(const float2*)&bias[n0 + col];
            sbyte[row * 64 + col]           = (C[mt][nt][0] + bb.x >= 1.0f) ? 1 : 0;
            sbyte[row * 64 + col + 1]       = (C[mt][nt][1] + bb.y >= 1.0f) ? 1 : 0;
            sbyte[(row + 8) * 64 + col]     = (C[mt][nt][2] + bb.x >= 1.0f) ? 1 : 0;
            sbyte[(row + 8) * 64 + col + 1] = (C[mt][nt][3] + bb.y >= 1.0f) ? 1 : 0;
        }
    __syncthreads();
    if (tid < 128) {
        unsigned long long bits = 0ull;
#pragma unroll
        for (int q = 0; q < 8; q++) {
            unsigned long long u = *(const unsigned long long*)&sbyte[tid * 64 + 8 * q];
#pragma unroll
            for (int j = 0; j < 8; j++)
                bits |= ((u >> (8 * j)) & 1ull) << (8 * q + j);
        }
        int m = m0 + tid;
        int b = m >> 11, t = m & 2047;
        int head = n0 >> 6;
        unsigned long long* dst = (which == 2) ? g_qb : (which == 0) ? g_kb : g_vb;
        dst[(size_t)((b << 3) + head) * TT + t] = bits;
    }
}

// =====================================================================
// Output projection: A binary from g_xs (1 pass) x W 3-split.
// =====================================================================
__global__ __launch_bounds__(256, 2) void out_mma_kernel(
    const float* __restrict__ bias, float* __restrict__ out)
{
    __shared__ unsigned short Asp[128 * SROW];
    __shared__ unsigned short Wsp[3 * 64 * SROW];

    const int tid  = threadIdx.x;
    const int lane = tid & 31;
    const int g    = lane >> 2, tg = lane & 3;
    const int wrp  = tid >> 5;
    const int mw   = wrp >> 1, nw = wrp & 1;

    int s2 = blockIdx.x;
    int n0 = (s2 & 7) * 64, m0 = (s2 >> 3) * 128;

    const unsigned short* gW = g_wsp + (size_t)3 * 3 * 512 * 512;   // Wo
    const unsigned abase = (unsigned)__cvta_generic_to_shared(Asp);
    const unsigned wbase = (unsigned)__cvta_generic_to_shared(Wsp);

    float C[2][4][4];
#pragma unroll
    for (int mt = 0; mt < 2; mt++)
#pragma unroll
        for (int nt = 0; nt < 4; nt++)
#pragma unroll
            for (int r = 0; r < 4; r++) C[mt][nt][r] = 0.f;

    const int arow_l = lane & 15;
    const int ak8 = (lane >> 4) * 8;
    const int brow = (lane & 7) + ((lane & 16) >> 1);
    const int bk8 = (lane & 8);
    const int xrow = tid >> 1, xhalf = tid & 1;

    for (int ch = 0; ch < 16; ++ch) {
        const int k0 = ch << 5;
        __syncthreads();
        {
            uint4 u = *(const uint4*)(g_xs + (size_t)(m0 + xrow) * DD + k0 + xhalf * 16);
            unsigned w0 = u.x, w1 = u.y, w2 = u.z, w3 = u.w;
            uint4 o0, o1;
            o0.x = ((w0 & 1u) ? 0x3F80u : 0u) | ((w0 & 0x100u) ? 0x3F800000u : 0u);
            o0.y = (((w0 >> 16) & 1u) ? 0x3F80u : 0u) | ((w0 & 0x1000000u) ? 0x3F800000u : 0u);
            o0.z = ((w1 & 1u) ? 0x3F80u : 0u) | ((w1 & 0x100u) ? 0x3F800000u : 0u);
            o0.w = (((w1 >> 16) & 1u) ? 0x3F80u : 0u) | ((w1 & 0x1000000u) ? 0x3F800000u : 0u);
            o1.x = ((w2 & 1u) ? 0x3F80u : 0u) | ((w2 & 0x100u) ? 0x3F800000u : 0u);
            o1.y = (((w2 >> 16) & 1u) ? 0x3F80u : 0u) | ((w2 & 0x1000000u) ? 0x3F800000u : 0u);
            o1.z = ((w3 & 1u) ? 0x3F80u : 0u) | ((w3 & 0x100u) ? 0x3F800000u : 0u);
            o1.w = (((w3 >> 16) & 1u) ? 0x3F80u : 0u) | ((w3 & 0x1000000u) ? 0x3F800000u : 0u);
            unsigned short* dstp = &Asp[xrow * SROW + xhalf * 16];
            *(uint4*)dstp       = o0;
            *(uint4*)(dstp + 8) = o1;
        }
#pragma unroll
        for (int i = 0; i < 3; i++) {
            int u = tid + 256 * i;
            int sp = u >> 8, row = (u >> 2) & 63, part = u & 3;
            unsigned dst = wbase + (((sp * 64 + row) * SROW) + part * 8) * 2;
            cpa16(dst, gW + ((size_t)sp * 512 + n0 + row) * 512 + k0 + part * 8);
        }
        cp_commit_wait();
        __syncthreads();

#pragma unroll
        for (int s = 0; s < 2; ++s) {
            unsigned af[2][4];
#pragma unroll
            for (int mt = 0; mt < 2; mt++) {
                unsigned a = abase +
                    (((mw * 32 + mt * 16 + arow_l) * SROW) + s * 16 + ak8) * 2;
                ldsm4(af[mt][0], af[mt][1], af[mt][2], af[mt][3], a);
            }
#pragma unroll
            for (int j = 0; j < 3; j++) {
                unsigned bfr[2][4];
#pragma unroll
                for (int np = 0; np < 2; np++) {
                    unsigned a = wbase +
                        (((j * 64 + nw * 32 + np * 16 + brow) * SROW) +
                         s * 16 + bk8) * 2;
                    ldsm4(bfr[np][0], bfr[np][1], bfr[np][2], bfr[np][3], a);
                }
#pragma unroll
                for (int mt = 0; mt < 2; mt++)
#pragma unroll
                    for (int np = 0; np < 2; np++) {
                        mma_bf16(C[mt][np * 2], af[mt][0], af[mt][1], af[mt][2],
                                 af[mt][3], bfr[np][0], bfr[np][1]);
                        mma_bf16(C[mt][np * 2 + 1], af[mt][0], af[mt][1], af[mt][2],
                                 af[mt][3], bfr[np][2], bfr[np][3]);
                    }
            }
        }
    }

#pragma unroll
    for (int mt = 0; mt < 2; mt++)
#pragma unroll
        for (int nt = 0; nt < 4; nt++) {
            int row = m0 + mw * 32 + mt * 16 + g;
            int col = n0 + nw * 32 + nt * 8 + tg * 2;
            float2 bb = *(const float2*)&bias[col];
            float2 r0, r1;
            r0.x = (C[mt][nt][0] + bb.x >= 1.0f) ? 1.0f : 0.0f;
            r0.y = (C[mt][nt][1] + bb.y >= 1.0f) ? 1.0f : 0.0f;
            r1.x = (C[mt][nt][2] + bb.x >= 1.0f) ? 1.0f : 0.0f;
            r1.y = (C[mt][nt][3] + bb.y >= 1.0f) ? 1.0f : 0.0f;
            *(float2*)&out[(size_t)row * DD + col] = r0;
            *(float2*)&out[(size_t)(row + 8) * DD + col] = r1;
        }
}

// ---------------- v bit transpose ----------------
__global__ void vtrans_kernel()
{
    int bx = blockIdx.x;
    int bh = bx >> 5, w = bx & 31;
    int tid = threadIdx.x;
    int lane = tid & 31, warp = tid >> 5;
    __shared__ unsigned sh[64][2];
    unsigned long long r = g_vb[(size_t)bh * TT + w * 64 + tid];
#pragma unroll 8
    for (int d = 0; d < 64; d++) {
        unsigned b = __ballot_sync(0xffffffffu, (unsigned)((r >> d) & 1ull));
        if (lane == 0) sh[d][warp] = b;
    }
    __syncthreads();
    g_vT[(size_t)(bh * 64 + tid) * 32 + w] =
        (unsigned long long)sh[tid][0] | ((unsigned long long)sh[tid][1] << 32);
}

// =====================================================================
// Attention: QK popcount -> s8 cnt tile -> PV via IMMA (exact). Unchanged.
// =====================================================================
__global__ __launch_bounds__(128) void attn_kernel(const float* __restrict__ scale_p)
{
    const int tid = threadIdx.x;
    const int lane = tid & 31;
    const int warpid = tid >> 5;
    const int g = lane >> 2, tg = lane & 3;
    const int rowA = warpid * 16 + g;

    int bx = blockIdx.x;
    int bh = bx & 31;
    int tq = 31 - (bx >> 5);

    __shared__ unsigned long long qsh[64];
    __shared__ unsigned long long ksh[64];
    __shared__ unsigned char csh[64 * 68];

    const float scale = *scale_p;
    const size_t base = (size_t)bh * TT;

    if (tid < 64) qsh[tid] = g_qb[base + (size_t)tq * 64 + tid];

    int acc[8][4];
#pragma unroll
    for (int nt = 0; nt < 8; nt++)
#pragma unroll
        for (int r = 0; r < 4; r++) acc[nt][r] = 0;

    const int tQ = tid >> 1;
    const int khalf = tid & 1;

    for (int w = 0; w <= tq; ++w) {
        __syncthreads();
        if (tid < 64) ksh[tid] = g_kb[base + (size_t)w * 64 + tid];
        unsigned long long vt[8];
#pragma unroll
        for (int nt = 0; nt < 8; ++nt)
            vt[nt] = g_vT[((size_t)bh * 64 + nt * 8 + g) * 32 + w];
        __syncthreads();

        {
            unsigned long long q = qsh[tQ];
            const bool diag = (w == tq);
#pragma unroll 2
            for (int k4 = 0; k4 < 32; k4 += 4) {
                unsigned pack = 0;
#pragma unroll
                for (int j = 0; j < 4; ++j) {
                    int kc = khalf * 32 + k4 + j;
                    int c = __popcll(q & ksh[kc]);
                    if (diag && kc > tQ) c = 0;
                    pack |= (unsigned)c << (8 * j);
                }
                *(unsigned*)&csh[tQ * 68 + khalf * 32 + k4] = pack;
            }
        }
        __syncthreads();

#pragma unroll
        for (int s = 0; s < 2; ++s) {
            unsigned a0 = *(const unsigned*)&csh[rowA * 68 + s * 32 + tg * 4];
            unsigned a1 = *(const unsigned*)&csh[(rowA + 8) * 68 + s * 32 + tg * 4];
            unsigned a2 = *(const unsigned*)&csh[rowA * 68 + s * 32 + 16 + tg * 4];
            unsigned a3 = *(const unsigned*)&csh[(rowA + 8) * 68 + s * 32 + 16 + tg * 4];
#pragma unroll
            for (int nt = 0; nt < 8; ++nt) {
                unsigned b0 = expand4((unsigned)(vt[nt] >> (s * 32 + tg * 4)) & 0xFu);
                unsigned b1 = expand4((unsigned)(vt[nt] >> (s * 32 + 16 + tg * 4)) & 0xFu);
                mma_s8(acc[nt], a0, a1, a2, a3, b0, b1);
            }
        }
    }

    __syncthreads();
#pragma unroll
    for (int nt = 0; nt < 8; ++nt) {
        int d0 = nt * 8 + tg * 2;
        csh[d0 * 68 + rowA]           = ((float)acc[nt][0] * scale >= 1.0f) ? 1 : 0;
        csh[(d0 + 1) * 68 + rowA]     = ((float)acc[nt][1] * scale >= 1.0f) ? 1 : 0;
        csh[d0 * 68 + rowA + 8]       = ((float)acc[nt][2] * scale >= 1.0f) ? 1 : 0;
        csh[(d0 + 1) * 68 + rowA + 8] = ((float)acc[nt][3] * scale >= 1.0f) ? 1 : 0;
    }
    __syncthreads();
    {
        int d = tid >> 1, hf = tid & 1;
        size_t b = (size_t)(bh >> 3), h = (size_t)(bh & 7);
        size_t off = (b << 20) + (h << 17) + ((size_t)d << 11)
                   + (size_t)tq * 64 + (size_t)hf * 32;
#pragma unroll
        for (int q4 = 0; q4 < 32; q4 += 4) {
            unsigned v = *(const unsigned*)&csh[d * 68 + hf * 32 + q4];
            *(unsigned*)(g_xs + off + q4) = v;
        }
    }
}

// ---------------- launch ----------------
extern "C" void kernel_launch(void* const* d_in, const int* in_sizes, int n_in,
                              void* d_out, int out_size)
{
    const float* query = (const float*)d_in[0];
    const float* key   = (const float*)d_in[1];
    const float* value = (const float*)d_in[2];
    const float* scale = (const float*)d_in[3];
    const float* Wq = (const float*)d_in[4];  const float* bq = (const float*)d_in[5];
    const float* Wk = (const float*)d_in[6];  const float* bk = (const float*)d_in[7];
    const float* Wv = (const float*)d_in[8];  const float* bv = (const float*)d_in[9];
    const float* Wo = (const float*)d_in[10]; const float* bo = (const float*)d_in[11];
    float* out = (float*)d_out;

    const int DIN = in_sizes[0] / MROWS;   // 100

    prep_w_kernel<<<dim3(8, 8, 4), 256>>>(Wq, Wk, Wv, Wo);
    qkv_mma_kernel<<<1536, 256>>>(query, key, value, bq, bk, bv, DIN);
    vtrans_kernel<<<BHN * (TT / 64), 64>>>();
    attn_kernel<<<BHN * (TT / 64), 128>>>(scale);
    out_mma_kernel<<<512, 256>>>(bo, out);
}

// round 9
// speedup vs baseline: 1.7438x; 1.1427x over previous
#include <cuda_runtime.h>
#include <cstdint>

#define BB 4
#define TT 2048
#define DD 512
#define HH 8
#define DK 64
#define BHN (BB*HH)          // 32
#define NTW (TT/64)          // 32 k-tiles
#define MROWS (BB*TT)        // 8192
#define SROW 40              // smem row stride (bf16 units) = 80B

// ---------------- scratch ----------------
__device__ unsigned long long g_qb[BHN*TT];
__device__ unsigned long long g_kb[BHN*TT];
__device__ unsigned long long g_vb[BHN*TT];
__device__ unsigned long long g_vT[BHN*DK*NTW];      // [bh][d][w]
__device__ unsigned long long g_kT[BHN*DK*NTW];      // [bh][j][w]
__device__ unsigned char      g_xs[BB*TT*DD];
__device__ unsigned short     g_wsp[4*3*512*512];    // pre-split W
__device__ unsigned char      g_kv[BHN*NTW*64*64];   // KV tiles s8: [bh][w][d][j]

// ---------------- helpers ----------------
__device__ __forceinline__ unsigned expand4(unsigned x) {
    return (x * 0x00204081u) & 0x01010101u;
}
__device__ __forceinline__ void mma_s8(int* c, unsigned a0, unsigned a1, unsigned a2,
                                       unsigned a3, unsigned b0, unsigned b1) {
    asm volatile(
        "mma.sync.aligned.m16n8k32.row.col.s32.s8.s8.s32 "
        "{%0,%1,%2,%3}, {%4,%5,%6,%7}, {%8,%9}, {%0,%1,%2,%3};"
        : "+r"(c[0]), "+r"(c[1]), "+r"(c[2]), "+r"(c[3])
        : "r"(a0), "r"(a1), "r"(a2), "r"(a3), "r"(b0), "r"(b1));
}
__device__ __forceinline__ void mma_bf16(float* c, unsigned a0, unsigned a1,
                                         unsigned a2, unsigned a3,
                                         unsigned b0, unsigned b1) {
    asm volatile(
        "mma.sync.aligned.m16n8k16.row.col.f32.bf16.bf16.f32 "
        "{%0,%1,%2,%3}, {%4,%5,%6,%7}, {%8,%9}, {%0,%1,%2,%3};"
        : "+f"(c[0]), "+f"(c[1]), "+f"(c[2]), "+f"(c[3])
        : "r"(a0), "r"(a1), "r"(a2), "r"(a3), "r"(b0), "r"(b1));
}
__device__ __forceinline__ void split3(float a, unsigned short& s0,
                                       unsigned short& s1, unsigned short& s2) {
    unsigned u0 = __float_as_uint(a);
    s0 = (unsigned short)(u0 >> 16);
    float r1 = a - __uint_as_float(u0 & 0xFFFF0000u);
    unsigned u1 = __float_as_uint(r1);
    s1 = (unsigned short)(u1 >> 16);
    float r2 = r1 - __uint_as_float(u1 & 0xFFFF0000u);
    s2 = (unsigned short)(__float_as_uint(r2) >> 16);
}
__device__ __forceinline__ void ldsm4(unsigned& r0, unsigned& r1, unsigned& r2,
                                      unsigned& r3, unsigned addr) {
    asm volatile("ldmatrix.sync.aligned.m8n8.x4.shared.b16 {%0,%1,%2,%3}, [%4];"
                 : "=r"(r0), "=r"(r1), "=r"(r2), "=r"(r3) : "r"(addr));
}
__device__ __forceinline__ void cpa16(unsigned dst, const void* src) {
    asm volatile("cp.async.cg.shared.global [%0], [%1], 16;" :: "r"(dst), "l"(src));
}
__device__ __forceinline__ void cp_commit_wait() {
    asm volatile("cp.async.commit_group;");
    asm volatile("cp.async.wait_group 0;" ::: "memory");
}
#define CP_COMMIT() asm volatile("cp.async.commit_group;")
#define CP_WAIT(n)  asm volatile("cp.async.wait_group %0;" :: "n"(n) : "memory")

// =====================================================================
// prep: split W (transposed to [n][k]) into g_wsp.
// =====================================================================
__global__ void prep_w_kernel(const float* __restrict__ Wq, const float* __restrict__ Wk,
                              const float* __restrict__ Wv, const float* __restrict__ Wo)
{
    __shared__ float sh[64][68];
    int w = blockIdx.z;
    const float* W = (w == 0) ? Wq : (w == 1) ? Wk : (w == 2) ? Wv : Wo;
    int k0 = blockIdx.x * 64, n0 = blockIdx.y * 64;
    int t = threadIdx.x;
#pragma unroll
    for (int r = 0; r < 4; r++) {
        int row = (t >> 4) * 4 + r;
        int col = (t & 15) * 4;
        float4 v = *(const float4*)&W[(size_t)(k0 + row) * DD + n0 + col];
        sh[row][col] = v.x; sh[row][col+1] = v.y; sh[row][col+2] = v.z; sh[row][col+3] = v.w;
    }
    __syncthreads();
#pragma unroll
    for (int r = 0; r < 4; r++) {
        int n = (t >> 4) * 4 + r;
        int k4 = (t & 15) * 4;
        unsigned short a0, a1, a2, b0, b1, b2, c0, c1, c2, d0, d1, d2;
        split3(sh[k4 + 0][n], a0, a1, a2);
        split3(sh[k4 + 1][n], b0, b1, b2);
        split3(sh[k4 + 2][n], c0, c1, c2);
        split3(sh[k4 + 3][n], d0, d1, d2);
        size_t base = ((size_t)(w * 3) * 512 + (n0 + n)) * 512 + k0 + k4;
        const size_t P = (size_t)512 * 512;
        *(uint2*)&g_wsp[base] =
            make_uint2((unsigned)a0 | ((unsigned)b0 << 16),
                       (unsigned)c0 | ((unsigned)d0 << 16));
        *(uint2*)&g_wsp[base + P] =
            make_uint2((unsigned)a1 | ((unsigned)b1 << 16),
                       (unsigned)c1 | ((unsigned)d1 << 16));
        *(uint2*)&g_wsp[base + 2 * P] =
            make_uint2((unsigned)a2 | ((unsigned)b2 << 16),
                       (unsigned)c2 | ((unsigned)d2 << 16));
    }
}

// =====================================================================
// qkv GEMM (unchanged from the 344us run).
// =====================================================================
__global__ __launch_bounds__(256, 2) void qkv_mma_kernel(
    const float* __restrict__ Aq, const float* __restrict__ Ak,
    const float* __restrict__ Av,
    const float* __restrict__ bq, const float* __restrict__ bk,
    const float* __restrict__ bv, int DIN)
{
    __shared__ char smemraw[46080];

    const int tid  = threadIdx.x;
    const int lane = tid & 31;
    const int g    = lane >> 2, tg = lane & 3;
    const int wrp  = tid >> 5;
    const int mw   = wrp >> 1, nw = wrp & 1;

    int idx = blockIdx.x;
    int which = idx >> 9;
    int s2 = idx & 511;
    int n0 = (s2 & 7) * 64, m0 = (s2 >> 3) * 128;

    const float* A    = (which == 0) ? Ak : (which == 1) ? Av : Aq;
    const float* bias = (which == 0) ? bk : (which == 1) ? bv : bq;
    const int KA = (which == 2) ? DIN : DD;
    const int KS = (which == 2) ? 128 : DD;
    const int wsel = (which == 0) ? 1 : (which == 1) ? 2 : 0;
    const unsigned short* gW = g_wsp + (size_t)wsel * 3 * 512 * 512;

    const unsigned sbase = (unsigned)__cvta_generic_to_shared(smemraw);
    const unsigned wbase = sbase + 30720;

    float C[2][4][4];
#pragma unroll
    for (int mt = 0; mt < 2; mt++)
#pragma unroll
        for (int nt = 0; nt < 4; nt++)
#pragma unroll
            for (int r = 0; r < 4; r++) C[mt][nt][r] = 0.f;

    const int arow = tid >> 1, akh = (tid & 1) * 16;
    const int arow_l = lane & 15;
    const int ak8 = (lane >> 4) * 8;
    const int brow = (lane & 7) + ((lane & 16) >> 1);
    const int bk8 = (lane & 8);

    const int nch = KS >> 5;
    for (int ch = 0; ch < nch; ++ch) {
        const int k0 = ch << 5;
        __syncthreads();
        {
            float v0,v1,v2,v3,v4,v5,v6,v7,v8,v9,va,vb,vc,vd,ve,vf;
            if (which != 2) {
                const float4* ap = (const float4*)(A + (size_t)(m0 + arow) * DD + k0 + akh);
                float4 x0 = ap[0], x1 = ap[1], x2 = ap[2], x3 = ap[3];
                v0=x0.x; v1=x0.y; v2=x0.z; v3=x0.w; v4=x1.x; v5=x1.y; v6=x1.z; v7=x1.w;
                v8=x2.x; v9=x2.y; va=x2.z; vb=x2.w; vc=x3.x; vd=x3.y; ve=x3.z; vf=x3.w;
            } else {
                const float* ar = A + (size_t)(m0 + arow) * KA;
                int kb = k0 + akh;
                v0 = (kb+0 < KA) ? ar[kb+0] : 0.f;  v1 = (kb+1 < KA) ? ar[kb+1] : 0.f;
                v2 = (kb+2 < KA) ? ar[kb+2] : 0.f;  v3 = (kb+3 < KA) ? ar[kb+3] : 0.f;
                v4 = (kb+4 < KA) ? ar[kb+4] : 0.f;  v5 = (kb+5 < KA) ? ar[kb+5] : 0.f;
                v6 = (kb+6 < KA) ? ar[kb+6] : 0.f;  v7 = (kb+7 < KA) ? ar[kb+7] : 0.f;
                v8 = (kb+8 < KA) ? ar[kb+8] : 0.f;  v9 = (kb+9 < KA) ? ar[kb+9] : 0.f;
                va = (kb+10 < KA) ? ar[kb+10] : 0.f; vb = (kb+11 < KA) ? ar[kb+11] : 0.f;
                vc = (kb+12 < KA) ? ar[kb+12] : 0.f; vd = (kb+13 < KA) ? ar[kb+13] : 0.f;
                ve = (kb+14 < KA) ? ar[kb+14] : 0.f; vf = (kb+15 < KA) ? ar[kb+15] : 0.f;
            }
            unsigned short h0[16], h1[16], h2[16];
            split3(v0,h0[0],h1[0],h2[0]);   split3(v1,h0[1],h1[1],h2[1]);
            split3(v2,h0[2],h1[2],h2[2]);   split3(v3,h0[3],h1[3],h2[3]);
            split3(v4,h0[4],h1[4],h2[4]);   split3(v5,h0[5],h1[5],h2[5]);
            split3(v6,h0[6],h1[6],h2[6]);   split3(v7,h0[7],h1[7],h2[7]);
            split3(v8,h0[8],h1[8],h2[8]);   split3(v9,h0[9],h1[9],h2[9]);
            split3(va,h0[10],h1[10],h2[10]); split3(vb,h0[11],h1[11],h2[11]);
            split3(vc,h0[12],h1[12],h2[12]); split3(vd,h0[13],h1[13],h2[13]);
            split3(ve,h0[14],h1[14],h2[14]); split3(vf,h0[15],h1[15],h2[15]);
            unsigned short* base0 = (unsigned short*)smemraw + arow * SROW + akh;
            const int PL = 128 * SROW;
#pragma unroll
            for (int sp = 0; sp < 3; sp++) {
                unsigned short* hh = (sp == 0) ? h0 : (sp == 1) ? h1 : h2;
                uint4 u0, u1;
                u0.x = (unsigned)hh[0] | ((unsigned)hh[1] << 16);
                u0.y = (unsigned)hh[2] | ((unsigned)hh[3] << 16);
                u0.z = (unsigned)hh[4] | ((unsigned)hh[5] << 16);
                u0.w = (unsigned)hh[6] | ((unsigned)hh[7] << 16);
                u1.x = (unsigned)hh[8] | ((unsigned)hh[9] << 16);
                u1.y = (unsigned)hh[10] | ((unsigned)hh[11] << 16);
                u1.z = (unsigned)hh[12] | ((unsigned)hh[13] << 16);
                u1.w = (unsigned)hh[14] | ((unsigned)hh[15] << 16);
                *(uint4*)(base0 + sp * PL)     = u0;
                *(uint4*)(base0 + sp * PL + 8) = u1;
            }
        }
#pragma unroll
        for (int i = 0; i < 3; i++) {
            int u = tid + 256 * i;
            int sp = u >> 8, row = (u >> 2) & 63, part = u & 3;
            unsigned dst = wbase + (((sp * 64 + row) * SROW) + part * 8) * 2;
            cpa16(dst, gW + ((size_t)sp * 512 + n0 + row) * 512 + k0 + part * 8);
        }
        cp_commit_wait();
        __syncthreads();

#pragma unroll
        for (int s = 0; s < 2; ++s) {
            unsigned af[3][2][4];
#pragma unroll
            for (int sp = 0; sp < 3; sp++)
#pragma unroll
                for (int mt = 0; mt < 2; mt++) {
                    unsigned a = sbase +
                        (((sp * 128 + mw * 32 + mt * 16 + arow_l) * SROW) +
                         s * 16 + ak8) * 2;
                    ldsm4(af[sp][mt][0], af[sp][mt][1], af[sp][mt][2], af[sp][mt][3], a);
                }
#pragma unroll
            for (int j = 0; j < 3; j++) {
                unsigned bfr[2][4];
#pragma unroll
                for (int np = 0; np < 2; np++) {
                    unsigned a = wbase +
                        (((j * 64 + nw * 32 + np * 16 + brow) * SROW) +
                         s * 16 + bk8) * 2;
                    ldsm4(bfr[np][0], bfr[np][1], bfr[np][2], bfr[np][3], a);
                }
#pragma unroll
                for (int i = 0; i < 3; i++) {
                    if (i + j > 2) break;
#pragma unroll
                    for (int mt = 0; mt < 2; mt++)
#pragma unroll
                        for (int np = 0; np < 2; np++) {
                            mma_bf16(C[mt][np * 2], af[i][mt][0], af[i][mt][1],
                                     af[i][mt][2], af[i][mt][3],
                                     bfr[np][0], bfr[np][1]);
                            mma_bf16(C[mt][np * 2 + 1], af[i][mt][0], af[i][mt][1],
                                     af[i][mt][2], af[i][mt][3],
                                     bfr[np][2], bfr[np][3]);
                        }
                }
            }
        }
    }

    __syncthreads();
    unsigned char* sbyte = (unsigned char*)smemraw;
#pragma unroll
    for (int mt = 0; mt < 2; mt++)
#pragma unroll
        for (int nt = 0; nt < 4; nt++) {
            int row = mw * 32 + mt * 16 + g;
            int col = nw * 32 + nt * 8 + tg * 2;
            float2 bb = *(const float2*)&bias[n0 + col];
            sbyte[row * 64 + col]           = (C[mt][nt][0] + bb.x >= 1.0f) ? 1 : 0;
            sbyte[row * 64 + col + 1]       = (C[mt][nt][1] + bb.y >= 1.0f) ? 1 : 0;
            sbyte[(row + 8) * 64 + col]     = (C[mt][nt][2] + bb.x >= 1.0f) ? 1 : 0;
            sbyte[(row + 8) * 64 + col + 1] = (C[mt][nt][3] + bb.y >= 1.0f) ? 1 : 0;
        }
    __syncthreads();
    if (tid < 128) {
        unsigned long long bits = 0ull;
#pragma unroll
        for (int q = 0; q < 8; q++) {
            unsigned long long u = *(const unsigned long long*)&sbyte[tid * 64 + 8 * q];
#pragma unroll
            for (int j = 0; j < 8; j++)
                bits |= ((u >> (8 * j)) & 1ull) << (8 * q + j);
        }
        int m = m0 + tid;
        int b = m >> 11, t = m & 2047;
        int head = n0 >> 6;
        unsigned long long* dst = (which == 2) ? g_qb : (which == 0) ? g_kb : g_vb;
        dst[(size_t)((b << 3) + head) * TT + t] = bits;
    }
}

// ---------------- bit transpose for k and v ----------------
__global__ void trans_kernel()
{
    int bx = blockIdx.x;                 // 2048: [0,1024)=v, [1024,2048)=k
    int which = bx >> 10;
    int idx = bx & 1023;
    int bh = idx >> 5, w = idx & 31;
    int tid = threadIdx.x;
    int lane = tid & 31, warp = tid >> 5;
    __shared__ unsigned sh[64][2];
    const unsigned long long* src = (which == 0) ? g_vb : g_kb;
    unsigned long long* dst = (which == 0) ? g_vT : g_kT;
    unsigned long long r = src[(size_t)bh * TT + w * 64 + tid];
#pragma unroll 8
    for (int d = 0; d < 64; d++) {
        unsigned b = __ballot_sync(0xffffffffu, (unsigned)((r >> d) & 1ull));
        if (lane == 0) sh[d][warp] = b;
    }
    __syncthreads();
    dst[(size_t)(bh * 64 + tid) * 32 + w] =
        (unsigned long long)sh[tid][0] | ((unsigned long long)sh[tid][1] << 32);
}

// =====================================================================
// KV precompute: KV[bh][w][d][j] = sum_k v[k,d]*k[k,j]  (<=64, s8)
// =====================================================================
__global__ __launch_bounds__(128) void kvprod_kernel()
{
    const int tid = threadIdx.x;
    const int lane = tid & 31;
    const int g = lane >> 2, tg = lane & 3;
    const int wr16 = (tid >> 5) * 16;

    int bh = blockIdx.x >> 5, w = blockIdx.x & 31;

    unsigned long long vd0 = g_vT[((size_t)bh * 64 + wr16 + g) * 32 + w];
    unsigned long long vd1 = g_vT[((size_t)bh * 64 + wr16 + 8 + g) * 32 + w];
    unsigned long long kt[8];
#pragma unroll
    for (int nt = 0; nt < 8; nt++)
        kt[nt] = g_kT[((size_t)bh * 64 + nt * 8 + g) * 32 + w];

    int acc[8][4];
#pragma unroll
    for (int nt = 0; nt < 8; nt++)
#pragma unroll
        for (int r = 0; r < 4; r++) acc[nt][r] = 0;

#pragma unroll
    for (int s = 0; s < 2; s++) {
        unsigned l0 = (unsigned)(vd0 >> (32 * s));
        unsigned l1 = (unsigned)(vd1 >> (32 * s));
        unsigned a0 = expand4((l0 >> (4 * tg)) & 0xFu);
        unsigned a1 = expand4((l1 >> (4 * tg)) & 0xFu);
        unsigned a2 = expand4((l0 >> (16 + 4 * tg)) & 0xFu);
        unsigned a3 = expand4((l1 >> (16 + 4 * tg)) & 0xFu);
#pragma unroll
        for (int nt = 0; nt < 8; nt++) {
            unsigned kl = (unsigned)(kt[nt] >> (32 * s));
            unsigned b0 = expand4((kl >> (4 * tg)) & 0xFu);
            unsigned b1 = expand4((kl >> (16 + 4 * tg)) & 0xFu);
            mma_s8(acc[nt], a0, a1, a2, a3, b0, b1);
        }
    }

    unsigned char* dst = g_kv + ((size_t)(bh * 32 + w) * 64) * 64;
#pragma unroll
    for (int nt = 0; nt < 8; nt++) {
        int j0 = nt * 8 + 2 * tg;
        *(unsigned short*)(dst + (wr16 + g) * 64 + j0) =
            (unsigned short)((acc[nt][0] & 0xFF) | ((acc[nt][1] & 0xFF) << 8));
        *(unsigned short*)(dst + (wr16 + 8 + g) * 64 + j0) =
            (unsigned short)((acc[nt][2] & 0xFF) | ((acc[nt][3] & 0xFF) << 8));
    }
}

// =====================================================================
// Attention: off-diag tiles S += q x KV_w (s8 IMMA, q-fragments hoisted,
// double-buffered cp.async KV). Diag tile: QK-IMMA + causal mask + PV-IMMA.
// All integer-exact.
// =====================================================================
__global__ __launch_bounds__(128) void attn_kernel(const float* __restrict__ scale_p)
{
    __shared__ __align__(16) unsigned char KVsh[2][64 * 80];
    __shared__ unsigned char csh[64 * 68];
    __shared__ unsigned long long ksh[64];

    const int tid = threadIdx.x;
    const int lane = tid & 31;
    const int g = lane >> 2, tg = lane & 3;
    const int wr16 = (tid >> 5) * 16;
    const int rowA = wr16 + g;

    int bx = blockIdx.x;
    int bh = bx & 31;
    int tq = 31 - (bx >> 5);             // big tiles first

    const float scale = *scale_p;
    const size_t base = (size_t)bh * TT;
    const unsigned char* KVg = g_kv + (size_t)bh * 32 * 64 * 64;

    // hoisted q A-fragments
    unsigned long long q0 = g_qb[base + (size_t)tq * 64 + rowA];
    unsigned long long q1 = g_qb[base + (size_t)tq * 64 + rowA + 8];
    unsigned qa[2][4];
#pragma unroll
    for (int s = 0; s < 2; s++) {
        unsigned l0 = (unsigned)(q0 >> (32 * s));
        unsigned l1 = (unsigned)(q1 >> (32 * s));
        qa[s][0] = expand4((l0 >> (4 * tg)) & 0xFu);
        qa[s][1] = expand4((l1 >> (4 * tg)) & 0xFu);
        qa[s][2] = expand4((l0 >> (16 + 4 * tg)) & 0xFu);
        qa[s][3] = expand4((l1 >> (16 + 4 * tg)) & 0xFu);
    }

    int acc[8][4];
#pragma unroll
    for (int nt = 0; nt < 8; nt++)
#pragma unroll
        for (int r = 0; r < 4; r++) acc[nt][r] = 0;

    // KV loader map: 2x16B per thread
    const int kvrow0 = tid >> 2, kvp0 = tid & 3;            // unit tid
    const int kvrow1 = (tid + 128) >> 2, kvp1 = tid & 3;    // unit tid+128
    const unsigned kvb0 = (unsigned)__cvta_generic_to_shared(&KVsh[0][0]);
    const unsigned kvb1 = (unsigned)__cvta_generic_to_shared(&KVsh[1][0]);

    // ---- off-diagonal tiles ----
    if (tq > 0) {
        cpa16(kvb0 + kvrow0 * 80 + kvp0 * 16, KVg + 0 * 4096 + kvrow0 * 64 + kvp0 * 16);
        cpa16(kvb0 + kvrow1 * 80 + kvp1 * 16, KVg + 0 * 4096 + kvrow1 * 64 + kvp1 * 16);
        CP_COMMIT();
    }
    for (int w = 0; w < tq; ++w) {
        __syncthreads();                  // buffer (w+1)&1 free
        if (w + 1 < tq) {
            unsigned kb = ((w + 1) & 1) ? kvb1 : kvb0;
            const unsigned char* src = KVg + (size_t)(w + 1) * 4096;
            cpa16(kb + kvrow0 * 80 + kvp0 * 16, src + kvrow0 * 64 + kvp0 * 16);
            cpa16(kb + kvrow1 * 80 + kvp1 * 16, src + kvrow1 * 64 + kvp1 * 16);
            CP_COMMIT();
            CP_WAIT(1);
        } else {
            CP_WAIT(0);
        }
        __syncthreads();                  // KV(w) visible
        const unsigned char* kb = KVsh[w & 1];
#pragma unroll
        for (int s = 0; s < 2; s++)
#pragma unroll
            for (int nt = 0; nt < 8; nt++) {
                unsigned b0 = *(const unsigned*)(kb + (nt * 8 + g) * 80 + s * 32 + tg * 4);
                unsigned b1 = *(const unsigned*)(kb + (nt * 8 + g) * 80 + s * 32 + 16 + tg * 4);
                mma_s8(acc[nt], qa[s][0], qa[s][1], qa[s][2], qa[s][3], b0, b1);
            }
    }

    // ---- diagonal tile ----
    if (tid < 64) ksh[tid] = g_kb[base + (size_t)tq * 64 + tid];
    unsigned long long vt[8];
#pragma unroll
    for (int nt = 0; nt < 8; nt++)
        vt[nt] = g_vT[((size_t)bh * 64 + nt * 8 + g) * 32 + tq];
    __syncthreads();

    {
        unsigned long long kk[8];
#pragma unroll
        for (int nt = 0; nt < 8; nt++) kk[nt] = ksh[nt * 8 + g];
        int qcc[8][4];
#pragma unroll
        for (int nt = 0; nt < 8; nt++)
#pragma unroll
            for (int r = 0; r < 4; r++) qcc[nt][r] = 0;
#pragma unroll
        for (int s = 0; s < 2; s++)
#pragma unroll
            for (int nt = 0; nt < 8; nt++) {
                unsigned kl = (unsigned)(kk[nt] >> (32 * s));
                unsigned b0 = expand4((kl >> (4 * tg)) & 0xFu);
                unsigned b1 = expand4((kl >> (16 + 4 * tg)) & 0xFu);
                mma_s8(qcc[nt], qa[s][0], qa[s][1], qa[s][2], qa[s][3], b0, b1);
            }
        // causal mask (keep kc <= t) + stage s8 cnt (warp-private rows)
        int t0 = rowA, t1 = rowA + 8;
#pragma unroll
        for (int nt = 0; nt < 8; nt++) {
            int kc = nt * 8 + 2 * tg;
            unsigned v00 = (kc <= t0) ? (qcc[nt][0] & 0xFF) : 0u;
            unsigned v01 = (kc + 1 <= t0) ? (qcc[nt][1] & 0xFF) : 0u;
            unsigned v10 = (kc <= t1) ? (qcc[nt][2] & 0xFF) : 0u;
            unsigned v11 = (kc + 1 <= t1) ? (qcc[nt][3] & 0xFF) : 0u;
            *(unsigned short*)&csh[t0 * 68 + kc] = (unsigned short)(v00 | (v01 << 8));
            *(unsigned short*)&csh[t1 * 68 + kc] = (unsigned short)(v10 | (v11 << 8));
        }
        __syncwarp();
        // PV on masked counts
#pragma unroll
        for (int s = 0; s < 2; s++) {
            unsigned a0 = *(const unsigned*)&csh[rowA * 68 + s * 32 + tg * 4];
            unsigned a1 = *(const unsigned*)&csh[(rowA + 8) * 68 + s * 32 + tg * 4];
            unsigned a2 = *(const unsigned*)&csh[rowA * 68 + s * 32 + 16 + tg * 4];
            unsigned a3 = *(const unsigned*)&csh[(rowA + 8) * 68 + s * 32 + 16 + tg * 4];
#pragma unroll
            for (int nt = 0; nt < 8; nt++) {
                unsigned b0 = expand4((unsigned)(vt[nt] >> (s * 32 + tg * 4)) & 0xFu);
                unsigned b1 = expand4((unsigned)(vt[nt] >> (s * 32 + 16 + tg * 4)) & 0xFu);
                mma_s8(acc[nt], a0, a1, a2, a3, b0, b1);
            }
        }
    }

    // ---- spike + transpose to [d][t] via csh, then scrambled store ----
    __syncthreads();
#pragma unroll
    for (int nt = 0; nt < 8; ++nt) {
        int d0 = nt * 8 + tg * 2;
        csh[d0 * 68 + rowA]           = ((float)acc[nt][0] * scale >= 1.0f) ? 1 : 0;
        csh[(d0 + 1) * 68 + rowA]     = ((float)acc[nt][1] * scale >= 1.0f) ? 1 : 0;
        csh[d0 * 68 + rowA + 8]       = ((float)acc[nt][2] * scale >= 1.0f) ? 1 : 0;
        csh[(d0 + 1) * 68 + rowA + 8] = ((float)acc[nt][3] * scale >= 1.0f) ? 1 : 0;
    }
    __syncthreads();
    {
        int d = tid >> 1, hf = tid & 1;
        size_t b = (size_t)(bh >> 3), h = (size_t)(bh & 7);
        size_t off = (b << 20) + (h << 17) + ((size_t)d << 11)
                   + (size_t)tq * 64 + (size_t)hf * 32;
#pragma unroll
        for (int q4 = 0; q4 < 32; q4 += 4) {
            unsigned v = *(const unsigned*)&csh[d * 68 + hf * 32 + q4];
            *(unsigned*)(g_xs + off + q4) = v;
        }
    }
}

// =====================================================================
// Output projection (unchanged from the 344us run).
// =====================================================================
__global__ __launch_bounds__(256, 2) void out_mma_kernel(
    const float* __restrict__ bias, float* __restrict__ out)
{
    __shared__ unsigned short Asp[128 * SROW];
    __shared__ unsigned short Wsp[3 * 64 * SROW];

    const int tid  = threadIdx.x;
    const int lane = tid & 31;
    const int g    = lane >> 2, tg = lane & 3;
    const int wrp  = tid >> 5;
    const int mw   = wrp >> 1, nw = wrp & 1;

    int s2 = blockIdx.x;
    int n0 = (s2 & 7) * 64, m0 = (s2 >> 3) * 128;

    const unsigned short* gW = g_wsp + (size_t)3 * 3 * 512 * 512;
    const unsigned abase = (unsigned)__cvta_generic_to_shared(Asp);
    const unsigned wbase = (unsigned)__cvta_generic_to_shared(Wsp);

    float C[2][4][4];
#pragma unroll
    for (int mt = 0; mt < 2; mt++)
#pragma unroll
        for (int nt = 0; nt < 4; nt++)
#pragma unroll
            for (int r = 0; r < 4; r++) C[mt][nt][r] = 0.f;

    const int arow_l = lane & 15;
    const int ak8 = (lane >> 4) * 8;
    const int brow = (lane & 7) + ((lane & 16) >> 1);
    const int bk8 = (lane & 8);
    const int xrow = tid >> 1, xhalf = tid & 1;

    for (int ch = 0; ch < 16; ++ch) {
        const int k0 = ch << 5;
        __syncthreads();
        {
            uint4 u = *(const uint4*)(g_xs + (size_t)(m0 + xrow) * DD + k0 + xhalf * 16);
            unsigned w0 = u.x, w1 = u.y, w2 = u.z, w3 = u.w;
            uint4 o0, o1;
            o0.x = ((w0 & 1u) ? 0x3F80u : 0u) | ((w0 & 0x100u) ? 0x3F800000u : 0u);
            o0.y = (((w0 >> 16) & 1u) ? 0x3F80u : 0u) | ((w0 & 0x1000000u) ? 0x3F800000u : 0u);
            o0.z = ((w1 & 1u) ? 0x3F80u : 0u) | ((w1 & 0x100u) ? 0x3F800000u : 0u);
            o0.w = (((w1 >> 16) & 1u) ? 0x3F80u : 0u) | ((w1 & 0x1000000u) ? 0x3F800000u : 0u);
            o1.x = ((w2 & 1u) ? 0x3F80u : 0u) | ((w2 & 0x100u) ? 0x3F800000u : 0u);
            o1.y = (((w2 >> 16) & 1u) ? 0x3F80u : 0u) | ((w2 & 0x1000000u) ? 0x3F800000u : 0u);
            o1.z = ((w3 & 1u) ? 0x3F80u : 0u) | ((w3 & 0x100u) ? 0x3F800000u : 0u);
            o1.w = (((w3 >> 16) & 1u) ? 0x3F80u : 0u) | ((w3 & 0x1000000u) ? 0x3F800000u : 0u);
            unsigned short* dstp = &Asp[xrow * SROW + xhalf * 16];
            *(uint4*)dstp       = o0;
            *(uint4*)(dstp + 8) = o1;
        }
#pragma unroll
        for (int i = 0; i < 3; i++) {
            int u = tid + 256 * i;
            int sp = u >> 8, row = (u >> 2) & 63, part = u & 3;
            unsigned dst = wbase + (((sp * 64 + row) * SROW) + part * 8) * 2;
            cpa16(dst, gW + ((size_t)sp * 512 + n0 + row) * 512 + k0 + part * 8);
        }
        cp_commit_wait();
        __syncthreads();

#pragma unroll
        for (int s = 0; s < 2; ++s) {
            unsigned af[2][4];
#pragma unroll
            for (int mt = 0; mt < 2; mt++) {
                unsigned a = abase +
                    (((mw * 32 + mt * 16 + arow_l) * SROW) + s * 16 + ak8) * 2;
                ldsm4(af[mt][0], af[mt][1], af[mt][2], af[mt][3], a);
            }
#pragma unroll
            for (int j = 0; j < 3; j++) {
                unsigned bfr[2][4];
#pragma unroll
                for (int np = 0; np < 2; np++) {
                    unsigned a = wbase +
                        (((j * 64 + nw * 32 + np * 16 + brow) * SROW) +
                         s * 16 + bk8) * 2;
                    ldsm4(bfr[np][0], bfr[np][1], bfr[np][2], bfr[np][3], a);
                }
#pragma unroll
                for (int mt = 0; mt < 2; mt++)
#pragma unroll
                    for (int np = 0; np < 2; np++) {
                        mma_bf16(C[mt][np * 2], af[mt][0], af[mt][1], af[mt][2],
                                 af[mt][3], bfr[np][0], bfr[np][1]);
                        mma_bf16(C[mt][np * 2 + 1], af[mt][0], af[mt][1], af[mt][2],
                                 af[mt][3], bfr[np][2], bfr[np][3]);
                    }
            }
        }
    }

#pragma unroll
    for (int mt = 0; mt < 2; mt++)
#pragma unroll
        for (int nt = 0; nt < 4; nt++) {
            int row = m0 + mw * 32 + mt * 16 + g;
            int col = n0 + nw * 32 + nt * 8 + tg * 2;
            float2 bb = *(const float2*)&bias[col];
            float2 r0, r1;
            r0.x = (C[mt][nt][0] + bb.x >= 1.0f) ? 1.0f : 0.0f;
            r0.y = (C[mt][nt][1] + bb.y >= 1.0f) ? 1.0f : 0.0f;
            r1.x = (C[mt][nt][2] + bb.x >= 1.0f) ? 1.0f : 0.0f;
            r1.y = (C[mt][nt][3] + bb.y >= 1.0f) ? 1.0f : 0.0f;
            *(float2*)&out[(size_t)row * DD + col] = r0;
            *(float2*)&out[(size_t)(row + 8) * DD + col] = r1;
        }
}

// ---------------- launch ----------------
extern "C" void kernel_launch(void* const* d_in, const int* in_sizes, int n_in,
                              void* d_out, int out_size)
{
    const float* query = (const float*)d_in[0];
    const float* key   = (const float*)d_in[1];
    const float* value = (const float*)d_in[2];
    const float* scale = (const float*)d_in[3];
    const float* Wq = (const float*)d_in[4];  const float* bq = (const float*)d_in[5];
    const float* Wk = (const float*)d_in[6];  const float* bk = (const float*)d_in[7];
    const float* Wv = (const float*)d_in[8];  const float* bv = (const float*)d_in[9];
    const float* Wo = (const float*)d_in[10]; const float* bo = (const float*)d_in[11];
    float* out = (float*)d_out;

    const int DIN = in_sizes[0] / MROWS;   // 100

    prep_w_kernel<<<dim3(8, 8, 4), 256>>>(Wq, Wk, Wv, Wo);
    qkv_mma_kernel<<<1536, 256>>>(query, key, value, bq, bk, bv, DIN);
    trans_kernel<<<2048, 64>>>();
    kvprod_kernel<<<BHN * NTW, 128>>>();
    attn_kernel<<<BHN * NTW, 128>>>(scale);
    out_mma_kernel<<<512, 256>>>(bo, out);
}

// round 11
// speedup vs baseline: 1.9107x; 1.0957x over previous
#include <cuda_runtime.h>
#include <cstdint>

#define BB 4
#define TT 2048
#define DD 512
#define HH 8
#define DK 64
#define BHN (BB*HH)          // 32
#define NTW (TT/64)          // 32 k-tiles
#define MROWS (BB*TT)        // 8192
#define SROW 40              // smem row stride (bf16 units) = 80B

// ---------------- scratch (R9 footprint: ~17 MB total) ----------------
__device__ unsigned long long g_qb[BHN*TT];
__device__ unsigned long long g_kb[BHN*TT];
__device__ unsigned long long g_vb[BHN*TT];
__device__ unsigned long long g_vT[BHN*DK*NTW];      // [bh][d][w]
__device__ unsigned long long g_kT[BHN*DK*NTW];      // [bh][j][w]
__device__ unsigned char      g_xs[BB*TT*DD];
__device__ unsigned short     g_wsp[4*3*512*512];    // pre-split W (6 MB)
__device__ unsigned char      g_kv[BHN*NTW*64*64];   // KV tiles s8 (4 MB)

// ---------------- helpers ----------------
__device__ __forceinline__ unsigned expand4(unsigned x) {
    return (x * 0x00204081u) & 0x01010101u;
}
__device__ __forceinline__ void mma_s8(int* c, unsigned a0, unsigned a1, unsigned a2,
                                       unsigned a3, unsigned b0, unsigned b1) {
    asm volatile(
        "mma.sync.aligned.m16n8k32.row.col.s32.s8.s8.s32 "
        "{%0,%1,%2,%3}, {%4,%5,%6,%7}, {%8,%9}, {%0,%1,%2,%3};"
        : "+r"(c[0]), "+r"(c[1]), "+r"(c[2]), "+r"(c[3])
        : "r"(a0), "r"(a1), "r"(a2), "r"(a3), "r"(b0), "r"(b1));
}
__device__ __forceinline__ void mma_bf16(float* c, unsigned a0, unsigned a1,
                                         unsigned a2, unsigned a3,
                                         unsigned b0, unsigned b1) {
    asm volatile(
        "mma.sync.aligned.m16n8k16.row.col.f32.bf16.bf16.f32 "
        "{%0,%1,%2,%3}, {%4,%5,%6,%7}, {%8,%9}, {%0,%1,%2,%3};"
        : "+f"(c[0]), "+f"(c[1]), "+f"(c[2]), "+f"(c[3])
        : "r"(a0), "r"(a1), "r"(a2), "r"(a3), "r"(b0), "r"(b1));
}
__device__ __forceinline__ void split3(float a, unsigned short& s0,
                                       unsigned short& s1, unsigned short& s2) {
    unsigned u0 = __float_as_uint(a);
    s0 = (unsigned short)(u0 >> 16);
    float r1 = a - __uint_as_float(u0 & 0xFFFF0000u);
    unsigned u1 = __float_as_uint(r1);
    s1 = (unsigned short)(u1 >> 16);
    float r2 = r1 - __uint_as_float(u1 & 0xFFFF0000u);
    s2 = (unsigned short)(__float_as_uint(r2) >> 16);
}
__device__ __forceinline__ void ldsm4(unsigned& r0, unsigned& r1, unsigned& r2,
                                      unsigned& r3, unsigned addr) {
    asm volatile("ldmatrix.sync.aligned.m8n8.x4.shared.b16 {%0,%1,%2,%3}, [%4];"
                 : "=r"(r0), "=r"(r1), "=r"(r2), "=r"(r3) : "r"(addr));
}
__device__ __forceinline__ void cpa16(unsigned dst, const void* src) {
    asm volatile("cp.async.cg.shared.global [%0], [%1], 16;" :: "r"(dst), "l"(src));
}
#define CP_COMMIT() asm volatile("cp.async.commit_group;")
#define CP_WAIT(n)  asm volatile("cp.async.wait_group %0;" :: "n"(n) : "memory")

// =====================================================================
// prep: split W (transposed to [n][k]) into g_wsp.
// =====================================================================
__global__ void prep_w_kernel(const float* __restrict__ Wq, const float* __restrict__ Wk,
                              const float* __restrict__ Wv, const float* __restrict__ Wo)
{
    __shared__ float sh[64][68];
    int w = blockIdx.z;
    const float* W = (w == 0) ? Wq : (w == 1) ? Wk : (w == 2) ? Wv : Wo;
    int k0 = blockIdx.x * 64, n0 = blockIdx.y * 64;
    int t = threadIdx.x;
#pragma unroll
    for (int r = 0; r < 4; r++) {
        int row = (t >> 4) * 4 + r;
        int col = (t & 15) * 4;
        float4 v = *(const float4*)&W[(size_t)(k0 + row) * DD + n0 + col];
        sh[row][col] = v.x; sh[row][col+1] = v.y; sh[row][col+2] = v.z; sh[row][col+3] = v.w;
    }
    __syncthreads();
#pragma unroll
    for (int r = 0; r < 4; r++) {
        int n = (t >> 4) * 4 + r;
        int k4 = (t & 15) * 4;
        unsigned short a0, a1, a2, b0, b1, b2, c0, c1, c2, d0, d1, d2;
        split3(sh[k4 + 0][n], a0, a1, a2);
        split3(sh[k4 + 1][n], b0, b1, b2);
        split3(sh[k4 + 2][n], c0, c1, c2);
        split3(sh[k4 + 3][n], d0, d1, d2);
        size_t base = ((size_t)(w * 3) * 512 + (n0 + n)) * 512 + k0 + k4;
        const size_t P = (size_t)512 * 512;
        *(uint2*)&g_wsp[base] =
            make_uint2((unsigned)a0 | ((unsigned)b0 << 16),
                       (unsigned)c0 | ((unsigned)d0 << 16));
        *(uint2*)&g_wsp[base + P] =
            make_uint2((unsigned)a1 | ((unsigned)b1 << 16),
                       (unsigned)c1 | ((unsigned)d1 << 16));
        *(uint2*)&g_wsp[base + 2 * P] =
            make_uint2((unsigned)a2 | ((unsigned)b2 << 16),
                       (unsigned)c2 | ((unsigned)d2 << 16));
    }
}

// =====================================================================
// qkv GEMM: in-kernel A split, register-prefetch pipeline: during the
// MMA of chunk ch the global loads for ch+1 (A float4s + W uint4s) are
// already in flight into registers. No extra smem, no cp.async here.
// =====================================================================
#define QKV_LOAD_A(K0)                                                        \
    do {                                                                      \
        if (which != 2) {                                                     \
            const float4* ap = (const float4*)(A + (size_t)(m0 + arow) * DD + (K0) + akh); \
            float4 x0 = ap[0], x1 = ap[1], x2 = ap[2], x3 = ap[3];            \
            pv0=x0.x; pv1=x0.y; pv2=x0.z; pv3=x0.w;                           \
            pv4=x1.x; pv5=x1.y; pv6=x1.z; pv7=x1.w;                           \
            pv8=x2.x; pv9=x2.y; pva=x2.z; pvb=x2.w;                           \
            pvc=x3.x; pvd=x3.y; pve=x3.z; pvf=x3.w;                           \
        } else {                                                              \
            const float* ar = A + (size_t)(m0 + arow) * KA;                   \
            int kb = (K0) + akh;                                              \
            pv0 = (kb+0 < KA) ? ar[kb+0] : 0.f;  pv1 = (kb+1 < KA) ? ar[kb+1] : 0.f; \
            pv2 = (kb+2 < KA) ? ar[kb+2] : 0.f;  pv3 = (kb+3 < KA) ? ar[kb+3] : 0.f; \
            pv4 = (kb+4 < KA) ? ar[kb+4] : 0.f;  pv5 = (kb+5 < KA) ? ar[kb+5] : 0.f; \
            pv6 = (kb+6 < KA) ? ar[kb+6] : 0.f;  pv7 = (kb+7 < KA) ? ar[kb+7] : 0.f; \
            pv8 = (kb+8 < KA) ? ar[kb+8] : 0.f;  pv9 = (kb+9 < KA) ? ar[kb+9] : 0.f; \
            pva = (kb+10 < KA) ? ar[kb+10] : 0.f; pvb = (kb+11 < KA) ? ar[kb+11] : 0.f; \
            pvc = (kb+12 < KA) ? ar[kb+12] : 0.f; pvd = (kb+13 < KA) ? ar[kb+13] : 0.f; \
            pve = (kb+14 < KA) ? ar[kb+14] : 0.f; pvf = (kb+15 < KA) ? ar[kb+15] : 0.f; \
        }                                                                     \
    } while (0)

#define QKV_LOAD_W(K0)                                                        \
    do {                                                                      \
        pwa = *(const uint4*)(gW + ((size_t)0 * 512 + n0 + wrow) * 512 + (K0) + wpart * 8); \
        pwb = *(const uint4*)(gW + ((size_t)1 * 512 + n0 + wrow) * 512 + (K0) + wpart * 8); \
        pwc = *(const uint4*)(gW + ((size_t)2 * 512 + n0 + wrow) * 512 + (K0) + wpart * 8); \
    } while (0)

__global__ __launch_bounds__(256, 2) void qkv_mma_kernel(
    const float* __restrict__ Aq, const float* __restrict__ Ak,
    const float* __restrict__ Av,
    const float* __restrict__ bq, const float* __restrict__ bk,
    const float* __restrict__ bv, int DIN)
{
    __shared__ char smemraw[46080];   // A planes [0,30720), W [30720,46080)

    const int tid  = threadIdx.x;
    const int lane = tid & 31;
    const int g    = lane >> 2, tg = lane & 3;
    const int wrp  = tid >> 5;
    const int mw   = wrp >> 1, nw = wrp & 1;

    int idx = blockIdx.x;
    int which = idx >> 9;                      // 0=k,1=v,2=q
    int s2 = idx & 511;
    int n0 = (s2 & 7) * 64, m0 = (s2 >> 3) * 128;

    const float* A    = (which == 0) ? Ak : (which == 1) ? Av : Aq;
    const float* bias = (which == 0) ? bk : (which == 1) ? bv : bq;
    const int KA = DIN;
    const int KS = (which == 2) ? 128 : DD;
    const int wsel = (which == 0) ? 1 : (which == 1) ? 2 : 0;
    const unsigned short* gW = g_wsp + (size_t)wsel * 3 * 512 * 512;

    const unsigned sbase = (unsigned)__cvta_generic_to_shared(smemraw);
    const unsigned wbase = sbase + 30720;

    float C[2][4][4];
#pragma unroll
    for (int mt = 0; mt < 2; mt++)
#pragma unroll
        for (int nt = 0; nt < 4; nt++)
#pragma unroll
            for (int r = 0; r < 4; r++) C[mt][nt][r] = 0.f;

    const int arow = tid >> 1, akh = (tid & 1) * 16;
    const int arow_l = lane & 15;
    const int ak8 = (lane >> 4) * 8;
    const int brow = (lane & 7) + ((lane & 16) >> 1);
    const int bk8 = (lane & 8);
    const int wrow = (tid >> 2) & 63, wpart = tid & 3;   // W loader map

    // prefetch registers
    float pv0,pv1,pv2,pv3,pv4,pv5,pv6,pv7,pv8,pv9,pva,pvb,pvc,pvd,pve,pvf;
    uint4 pwa, pwb, pwc;

    QKV_LOAD_A(0);
    QKV_LOAD_W(0);

    const int nch = KS >> 5;
    for (int ch = 0; ch < nch; ++ch) {
        const int k0 = ch << 5;
        __syncthreads();                       // prev MMA done reading smem
        // ---- A: split prefetched values -> STS 3 planes ----
        {
            unsigned short h0[16], h1[16], h2[16];
            split3(pv0,h0[0],h1[0],h2[0]);   split3(pv1,h0[1],h1[1],h2[1]);
            split3(pv2,h0[2],h1[2],h2[2]);   split3(pv3,h0[3],h1[3],h2[3]);
            split3(pv4,h0[4],h1[4],h2[4]);   split3(pv5,h0[5],h1[5],h2[5]);
            split3(pv6,h0[6],h1[6],h2[6]);   split3(pv7,h0[7],h1[7],h2[7]);
            split3(pv8,h0[8],h1[8],h2[8]);   split3(pv9,h0[9],h1[9],h2[9]);
            split3(pva,h0[10],h1[10],h2[10]); split3(pvb,h0[11],h1[11],h2[11]);
            split3(pvc,h0[12],h1[12],h2[12]); split3(pvd,h0[13],h1[13],h2[13]);
            split3(pve,h0[14],h1[14],h2[14]); split3(pvf,h0[15],h1[15],h2[15]);
            unsigned short* base0 = (unsigned short*)smemraw + arow * SROW + akh;
            const int PL = 128 * SROW;
#pragma unroll
            for (int sp = 0; sp < 3; sp++) {
                unsigned short* hh = (sp == 0) ? h0 : (sp == 1) ? h1 : h2;
                uint4 u0, u1;
                u0.x = (unsigned)hh[0] | ((unsigned)hh[1] << 16);
                u0.y = (unsigned)hh[2] | ((unsigned)hh[3] << 16);
                u0.z = (unsigned)hh[4] | ((unsigned)hh[5] << 16);
                u0.w = (unsigned)hh[6] | ((unsigned)hh[7] << 16);
                u1.x = (unsigned)hh[8] | ((unsigned)hh[9] << 16);
                u1.y = (unsigned)hh[10] | ((unsigned)hh[11] << 16);
                u1.z = (unsigned)hh[12] | ((unsigned)hh[13] << 16);
                u1.w = (unsigned)hh[14] | ((unsigned)hh[15] << 16);
                *(uint4*)(base0 + sp * PL)     = u0;
                *(uint4*)(base0 + sp * PL + 8) = u1;
            }
        }
        // ---- W: STS prefetched uint4s ----
        {
            char* wd = smemraw + 30720;
            *(uint4*)(wd + (((0 * 64 + wrow) * SROW) + wpart * 8) * 2) = pwa;
            *(uint4*)(wd + (((1 * 64 + wrow) * SROW) + wpart * 8) * 2) = pwb;
            *(uint4*)(wd + (((2 * 64 + wrow) * SROW) + wpart * 8) * 2) = pwc;
        }
        __syncthreads();                       // tiles visible
        // ---- prefetch chunk ch+1 (overlaps with MMA below) ----
        if (ch + 1 < nch) {
            QKV_LOAD_A(k0 + 32);
            QKV_LOAD_W(k0 + 32);
        }
        // ---- MMA phase (identical op order to the 301us run) ----
#pragma unroll
        for (int s = 0; s < 2; ++s) {
            unsigned af[3][2][4];
#pragma unroll
            for (int sp = 0; sp < 3; sp++)
#pragma unroll
                for (int mt = 0; mt < 2; mt++) {
                    unsigned a = sbase +
                        (((sp * 128 + mw * 32 + mt * 16 + arow_l) * SROW) +
                         s * 16 + ak8) * 2;
                    ldsm4(af[sp][mt][0], af[sp][mt][1], af[sp][mt][2], af[sp][mt][3], a);
                }
#pragma unroll
            for (int j = 0; j < 3; j++) {
                unsigned bfr[2][4];
#pragma unroll
                for (int np = 0; np < 2; np++) {
                    unsigned a = wbase +
                        (((j * 64 + nw * 32 + np * 16 + brow) * SROW) +
                         s * 16 + bk8) * 2;
                    ldsm4(bfr[np][0], bfr[np][1], bfr[np][2], bfr[np][3], a);
                }
#pragma unroll
                for (int i = 0; i < 3; i++) {
                    if (i + j > 2) break;
#pragma unroll
                    for (int mt = 0; mt < 2; mt++)
#pragma unroll
                        for (int np = 0; np < 2; np++) {
                            mma_bf16(C[mt][np * 2], af[i][mt][0], af[i][mt][1],
                                     af[i][mt][2], af[i][mt][3],
                                     bfr[np][0], bfr[np][1]);
                            mma_bf16(C[mt][np * 2 + 1], af[i][mt][0], af[i][mt][1],
                                     af[i][mt][2], af[i][mt][3],
                                     bfr[np][2], bfr[np][3]);
                        }
                }
            }
        }
    }

    // ---- epilogue: bias + spike -> bytes (overlay smem) -> bitpack ----
    __syncthreads();
    unsigned char* sbyte = (unsigned char*)smemraw;
#pragma unroll
    for (int mt = 0; mt < 2; mt++)
#pragma unroll
        for (int nt = 0; nt < 4; nt++) {
            int row = mw * 32 + mt * 16 + g;
            int col = nw * 32 + nt * 8 + tg * 2;
            float2 bb = *(const float2*)&bias[n0 + col];
            sbyte[row * 64 + col]           = (C[mt][nt][0] + bb.x >= 1.0f) ? 1 : 0;
            sbyte[row * 64 + col + 1]       = (C[mt][nt][1] + bb.y >= 1.0f) ? 1 : 0;
            sbyte[(row + 8) * 64 + col]     = (C[mt][nt][2] + bb.x >= 1.0f) ? 1 : 0;
            sbyte[(row + 8) * 64 + col + 1] = (C[mt][nt][3] + bb.y >= 1.0f) ? 1 : 0;
        }
    __syncthreads();
    if (tid < 128) {
        unsigned long long bits = 0ull;
#pragma unroll
        for (int q = 0; q < 8; q++) {
            unsigned long long u = *(const unsigned long long*)&sbyte[tid * 64 + 8 * q];
#pragma unroll
            for (int j = 0; j < 8; j++)
                bits |= ((u >> (8 * j)) & 1ull) << (8 * q + j);
        }
        int m = m0 + tid;
        int b = m >> 11, t = m & 2047;
        int head = n0 >> 6;
        unsigned long long* dst = (which == 2) ? g_qb : (which == 0) ? g_kb : g_vb;
        dst[(size_t)((b << 3) + head) * TT + t] = bits;
    }
}

// ---------------- bit transpose for k and v ----------------
__global__ void trans_kernel()
{
    int bx = blockIdx.x;
    int which = bx >> 10;
    int idx = bx & 1023;
    int bh = idx >> 5, w = idx & 31;
    int tid = threadIdx.x;
    int lane = tid & 31, warp = tid >> 5;
    __shared__ unsigned sh[64][2];
    const unsigned long long* src = (which == 0) ? g_vb : g_kb;
    unsigned long long* dst = (which == 0) ? g_vT : g_kT;
    unsigned long long r = src[(size_t)bh * TT + w * 64 + tid];
#pragma unroll 8
    for (int d = 0; d < 64; d++) {
        unsigned b = __ballot_sync(0xffffffffu, (unsigned)((r >> d) & 1ull));
        if (lane == 0) sh[d][warp] = b;
    }
    __syncthreads();
    dst[(size_t)(bh * 64 + tid) * 32 + w] =
        (unsigned long long)sh[tid][0] | ((unsigned long long)sh[tid][1] << 32);
}

// =====================================================================
// KV precompute (unchanged).
// =====================================================================
__global__ __launch_bounds__(128) void kvprod_kernel()
{
    const int tid = threadIdx.x;
    const int lane = tid & 31;
    const int g = lane >> 2, tg = lane & 3;
    const int wr16 = (tid >> 5) * 16;

    int bh = blockIdx.x >> 5, w = blockIdx.x & 31;

    unsigned long long vd0 = g_vT[((size_t)bh * 64 + wr16 + g) * 32 + w];
    unsigned long long vd1 = g_vT[((size_t)bh * 64 + wr16 + 8 + g) * 32 + w];
    unsigned long long kt[8];
#pragma unroll
    for (int nt = 0; nt < 8; nt++)
        kt[nt] = g_kT[((size_t)bh * 64 + nt * 8 + g) * 32 + w];

    int acc[8][4];
#pragma unroll
    for (int nt = 0; nt < 8; nt++)
#pragma unroll
        for (int r = 0; r < 4; r++) acc[nt][r] = 0;

#pragma unroll
    for (int s = 0; s < 2; s++) {
        unsigned l0 = (unsigned)(vd0 >> (32 * s));
        unsigned l1 = (unsigned)(vd1 >> (32 * s));
        unsigned a0 = expand4((l0 >> (4 * tg)) & 0xFu);
        unsigned a1 = expand4((l1 >> (4 * tg)) & 0xFu);
        unsigned a2 = expand4((l0 >> (16 + 4 * tg)) & 0xFu);
        unsigned a3 = expand4((l1 >> (16 + 4 * tg)) & 0xFu);
#pragma unroll
        for (int nt = 0; nt < 8; nt++) {
            unsigned kl = (unsigned)(kt[nt] >> (32 * s));
            unsigned b0 = expand4((kl >> (4 * tg)) & 0xFu);
            unsigned b1 = expand4((kl >> (16 + 4 * tg)) & 0xFu);
            mma_s8(acc[nt], a0, a1, a2, a3, b0, b1);
        }
    }

    unsigned char* dst = g_kv + ((size_t)(bh * 32 + w) * 64) * 64;
#pragma unroll
    for (int nt = 0; nt < 8; nt++) {
        int j0 = nt * 8 + 2 * tg;
        *(unsigned short*)(dst + (wr16 + g) * 64 + j0) =
            (unsigned short)((acc[nt][0] & 0xFF) | ((acc[nt][1] & 0xFF) << 8));
        *(unsigned short*)(dst + (wr16 + 8 + g) * 64 + j0) =
            (unsigned short)((acc[nt][2] & 0xFF) | ((acc[nt][3] & 0xFF) << 8));
    }
}

// =====================================================================
// Attention (unchanged from 301us run).
// =====================================================================
__global__ __launch_bounds__(128) void attn_kernel(const float* __restrict__ scale_p)
{
    __shared__ __align__(16) unsigned char KVsh[2][64 * 80];
    __shared__ unsigned char csh[64 * 68];
    __shared__ unsigned long long ksh[64];

    const int tid = threadIdx.x;
    const int lane = tid & 31;
    const int g = lane >> 2, tg = lane & 3;
    const int wr16 = (tid >> 5) * 16;
    const int rowA = wr16 + g;

    int bx = blockIdx.x;
    int bh = bx & 31;
    int tq = 31 - (bx >> 5);

    const float scale = *scale_p;
    const size_t base = (size_t)bh * TT;
    const unsigned char* KVg = g_kv + (size_t)bh * 32 * 64 * 64;

    unsigned long long q0 = g_qb[base + (size_t)tq * 64 + rowA];
    unsigned long long q1 = g_qb[base + (size_t)tq * 64 + rowA + 8];
    unsigned qa[2][4];
#pragma unroll
    for (int s = 0; s < 2; s++) {
        unsigned l0 = (unsigned)(q0 >> (32 * s));
        unsigned l1 = (unsigned)(q1 >> (32 * s));
        qa[s][0] = expand4((l0 >> (4 * tg)) & 0xFu);
        qa[s][1] = expand4((l1 >> (4 * tg)) & 0xFu);
        qa[s][2] = expand4((l0 >> (16 + 4 * tg)) & 0xFu);
        qa[s][3] = expand4((l1 >> (16 + 4 * tg)) & 0xFu);
    }

    int acc[8][4];
#pragma unroll
    for (int nt = 0; nt < 8; nt++)
#pragma unroll
        for (int r = 0; r < 4; r++) acc[nt][r] = 0;

    const int kvrow0 = tid >> 2, kvp0 = tid & 3;
    const int kvrow1 = (tid + 128) >> 2, kvp1 = tid & 3;
    const unsigned kvb0 = (unsigned)__cvta_generic_to_shared(&KVsh[0][0]);
    const unsigned kvb1 = (unsigned)__cvta_generic_to_shared(&KVsh[1][0]);

    if (tq > 0) {
        cpa16(kvb0 + kvrow0 * 80 + kvp0 * 16, KVg + 0 * 4096 + kvrow0 * 64 + kvp0 * 16);
        cpa16(kvb0 + kvrow1 * 80 + kvp1 * 16, KVg + 0 * 4096 + kvrow1 * 64 + kvp1 * 16);
        CP_COMMIT();
    }
    for (int w = 0; w < tq; ++w) {
        __syncthreads();
        if (w + 1 < tq) {
            unsigned kb = ((w + 1) & 1) ? kvb1 : kvb0;
            const unsigned char* src = KVg + (size_t)(w + 1) * 4096;
            cpa16(kb + kvrow0 * 80 + kvp0 * 16, src + kvrow0 * 64 + kvp0 * 16);
            cpa16(kb + kvrow1 * 80 + kvp1 * 16, src + kvrow1 * 64 + kvp1 * 16);
            CP_COMMIT();
            CP_WAIT(1);
        } else {
            CP_WAIT(0);
        }
        __syncthreads();
        const unsigned char* kb = KVsh[w & 1];
#pragma unroll
        for (int s = 0; s < 2; s++)
#pragma unroll
            for (int nt = 0; nt < 8; nt++) {
                unsigned b0 = *(const unsigned*)(kb + (nt * 8 + g) * 80 + s * 32 + tg * 4);
                unsigned b1 = *(const unsigned*)(kb + (nt * 8 + g) * 80 + s * 32 + 16 + tg * 4);
                mma_s8(acc[nt], qa[s][0], qa[s][1], qa[s][2], qa[s][3], b0, b1);
            }
    }

    if (tid < 64) ksh[tid] = g_kb[base + (size_t)tq * 64 + tid];
    unsigned long long vt[8];
#pragma unroll
    for (int nt = 0; nt < 8; nt++)
        vt[nt] = g_vT[((size_t)bh * 64 + nt * 8 + g) * 32 + tq];
    __syncthreads();

    {
        unsigned long long kk[8];
#pragma unroll
        for (int nt = 0; nt < 8; nt++) kk[nt] = ksh[nt * 8 + g];
        int qcc[8][4];
#pragma unroll
        for (int nt = 0; nt < 8; nt++)
#pragma unroll
            for (int r = 0; r < 4; r++) qcc[nt][r] = 0;
#pragma unroll
        for (int s = 0; s < 2; s++)
#pragma unroll
            for (int nt = 0; nt < 8; nt++) {
                unsigned kl = (unsigned)(kk[nt] >> (32 * s));
                unsigned b0 = expand4((kl >> (4 * tg)) & 0xFu);
                unsigned b1 = expand4((kl >> (16 + 4 * tg)) & 0xFu);
                mma_s8(qcc[nt], qa[s][0], qa[s][1], qa[s][2], qa[s][3], b0, b1);
            }
        int t0 = rowA, t1 = rowA + 8;
#pragma unroll
        for (int nt = 0; nt < 8; nt++) {
            int kc = nt * 8 + 2 * tg;
            unsigned v00 = (kc <= t0) ? (qcc[nt][0] & 0xFF) : 0u;
            unsigned v01 = (kc + 1 <= t0) ? (qcc[nt][1] & 0xFF) : 0u;
            unsigned v10 = (kc <= t1) ? (qcc[nt][2] & 0xFF) : 0u;
            unsigned v11 = (kc + 1 <= t1) ? (qcc[nt][3] & 0xFF) : 0u;
            *(unsigned short*)&csh[t0 * 68 + kc] = (unsigned short)(v00 | (v01 << 8));
            *(unsigned short*)&csh[t1 * 68 + kc] = (unsigned short)(v10 | (v11 << 8));
        }
        __syncwarp();
#pragma unroll
        for (int s = 0; s < 2; s++) {
            unsigned a0 = *(const unsigned*)&csh[rowA * 68 + s * 32 + tg * 4];
            unsigned a1 = *(const unsigned*)&csh[(rowA + 8) * 68 + s * 32 + tg * 4];
            unsigned a2 = *(const unsigned*)&csh[rowA * 68 + s * 32 + 16 + tg * 4];
            unsigned a3 = *(const unsigned*)&csh[(rowA + 8) * 68 + s * 32 + 16 + tg * 4];
#pragma unroll
            for (int nt = 0; nt < 8; nt++) {
                unsigned b0 = expand4((unsigned)(vt[nt] >> (s * 32 + tg * 4)) & 0xFu);
                unsigned b1 = expand4((unsigned)(vt[nt] >> (s * 32 + 16 + tg * 4)) & 0xFu);
                mma_s8(acc[nt], a0, a1, a2, a3, b0, b1);
            }
        }
    }

    __syncthreads();
#pragma unroll
    for (int nt = 0; nt < 8; ++nt) {
        int d0 = nt * 8 + tg * 2;
        csh[d0 * 68 + rowA]           = ((float)acc[nt][0] * scale >= 1.0f) ? 1 : 0;
        csh[(d0 + 1) * 68 + rowA]     = ((float)acc[nt][1] * scale >= 1.0f) ? 1 : 0;
        csh[d0 * 68 + rowA + 8]       = ((float)acc[nt][2] * scale >= 1.0f) ? 1 : 0;
        csh[(d0 + 1) * 68 + rowA + 8] = ((float)acc[nt][3] * scale >= 1.0f) ? 1 : 0;
    }
    __syncthreads();
    {
        int d = tid >> 1, hf = tid & 1;
        size_t b = (size_t)(bh >> 3), h = (size_t)(bh & 7);
        size_t off = (b << 20) + (h << 17) + ((size_t)d << 11)
                   + (size_t)tq * 64 + (size_t)hf * 32;
#pragma unroll
        for (int q4 = 0; q4 < 32; q4 += 4) {
            unsigned v = *(const unsigned*)&csh[d * 68 + hf * 32 + q4];
            *(unsigned*)(g_xs + off + q4) = v;
        }
    }
}

// =====================================================================
// Output projection: register-prefetch pipeline (A uint4 from g_xs +
// W 3x uint4), same MMA op order as 301us run.
// =====================================================================
__global__ __launch_bounds__(256, 2) void out_mma_kernel(
    const float* __restrict__ bias, float* __restrict__ out)
{
    __shared__ unsigned short Asp[128 * SROW];
    __shared__ unsigned short Wsp[3 * 64 * SROW];

    const int tid  = threadIdx.x;
    const int lane = tid & 31;
    const int g    = lane >> 2, tg = lane & 3;
    const int wrp  = tid >> 5;
    const int mw   = wrp >> 1, nw = wrp & 1;

    int s2 = blockIdx.x;
    int n0 = (s2 & 7) * 64, m0 = (s2 >> 3) * 128;

    const unsigned short* gW = g_wsp + (size_t)3 * 3 * 512 * 512;
    const unsigned abase = (unsigned)__cvta_generic_to_shared(Asp);
    const unsigned wbase = (unsigned)__cvta_generic_to_shared(Wsp);

    float C[2][4][4];
#pragma unroll
    for (int mt = 0; mt < 2; mt++)
#pragma unroll
        for (int nt = 0; nt < 4; nt++)
#pragma unroll
            for (int r = 0; r < 4; r++) C[mt][nt][r] = 0.f;

    const int arow_l = lane & 15;
    const int ak8 = (lane >> 4) * 8;
    const int brow = (lane & 7) + ((lane & 16) >> 1);
    const int bk8 = (lane & 8);
    const int xrow = tid >> 1, xhalf = tid & 1;
    const int wrow = (tid >> 2) & 63, wpart = tid & 3;

    uint4 pa, pwa, pwb, pwc;
    pa  = *(const uint4*)(g_xs + (size_t)(m0 + xrow) * DD + 0 + xhalf * 16);
    pwa = *(const uint4*)(gW + ((size_t)0 * 512 + n0 + wrow) * 512 + 0 + wpart * 8);
    pwb = *(const uint4*)(gW + ((size_t)1 * 512 + n0 + wrow) * 512 + 0 + wpart * 8);
    pwc = *(const uint4*)(gW + ((size_t)2 * 512 + n0 + wrow) * 512 + 0 + wpart * 8);

    for (int ch = 0; ch < 16; ++ch) {
        const int k0 = ch << 5;
        __syncthreads();
        // ---- A bytes -> bf16 -> STS ----
        {
            unsigned w0 = pa.x, w1 = pa.y, w2 = pa.z, w3 = pa.w;
            uint4 o0, o1;
            o0.x = ((w0 & 1u) ? 0x3F80u : 0u) | ((w0 & 0x100u) ? 0x3F800000u : 0u);
            o0.y = (((w0 >> 16) & 1u) ? 0x3F80u : 0u) | ((w0 & 0x1000000u) ? 0x3F800000u : 0u);
            o0.z = ((w1 & 1u) ? 0x3F80u : 0u) | ((w1 & 0x100u) ? 0x3F800000u : 0u);
            o0.w = (((w1 >> 16) & 1u) ? 0x3F80u : 0u) | ((w1 & 0x1000000u) ? 0x3F800000u : 0u);
            o1.x = ((w2 & 1u) ? 0x3F80u : 0u) | ((w2 & 0x100u) ? 0x3F800000u : 0u);
            o1.y = (((w2 >> 16) & 1u) ? 0x3F80u : 0u) | ((w2 & 0x1000000u) ? 0x3F800000u : 0u);
            o1.z = ((w3 & 1u) ? 0x3F80u : 0u) | ((w3 & 0x100u) ? 0x3F800000u : 0u);
            o1.w = (((w3 >> 16) & 1u) ? 0x3F80u : 0u) | ((w3 & 0x1000000u) ? 0x3F800000u : 0u);
            unsigned short* dstp = &Asp[xrow * SROW + xhalf * 16];
            *(uint4*)dstp       = o0;
            *(uint4*)(dstp + 8) = o1;
        }
        // ---- W STS ----
        *(uint4*)&Wsp[(0 * 64 + wrow) * SROW + wpart * 8] = pwa;
        *(uint4*)&Wsp[(1 * 64 + wrow) * SROW + wpart * 8] = pwb;
        *(uint4*)&Wsp[(2 * 64 + wrow) * SROW + wpart * 8] = pwc;
        __syncthreads();
        // ---- prefetch ch+1 ----
        if (ch + 1 < 16) {
            const int kn = k0 + 32;
            pa  = *(const uint4*)(g_xs + (size_t)(m0 + xrow) * DD + kn + xhalf * 16);
            pwa = *(const uint4*)(gW + ((size_t)0 * 512 + n0 + wrow) * 512 + kn + wpart * 8);
            pwb = *(const uint4*)(gW + ((size_t)1 * 512 + n0 + wrow) * 512 + kn + wpart * 8);
            pwc = *(const uint4*)(gW + ((size_t)2 * 512 + n0 + wrow) * 512 + kn + wpart * 8);
        }
        // ---- MMA ----
#pragma unroll
        for (int s = 0; s < 2; ++s) {
            unsigned af[2][4];
#pragma unroll
            for (int mt = 0; mt < 2; mt++) {
                unsigned a = abase +
                    (((mw * 32 + mt * 16 + arow_l) * SROW) + s * 16 + ak8) * 2;
                ldsm4(af[mt][0], af[mt][1], af[mt][2], af[mt][3], a);
            }
#pragma unroll
            for (int j = 0; j < 3; j++) {
                unsigned bfr[2][4];
#pragma unroll
                for (int np = 0; np < 2; np++) {
                    unsigned a = wbase +
                        (((j * 64 + nw * 32 + np * 16 + brow) * SROW) +
                         s * 16 + bk8) * 2;
                    ldsm4(bfr[np][0], bfr[np][1], bfr[np][2], bfr[np][3], a);
                }
#pragma unroll
                for (int mt = 0; mt < 2; mt++)
#pragma unroll
                    for (int np = 0; np < 2; np++) {
                        mma_bf16(C[mt][np * 2], af[mt][0], af[mt][1], af[mt][2],
                                 af[mt][3], bfr[np][0], bfr[np][1]);
                        mma_bf16(C[mt][np * 2 + 1], af[mt][0], af[mt][1], af[mt][2],
                                 af[mt][3], bfr[np][2], bfr[np][3]);
                    }
            }
        }
    }

#pragma unroll
    for (int mt = 0; mt < 2; mt++)
#pragma unroll
        for (int nt = 0; nt < 4; nt++) {
            int row = m0 + mw * 32 + mt * 16 + g;
            int col = n0 + nw * 32 + nt * 8 + tg * 2;
            float2 bb = *(const float2*)&bias[col];
            float2 r0, r1;
            r0.x = (C[mt][nt][0] + bb.x >= 1.0f) ? 1.0f : 0.0f;
            r0.y = (C[mt][nt][1] + bb.y >= 1.0f) ? 1.0f : 0.0f;
            r1.x = (C[mt][nt][2] + bb.x >= 1.0f) ? 1.0f : 0.0f;
            r1.y = (C[mt][nt][3] + bb.y >= 1.0f) ? 1.0f : 0.0f;
            *(float2*)&out[(size_t)row * DD + col] = r0;
            *(float2*)&out[(size_t)(row + 8) * DD + col] = r1;
        }
}

// ---------------- launch ----------------
extern "C" void kernel_launch(void* const* d_in, const int* in_sizes, int n_in,
                              void* d_out, int out_size)
{
    const float* query = (const float*)d_in[0];
    const float* key   = (const float*)d_in[1];
    const float* value = (const float*)d_in[2];
    const float* scale = (const float*)d_in[3];
    const float* Wq = (const float*)d_in[4];  const float* bq = (const float*)d_in[5];
    const float* Wk = (const float*)d_in[6];  const float* bk = (const float*)d_in[7];
    const float* Wv = (const float*)d_in[8];  const float* bv = (const float*)d_in[9];
    const float* Wo = (const float*)d_in[10]; const float* bo = (const float*)d_in[11];
    float* out = (float*)d_out;

    const int DIN = in_sizes[0] / MROWS;   // 100

    prep_w_kernel<<<dim3(8, 8, 4), 256>>>(Wq, Wk, Wv, Wo);
    qkv_mma_kernel<<<1536, 256>>>(query, key, value, bq, bk, bv, DIN);
    trans_kernel<<<2048, 64>>>();
    kvprod_kernel<<<BHN * NTW, 128>>>();
    attn_kernel<<<BHN * NTW, 128>>>(scale);
    out_mma_kernel<<<512, 256>>>(bo, out);
}

// round 12
// speedup vs baseline: 1.9129x; 1.0012x over previous
#include <cuda_runtime.h>
#include <cstdint>

#define BB 4
#define TT 2048
#define DD 512
#define HH 8
#define DK 64
#define BHN (BB*HH)          // 32
#define NTW (TT/64)          // 32 k-tiles
#define MROWS (BB*TT)        // 8192
#define SROW 40              // smem row stride (bf16 units) = 80B

// ---------------- scratch (proven ~17 MB footprint) ----------------
__device__ unsigned long long g_qb[BHN*TT];
__device__ unsigned long long g_kb[BHN*TT];
__device__ unsigned long long g_vb[BHN*TT];
__device__ unsigned long long g_vT[BHN*DK*NTW];      // [bh][d][w]
__device__ unsigned long long g_kT[BHN*DK*NTW];      // [bh][j][w]
__device__ unsigned char      g_xs[BB*TT*DD];
__device__ unsigned short     g_wsp[4*3*512*512];    // pre-split W (6 MB)
__device__ unsigned char      g_kv[BHN*NTW*64*64];   // KV tiles s8 (4 MB)

// ---------------- helpers ----------------
__device__ __forceinline__ unsigned expand4(unsigned x) {
    return (x * 0x00204081u) & 0x01010101u;
}
__device__ __forceinline__ void mma_s8(int* c, unsigned a0, unsigned a1, unsigned a2,
                                       unsigned a3, unsigned b0, unsigned b1) {
    asm volatile(
        "mma.sync.aligned.m16n8k32.row.col.s32.s8.s8.s32 "
        "{%0,%1,%2,%3}, {%4,%5,%6,%7}, {%8,%9}, {%0,%1,%2,%3};"
        : "+r"(c[0]), "+r"(c[1]), "+r"(c[2]), "+r"(c[3])
        : "r"(a0), "r"(a1), "r"(a2), "r"(a3), "r"(b0), "r"(b1));
}
__device__ __forceinline__ void mma_bf16(float* c, unsigned a0, unsigned a1,
                                         unsigned a2, unsigned a3,
                                         unsigned b0, unsigned b1) {
    asm volatile(
        "mma.sync.aligned.m16n8k16.row.col.f32.bf16.bf16.f32 "
        "{%0,%1,%2,%3}, {%4,%5,%6,%7}, {%8,%9}, {%0,%1,%2,%3};"
        : "+f"(c[0]), "+f"(c[1]), "+f"(c[2]), "+f"(c[3])
        : "r"(a0), "r"(a1), "r"(a2), "r"(a3), "r"(b0), "r"(b1));
}
__device__ __forceinline__ void split3(float a, unsigned short& s0,
                                       unsigned short& s1, unsigned short& s2) {
    unsigned u0 = __float_as_uint(a);
    s0 = (unsigned short)(u0 >> 16);
    float r1 = a - __uint_as_float(u0 & 0xFFFF0000u);
    unsigned u1 = __float_as_uint(r1);
    s1 = (unsigned short)(u1 >> 16);
    float r2 = r1 - __uint_as_float(u1 & 0xFFFF0000u);
    s2 = (unsigned short)(__float_as_uint(r2) >> 16);
}
// PRMT pair-pack: result = {hi16(va), hi16(vb)} packed little-endian
__device__ __forceinline__ unsigned prmt7632(unsigned a, unsigned b) {
    unsigned r;
    asm("prmt.b32 %0, %1, %2, 0x7632;" : "=r"(r) : "r"(a), "r"(b));
    return r;
}
__device__ __forceinline__ float trunchi(float a) {
    return __uint_as_float(__float_as_uint(a) & 0xFFFF0000u);
}
__device__ __forceinline__ void ldsm4(unsigned& r0, unsigned& r1, unsigned& r2,
                                      unsigned& r3, unsigned addr) {
    asm volatile("ldmatrix.sync.aligned.m8n8.x4.shared.b16 {%0,%1,%2,%3}, [%4];"
                 : "=r"(r0), "=r"(r1), "=r"(r2), "=r"(r3) : "r"(addr));
}
__device__ __forceinline__ void cpa16(unsigned dst, const void* src) {
    asm volatile("cp.async.cg.shared.global [%0], [%1], 16;" :: "r"(dst), "l"(src));
}
#define CP_COMMIT() asm volatile("cp.async.commit_group;")
#define CP_WAIT(n)  asm volatile("cp.async.wait_group %0;" :: "n"(n) : "memory")

// =====================================================================
// prep: split W (transposed to [n][k]) into g_wsp.
// =====================================================================
__global__ void prep_w_kernel(const float* __restrict__ Wq, const float* __restrict__ Wk,
                              const float* __restrict__ Wv, const float* __restrict__ Wo)
{
    __shared__ float sh[64][68];
    int w = blockIdx.z;
    const float* W = (w == 0) ? Wq : (w == 1) ? Wk : (w == 2) ? Wv : Wo;
    int k0 = blockIdx.x * 64, n0 = blockIdx.y * 64;
    int t = threadIdx.x;
#pragma unroll
    for (int r = 0; r < 4; r++) {
        int row = (t >> 4) * 4 + r;
        int col = (t & 15) * 4;
        float4 v = *(const float4*)&W[(size_t)(k0 + row) * DD + n0 + col];
        sh[row][col] = v.x; sh[row][col+1] = v.y; sh[row][col+2] = v.z; sh[row][col+3] = v.w;
    }
    __syncthreads();
#pragma unroll
    for (int r = 0; r < 4; r++) {
        int n = (t >> 4) * 4 + r;
        int k4 = (t & 15) * 4;
        unsigned short a0, a1, a2, b0, b1, b2, c0, c1, c2, d0, d1, d2;
        split3(sh[k4 + 0][n], a0, a1, a2);
        split3(sh[k4 + 1][n], b0, b1, b2);
        split3(sh[k4 + 2][n], c0, c1, c2);
        split3(sh[k4 + 3][n], d0, d1, d2);
        size_t base = ((size_t)(w * 3) * 512 + (n0 + n)) * 512 + k0 + k4;
        const size_t P = (size_t)512 * 512;
        *(uint2*)&g_wsp[base] =
            make_uint2((unsigned)a0 | ((unsigned)b0 << 16),
                       (unsigned)c0 | ((unsigned)d0 << 16));
        *(uint2*)&g_wsp[base + P] =
            make_uint2((unsigned)a1 | ((unsigned)b1 << 16),
                       (unsigned)c1 | ((unsigned)d1 << 16));
        *(uint2*)&g_wsp[base + 2 * P] =
            make_uint2((unsigned)a2 | ((unsigned)b2 << 16),
                       (unsigned)c2 | ((unsigned)d2 << 16));
    }
}

// =====================================================================
// qkv GEMM: register-prefetch pipeline + PRMT pair-split.
// =====================================================================
#define QKV_LOAD_A(K0)                                                        \
    do {                                                                      \
        if (which != 2) {                                                     \
            const float4* ap = (const float4*)(A + (size_t)(m0 + arow) * DD + (K0) + akh); \
            float4 x0 = ap[0], x1 = ap[1], x2 = ap[2], x3 = ap[3];            \
            pv0=x0.x; pv1=x0.y; pv2=x0.z; pv3=x0.w;                           \
            pv4=x1.x; pv5=x1.y; pv6=x1.z; pv7=x1.w;                           \
            pv8=x2.x; pv9=x2.y; pva=x2.z; pvb=x2.w;                           \
            pvc=x3.x; pvd=x3.y; pve=x3.z; pvf=x3.w;                           \
        } else {                                                              \
            const float* ar = A + (size_t)(m0 + arow) * KA;                   \
            int kb = (K0) + akh;                                              \
            pv0 = (kb+0 < KA) ? ar[kb+0] : 0.f;  pv1 = (kb+1 < KA) ? ar[kb+1] : 0.f; \
            pv2 = (kb+2 < KA) ? ar[kb+2] : 0.f;  pv3 = (kb+3 < KA) ? ar[kb+3] : 0.f; \
            pv4 = (kb+4 < KA) ? ar[kb+4] : 0.f;  pv5 = (kb+5 < KA) ? ar[kb+5] : 0.f; \
            pv6 = (kb+6 < KA) ? ar[kb+6] : 0.f;  pv7 = (kb+7 < KA) ? ar[kb+7] : 0.f; \
            pv8 = (kb+8 < KA) ? ar[kb+8] : 0.f;  pv9 = (kb+9 < KA) ? ar[kb+9] : 0.f; \
            pva = (kb+10 < KA) ? ar[kb+10] : 0.f; pvb = (kb+11 < KA) ? ar[kb+11] : 0.f; \
            pvc = (kb+12 < KA) ? ar[kb+12] : 0.f; pvd = (kb+13 < KA) ? ar[kb+13] : 0.f; \
            pve = (kb+14 < KA) ? ar[kb+14] : 0.f; pvf = (kb+15 < KA) ? ar[kb+15] : 0.f; \
        }                                                                     \
    } while (0)

#define QKV_LOAD_W(K0)                                                        \
    do {                                                                      \
        pwa = *(const uint4*)(gW + ((size_t)0 * 512 + n0 + wrow) * 512 + (K0) + wpart * 8); \
        pwb = *(const uint4*)(gW + ((size_t)1 * 512 + n0 + wrow) * 512 + (K0) + wpart * 8); \
        pwc = *(const uint4*)(gW + ((size_t)2 * 512 + n0 + wrow) * 512 + (K0) + wpart * 8); \
    } while (0)

// PRMT pair-split: two fp32 -> packed bf16 pair per plane (bit-identical to split3)
#define SPLITPAIR(I, VA, VB)                                                  \
    do {                                                                      \
        float ra_ = (VA), rb_ = (VB);                                         \
        p0_[I] = prmt7632(__float_as_uint(ra_), __float_as_uint(rb_));        \
        ra_ -= trunchi(ra_); rb_ -= trunchi(rb_);                             \
        p1_[I] = prmt7632(__float_as_uint(ra_), __float_as_uint(rb_));        \
        ra_ -= trunchi(ra_); rb_ -= trunchi(rb_);                             \
        p2_[I] = prmt7632(__float_as_uint(ra_), __float_as_uint(rb_));        \
    } while (0)

__global__ __launch_bounds__(256, 2) void qkv_mma_kernel(
    const float* __restrict__ Aq, const float* __restrict__ Ak,
    const float* __restrict__ Av,
    const float* __restrict__ bq, const float* __restrict__ bk,
    const float* __restrict__ bv, int DIN)
{
    __shared__ char smemraw[46080];   // A planes [0,30720), W [30720,46080)

    const int tid  = threadIdx.x;
    const int lane = tid & 31;
    const int g    = lane >> 2, tg = lane & 3;
    const int wrp  = tid >> 5;
    const int mw   = wrp >> 1, nw = wrp & 1;

    int idx = blockIdx.x;
    int which = idx >> 9;                      // 0=k,1=v,2=q
    int s2 = idx & 511;
    int n0 = (s2 & 7) * 64, m0 = (s2 >> 3) * 128;

    const float* A    = (which == 0) ? Ak : (which == 1) ? Av : Aq;
    const float* bias = (which == 0) ? bk : (which == 1) ? bv : bq;
    const int KA = DIN;
    const int KS = (which == 2) ? 128 : DD;
    const int wsel = (which == 0) ? 1 : (which == 1) ? 2 : 0;
    const unsigned short* gW = g_wsp + (size_t)wsel * 3 * 512 * 512;

    const unsigned sbase = (unsigned)__cvta_generic_to_shared(smemraw);
    const unsigned wbase = sbase + 30720;

    float C[2][4][4];
#pragma unroll
    for (int mt = 0; mt < 2; mt++)
#pragma unroll
        for (int nt = 0; nt < 4; nt++)
#pragma unroll
            for (int r = 0; r < 4; r++) C[mt][nt][r] = 0.f;

    const int arow = tid >> 1, akh = (tid & 1) * 16;
    const int arow_l = lane & 15;
    const int ak8 = (lane >> 4) * 8;
    const int brow = (lane & 7) + ((lane & 16) >> 1);
    const int bk8 = (lane & 8);
    const int wrow = (tid >> 2) & 63, wpart = tid & 3;

    float pv0,pv1,pv2,pv3,pv4,pv5,pv6,pv7,pv8,pv9,pva,pvb,pvc,pvd,pve,pvf;
    uint4 pwa, pwb, pwc;

    QKV_LOAD_A(0);
    QKV_LOAD_W(0);

    const int nch = KS >> 5;
    for (int ch = 0; ch < nch; ++ch) {
        const int k0 = ch << 5;
        __syncthreads();                       // prev MMA done reading smem
        // ---- A: PRMT pair-split -> STS 3 planes ----
        {
            unsigned p0_[8], p1_[8], p2_[8];
            SPLITPAIR(0, pv0, pv1); SPLITPAIR(1, pv2, pv3);
            SPLITPAIR(2, pv4, pv5); SPLITPAIR(3, pv6, pv7);
            SPLITPAIR(4, pv8, pv9); SPLITPAIR(5, pva, pvb);
            SPLITPAIR(6, pvc, pvd); SPLITPAIR(7, pve, pvf);
            unsigned short* base0 = (unsigned short*)smemraw + arow * SROW + akh;
            const int PL = 128 * SROW;
            *(uint4*)(base0)              = make_uint4(p0_[0], p0_[1], p0_[2], p0_[3]);
            *(uint4*)(base0 + 8)          = make_uint4(p0_[4], p0_[5], p0_[6], p0_[7]);
            *(uint4*)(base0 + PL)         = make_uint4(p1_[0], p1_[1], p1_[2], p1_[3]);
            *(uint4*)(base0 + PL + 8)     = make_uint4(p1_[4], p1_[5], p1_[6], p1_[7]);
            *(uint4*)(base0 + 2 * PL)     = make_uint4(p2_[0], p2_[1], p2_[2], p2_[3]);
            *(uint4*)(base0 + 2 * PL + 8) = make_uint4(p2_[4], p2_[5], p2_[6], p2_[7]);
        }
        // ---- W: STS prefetched uint4s ----
        {
            char* wd = smemraw + 30720;
            *(uint4*)(wd + (((0 * 64 + wrow) * SROW) + wpart * 8) * 2) = pwa;
            *(uint4*)(wd + (((1 * 64 + wrow) * SROW) + wpart * 8) * 2) = pwb;
            *(uint4*)(wd + (((2 * 64 + wrow) * SROW) + wpart * 8) * 2) = pwc;
        }
        __syncthreads();                       // tiles visible
        // ---- prefetch chunk ch+1 (overlaps with MMA below) ----
        if (ch + 1 < nch) {
            QKV_LOAD_A(k0 + 32);
            QKV_LOAD_W(k0 + 32);
        }
        // ---- MMA phase (identical op order) ----
#pragma unroll
        for (int s = 0; s < 2; ++s) {
            unsigned af[3][2][4];
#pragma unroll
            for (int sp = 0; sp < 3; sp++)
#pragma unroll
                for (int mt = 0; mt < 2; mt++) {
                    unsigned a = sbase +
                        (((sp * 128 + mw * 32 + mt * 16 + arow_l) * SROW) +
                         s * 16 + ak8) * 2;
                    ldsm4(af[sp][mt][0], af[sp][mt][1], af[sp][mt][2], af[sp][mt][3], a);
                }
#pragma unroll
            for (int j = 0; j < 3; j++) {
                unsigned bfr[2][4];
#pragma unroll
                for (int np = 0; np < 2; np++) {
                    unsigned a = wbase +
                        (((j * 64 + nw * 32 + np * 16 + brow) * SROW) +
                         s * 16 + bk8) * 2;
                    ldsm4(bfr[np][0], bfr[np][1], bfr[np][2], bfr[np][3], a);
                }
#pragma unroll
                for (int i = 0; i < 3; i++) {
                    if (i + j > 2) break;
#pragma unroll
                    for (int mt = 0; mt < 2; mt++)
#pragma unroll
                        for (int np = 0; np < 2; np++) {
                            mma_bf16(C[mt][np * 2], af[i][mt][0], af[i][mt][1],
                                     af[i][mt][2], af[i][mt][3],
                                     bfr[np][0], bfr[np][1]);
                            mma_bf16(C[mt][np * 2 + 1], af[i][mt][0], af[i][mt][1],
                                     af[i][mt][2], af[i][mt][3],
                                     bfr[np][2], bfr[np][3]);
                        }
                }
            }
        }
    }

    // ---- epilogue: bias + spike -> bytes (overlay smem) -> bitpack ----
    __syncthreads();
    unsigned char* sbyte = (unsigned char*)smemraw;
#pragma unroll
    for (int mt = 0; mt < 2; mt++)
#pragma unroll
        for (int nt = 0; nt < 4; nt++) {
            int row = mw * 32 + mt * 16 + g;
            int col = nw * 32 + nt * 8 + tg * 2;
            float2 bb = *(const float2*)&bias[n0 + col];
            sbyte[row * 64 + col]           = (C[mt][nt][0] + bb.x >= 1.0f) ? 1 : 0;
            sbyte[row * 64 + col + 1]       = (C[mt][nt][1] + bb.y >= 1.0f) ? 1 : 0;
            sbyte[(row + 8) * 64 + col]     = (C[mt][nt][2] + bb.x >= 1.0f) ? 1 : 0;
            sbyte[(row + 8) * 64 + col + 1] = (C[mt][nt][3] + bb.y >= 1.0f) ? 1 : 0;
        }
    __syncthreads();
    if (tid < 128) {
        unsigned long long bits = 0ull;
#pragma unroll
        for (int q = 0; q < 8; q++) {
            unsigned long long u = *(const unsigned long long*)&sbyte[tid * 64 + 8 * q];
#pragma unroll
            for (int j = 0; j < 8; j++)
                bits |= ((u >> (8 * j)) & 1ull) << (8 * q + j);
        }
        int m = m0 + tid;
        int b = m >> 11, t = m & 2047;
        int head = n0 >> 6;
        unsigned long long* dst = (which == 2) ? g_qb : (which == 0) ? g_kb : g_vb;
        dst[(size_t)((b << 3) + head) * TT + t] = bits;
    }
}

// ---------------- bit transpose for k and v ----------------
__global__ void trans_kernel()
{
    int bx = blockIdx.x;
    int which = bx >> 10;
    int idx = bx & 1023;
    int bh = idx >> 5, w = idx & 31;
    int tid = threadIdx.x;
    int lane = tid & 31, warp = tid >> 5;
    __shared__ unsigned sh[64][2];
    const unsigned long long* src = (which == 0) ? g_vb : g_kb;
    unsigned long long* dst = (which == 0) ? g_vT : g_kT;
    unsigned long long r = src[(size_t)bh * TT + w * 64 + tid];
#pragma unroll 8
    for (int d = 0; d < 64; d++) {
        unsigned b = __ballot_sync(0xffffffffu, (unsigned)((r >> d) & 1ull));
        if (lane == 0) sh[d][warp] = b;
    }
    __syncthreads();
    dst[(size_t)(bh * 64 + tid) * 32 + w] =
        (unsigned long long)sh[tid][0] | ((unsigned long long)sh[tid][1] << 32);
}

// =====================================================================
// KV precompute (unchanged).
// =====================================================================
__global__ __launch_bounds__(128) void kvprod_kernel()
{
    const int tid = threadIdx.x;
    const int lane = tid & 31;
    const int g = lane >> 2, tg = lane & 3;
    const int wr16 = (tid >> 5) * 16;

    int bh = blockIdx.x >> 5, w = blockIdx.x & 31;

    unsigned long long vd0 = g_vT[((size_t)bh * 64 + wr16 + g) * 32 + w];
    unsigned long long vd1 = g_vT[((size_t)bh * 64 + wr16 + 8 + g) * 32 + w];
    unsigned long long kt[8];
#pragma unroll
    for (int nt = 0; nt < 8; nt++)
        kt[nt] = g_kT[((size_t)bh * 64 + nt * 8 + g) * 32 + w];

    int acc[8][4];
#pragma unroll
    for (int nt = 0; nt < 8; nt++)
#pragma unroll
        for (int r = 0; r < 4; r++) acc[nt][r] = 0;

#pragma unroll
    for (int s = 0; s < 2; s++) {
        unsigned l0 = (unsigned)(vd0 >> (32 * s));
        unsigned l1 = (unsigned)(vd1 >> (32 * s));
        unsigned a0 = expand4((l0 >> (4 * tg)) & 0xFu);
        unsigned a1 = expand4((l1 >> (4 * tg)) & 0xFu);
        unsigned a2 = expand4((l0 >> (16 + 4 * tg)) & 0xFu);
        unsigned a3 = expand4((l1 >> (16 + 4 * tg)) & 0xFu);
#pragma unroll
        for (int nt = 0; nt < 8; nt++) {
            unsigned kl = (unsigned)(kt[nt] >> (32 * s));
            unsigned b0 = expand4((kl >> (4 * tg)) & 0xFu);
            unsigned b1 = expand4((kl >> (16 + 4 * tg)) & 0xFu);
            mma_s8(acc[nt], a0, a1, a2, a3, b0, b1);
        }
    }

    unsigned char* dst = g_kv + ((size_t)(bh * 32 + w) * 64) * 64;
#pragma unroll
    for (int nt = 0; nt < 8; nt++) {
        int j0 = nt * 8 + 2 * tg;
        *(unsigned short*)(dst + (wr16 + g) * 64 + j0) =
            (unsigned short)((acc[nt][0] & 0xFF) | ((acc[nt][1] & 0xFF) << 8));
        *(unsigned short*)(dst + (wr16 + 8 + g) * 64 + j0) =
            (unsigned short)((acc[nt][2] & 0xFF) | ((acc[nt][3] & 0xFF) << 8));
    }
}

// =====================================================================
// Attention (unchanged from 275us run).
// =====================================================================
__global__ __launch_bounds__(128) void attn_kernel(const float* __restrict__ scale_p)
{
    __shared__ __align__(16) unsigned char KVsh[2][64 * 80];
    __shared__ unsigned char csh[64 * 68];
    __shared__ unsigned long long ksh[64];

    const int tid = threadIdx.x;
    const int lane = tid & 31;
    const int g = lane >> 2, tg = lane & 3;
    const int wr16 = (tid >> 5) * 16;
    const int rowA = wr16 + g;

    int bx = blockIdx.x;
    int bh = bx & 31;
    int tq = 31 - (bx >> 5);

    const float scale = *scale_p;
    const size_t base = (size_t)bh * TT;
    const unsigned char* KVg = g_kv + (size_t)bh * 32 * 64 * 64;

    unsigned long long q0 = g_qb[base + (size_t)tq * 64 + rowA];
    unsigned long long q1 = g_qb[base + (size_t)tq * 64 + rowA + 8];
    unsigned qa[2][4];
#pragma unroll
    for (int s = 0; s < 2; s++) {
        unsigned l0 = (unsigned)(q0 >> (32 * s));
        unsigned l1 = (unsigned)(q1 >> (32 * s));
        qa[s][0] = expand4((l0 >> (4 * tg)) & 0xFu);
        qa[s][1] = expand4((l1 >> (4 * tg)) & 0xFu);
        qa[s][2] = expand4((l0 >> (16 + 4 * tg)) & 0xFu);
        qa[s][3] = expand4((l1 >> (16 + 4 * tg)) & 0xFu);
    }

    int acc[8][4];
#pragma unroll
    for (int nt = 0; nt < 8; nt++)
#pragma unroll
        for (int r = 0; r < 4; r++) acc[nt][r] = 0;

    const int kvrow0 = tid >> 2, kvp0 = tid & 3;
    const int kvrow1 = (tid + 128) >> 2, kvp1 = tid & 3;
    const unsigned kvb0 = (unsigned)__cvta_generic_to_shared(&KVsh[0][0]);
    const unsigned kvb1 = (unsigned)__cvta_generic_to_shared(&KVsh[1][0]);

    if (tq > 0) {
        cpa16(kvb0 + kvrow0 * 80 + kvp0 * 16, KVg + 0 * 4096 + kvrow0 * 64 + kvp0 * 16);
        cpa16(kvb0 + kvrow1 * 80 + kvp1 * 16, KVg + 0 * 4096 + kvrow1 * 64 + kvp1 * 16);
        CP_COMMIT();
    }
    for (int w = 0; w < tq; ++w) {
        __syncthreads();
        if (w + 1 < tq) {
            unsigned kb = ((w + 1) & 1) ? kvb1 : kvb0;
            const unsigned char* src = KVg + (size_t)(w + 1) * 4096;
            cpa16(kb + kvrow0 * 80 + kvp0 * 16, src + kvrow0 * 64 + kvp0 * 16);
            cpa16(kb + kvrow1 * 80 + kvp1 * 16, src + kvrow1 * 64 + kvp1 * 16);
            CP_COMMIT();
            CP_WAIT(1);
        } else {
            CP_WAIT(0);
        }
        __syncthreads();
        const unsigned char* kb = KVsh[w & 1];
#pragma unroll
        for (int s = 0; s < 2; s++)
#pragma unroll
            for (int nt = 0; nt < 8; nt++) {
                unsigned b0 = *(const unsigned*)(kb + (nt * 8 + g) * 80 + s * 32 + tg * 4);
                unsigned b1 = *(const unsigned*)(kb + (nt * 8 + g) * 80 + s * 32 + 16 + tg * 4);
                mma_s8(acc[nt], qa[s][0], qa[s][1], qa[s][2], qa[s][3], b0, b1);
            }
    }

    if (tid < 64) ksh[tid] = g_kb[base + (size_t)tq * 64 + tid];
    unsigned long long vt[8];
#pragma unroll
    for (int nt = 0; nt < 8; nt++)
        vt[nt] = g_vT[((size_t)bh * 64 + nt * 8 + g) * 32 + tq];
    __syncthreads();

    {
        unsigned long long kk[8];
#pragma unroll
        for (int nt = 0; nt < 8; nt++) kk[nt] = ksh[nt * 8 + g];
        int qcc[8][4];
#pragma unroll
        for (int nt = 0; nt < 8; nt++)
#pragma unroll
            for (int r = 0; r < 4; r++) qcc[nt][r] = 0;
#pragma unroll
        for (int s = 0; s < 2; s++)
#pragma unroll
            for (int nt = 0; nt < 8; nt++) {
                unsigned kl = (unsigned)(kk[nt] >> (32 * s));
                unsigned b0 = expand4((kl >> (4 * tg)) & 0xFu);
                unsigned b1 = expand4((kl >> (16 + 4 * tg)) & 0xFu);
                mma_s8(qcc[nt], qa[s][0], qa[s][1], qa[s][2], qa[s][3], b0, b1);
            }
        int t0 = rowA, t1 = rowA + 8;
#pragma unroll
        for (int nt = 0; nt < 8; nt++) {
            int kc = nt * 8 + 2 * tg;
            unsigned v00 = (kc <= t0) ? (qcc[nt][0] & 0xFF) : 0u;
            unsigned v01 = (kc + 1 <= t0) ? (qcc[nt][1] & 0xFF) : 0u;
            unsigned v10 = (kc <= t1) ? (qcc[nt][2] & 0xFF) : 0u;
            unsigned v11 = (kc + 1 <= t1) ? (qcc[nt][3] & 0xFF) : 0u;
            *(unsigned short*)&csh[t0 * 68 + kc] = (unsigned short)(v00 | (v01 << 8));
            *(unsigned short*)&csh[t1 * 68 + kc] = (unsigned short)(v10 | (v11 << 8));
        }
        __syncwarp();
#pragma unroll
        for (int s = 0; s < 2; s++) {
            unsigned a0 = *(const unsigned*)&csh[rowA * 68 + s * 32 + tg * 4];
            unsigned a1 = *(const unsigned*)&csh[(rowA + 8) * 68 + s * 32 + tg * 4];
            unsigned a2 = *(const unsigned*)&csh[rowA * 68 + s * 32 + 16 + tg * 4];
            unsigned a3 = *(const unsigned*)&csh[(rowA + 8) * 68 + s * 32 + 16 + tg * 4];
#pragma unroll
            for (int nt = 0; nt < 8; nt++) {
                unsigned b0 = expand4((unsigned)(vt[nt] >> (s * 32 + tg * 4)) & 0xFu);
                unsigned b1 = expand4((unsigned)(vt[nt] >> (s * 32 + 16 + tg * 4)) & 0xFu);
                mma_s8(acc[nt], a0, a1, a2, a3, b0, b1);
            }
        }
    }

    __syncthreads();
#pragma unroll
    for (int nt = 0; nt < 8; ++nt) {
        int d0 = nt * 8 + tg * 2;
        csh[d0 * 68 + rowA]           = ((float)acc[nt][0] * scale >= 1.0f) ? 1 : 0;
        csh[(d0 + 1) * 68 + rowA]     = ((float)acc[nt][1] * scale >= 1.0f) ? 1 : 0;
        csh[d0 * 68 + rowA + 8]       = ((float)acc[nt][2] * scale >= 1.0f) ? 1 : 0;
        csh[(d0 + 1) * 68 + rowA + 8] = ((float)acc[nt][3] * scale >= 1.0f) ? 1 : 0;
    }
    __syncthreads();
    {
        int d = tid >> 1, hf = tid & 1;
        size_t b = (size_t)(bh >> 3), h = (size_t)(bh & 7);
        size_t off = (b << 20) + (h << 17) + ((size_t)d << 11)
                   + (size_t)tq * 64 + (size_t)hf * 32;
#pragma unroll
        for (int q4 = 0; q4 < 32; q4 += 4) {
            unsigned v = *(const unsigned*)&csh[d * 68 + hf * 32 + q4];
            *(unsigned*)(g_xs + off + q4) = v;
        }
    }
}

// =====================================================================
// Output projection (unchanged from 275us run).
// =====================================================================
__global__ __launch_bounds__(256, 2) void out_mma_kernel(
    const float* __restrict__ bias, float* __restrict__ out)
{
    __shared__ unsigned short Asp[128 * SROW];
    __shared__ unsigned short Wsp[3 * 64 * SROW];

    const int tid  = threadIdx.x;
    const int lane = tid & 31;
    const int g    = lane >> 2, tg = lane & 3;
    const int wrp  = tid >> 5;
    const int mw   = wrp >> 1, nw = wrp & 1;

    int s2 = blockIdx.x;
    int n0 = (s2 & 7) * 64, m0 = (s2 >> 3) * 128;

    const unsigned short* gW = g_wsp + (size_t)3 * 3 * 512 * 512;
    const unsigned abase = (unsigned)__cvta_generic_to_shared(Asp);
    const unsigned wbase = (unsigned)__cvta_generic_to_shared(Wsp);

    float C[2][4][4];
#pragma unroll
    for (int mt = 0; mt < 2; mt++)
#pragma unroll
        for (int nt = 0; nt < 4; nt++)
#pragma unroll
            for (int r = 0; r < 4; r++) C[mt][nt][r] = 0.f;

    const int arow_l = lane & 15;
    const int ak8 = (lane >> 4) * 8;
    const int brow = (lane & 7) + ((lane & 16) >> 1);
    const int bk8 = (lane & 8);
    const int xrow = tid >> 1, xhalf = tid & 1;
    const int wrow = (tid >> 2) & 63, wpart = tid & 3;

    uint4 pa, pwa, pwb, pwc;
    pa  = *(const uint4*)(g_xs + (size_t)(m0 + xrow) * DD + 0 + xhalf * 16);
    pwa = *(const uint4*)(gW + ((size_t)0 * 512 + n0 + wrow) * 512 + 0 + wpart * 8);
    pwb = *(const uint4*)(gW + ((size_t)1 * 512 + n0 + wrow) * 512 + 0 + wpart * 8);
    pwc = *(const uint4*)(gW + ((size_t)2 * 512 + n0 + wrow) * 512 + 0 + wpart * 8);

    for (int ch = 0; ch < 16; ++ch) {
        const int k0 = ch << 5;
        __syncthreads();
        {
            unsigned w0 = pa.x, w1 = pa.y, w2 = pa.z, w3 = pa.w;
            uint4 o0, o1;
            o0.x = ((w0 & 1u) ? 0x3F80u : 0u) | ((w0 & 0x100u) ? 0x3F800000u : 0u);
            o0.y = (((w0 >> 16) & 1u) ? 0x3F80u : 0u) | ((w0 & 0x1000000u) ? 0x3F800000u : 0u);
            o0.z = ((w1 & 1u) ? 0x3F80u : 0u) | ((w1 & 0x100u) ? 0x3F800000u : 0u);
            o0.w = (((w1 >> 16) & 1u) ? 0x3F80u : 0u) | ((w1 & 0x1000000u) ? 0x3F800000u : 0u);
            o1.x = ((w2 & 1u) ? 0x3F80u : 0u) | ((w2 & 0x100u) ? 0x3F800000u : 0u);
            o1.y = (((w2 >> 16) & 1u) ? 0x3F80u : 0u) | ((w2 & 0x1000000u) ? 0x3F800000u : 0u);
            o1.z = ((w3 & 1u) ? 0x3F80u : 0u) | ((w3 & 0x100u) ? 0x3F800000u : 0u);
            o1.w = (((w3 >> 16) & 1u) ? 0x3F80u : 0u) | ((w3 & 0x1000000u) ? 0x3F800000u : 0u);
            unsigned short* dstp = &Asp[xrow * SROW + xhalf * 16];
            *(uint4*)dstp       = o0;
            *(uint4*)(dstp + 8) = o1;
        }
        *(uint4*)&Wsp[(0 * 64 + wrow) * SROW + wpart * 8] = pwa;
        *(uint4*)&Wsp[(1 * 64 + wrow) * SROW + wpart * 8] = pwb;
        *(uint4*)&Wsp[(2 * 64 + wrow) * SROW + wpart * 8] = pwc;
        __syncthreads();
        if (ch + 1 < 16) {
            const int kn = k0 + 32;
            pa  = *(const uint4*)(g_xs + (size_t)(m0 + xrow) * DD + kn + xhalf * 16);
            pwa = *(const uint4*)(gW + ((size_t)0 * 512 + n0 + wrow) * 512 + kn + wpart * 8);
            pwb = *(const uint4*)(gW + ((size_t)1 * 512 + n0 + wrow) * 512 + kn + wpart * 8);
            pwc = *(const uint4*)(gW + ((size_t)2 * 512 + n0 + wrow) * 512 + kn + wpart * 8);
        }
#pragma unroll
        for (int s = 0; s < 2; ++s) {
            unsigned af[2][4];
#pragma unroll
            for (int mt = 0; mt < 2; mt++) {
                unsigned a = abase +
                    (((mw * 32 + mt * 16 + arow_l) * SROW) + s * 16 + ak8) * 2;
                ldsm4(af[mt][0], af[mt][1], af[mt][2], af[mt][3], a);
            }
#pragma unroll
            for (int j = 0; j < 3; j++) {
                unsigned bfr[2][4];
#pragma unroll
                for (int np = 0; np < 2; np++) {
                    unsigned a = wbase +
                        (((j * 64 + nw * 32 + np * 16 + brow) * SROW) +
                         s * 16 + bk8) * 2;
                    ldsm4(bfr[np][0], bfr[np][1], bfr[np][2], bfr[np][3], a);
                }
#pragma unroll
                for (int mt = 0; mt < 2; mt++)
#pragma unroll
                    for (int np = 0; np < 2; np++) {
                        mma_bf16(C[mt][np * 2], af[mt][0], af[mt][1], af[mt][2],
                                 af[mt][3], bfr[np][0], bfr[np][1]);
                        mma_bf16(C[mt][np * 2 + 1], af[mt][0], af[mt][1], af[mt][2],
                                 af[mt][3], bfr[np][2], bfr[np][3]);
                    }
            }
        }
    }

#pragma unroll
    for (int mt = 0; mt < 2; mt++)
#pragma unroll
        for (int nt = 0; nt < 4; nt++) {
            int row = m0 + mw * 32 + mt * 16 + g;
            int col = n0 + nw * 32 + nt * 8 + tg * 2;
            float2 bb = *(const float2*)&bias[col];
            float2 r0, r1;
            r0.x = (C[mt][nt][0] + bb.x >= 1.0f) ? 1.0f : 0.0f;
            r0.y = (C[mt][nt][1] + bb.y >= 1.0f) ? 1.0f : 0.0f;
            r1.x = (C[mt][nt][2] + bb.x >= 1.0f) ? 1.0f : 0.0f;
            r1.y = (C[mt][nt][3] + bb.y >= 1.0f) ? 1.0f : 0.0f;
            *(float2*)&out[(size_t)row * DD + col] = r0;
            *(float2*)&out[(size_t)(row + 8) * DD + col] = r1;
        }
}

// ---------------- launch ----------------
extern "C" void kernel_launch(void* const* d_in, const int* in_sizes, int n_in,
                              void* d_out, int out_size)
{
    const float* query = (const float*)d_in[0];
    const float* key   = (const float*)d_in[1];
    const float* value = (const float*)d_in[2];
    const float* scale = (const float*)d_in[3];
    const float* Wq = (const float*)d_in[4];  const float* bq = (const float*)d_in[5];
    const float* Wk = (const float*)d_in[6];  const float* bk = (const float*)d_in[7];
    const float* Wv = (const float*)d_in[8];  const float* bv = (const float*)d_in[9];
    const float* Wo = (const float*)d_in[10]; const float* bo = (const float*)d_in[11];
    float* out = (float*)d_out;

    const int DIN = in_sizes[0] / MROWS;   // 100

    prep_w_kernel<<<dim3(8, 8, 4), 256>>>(Wq, Wk, Wv, Wo);
    qkv_mma_kernel<<<1536, 256>>>(query, key, value, bq, bk, bv, DIN);
    trans_kernel<<<2048, 64>>>();
    kvprod_kernel<<<BHN * NTW, 128>>>();
    attn_kernel<<<BHN * NTW, 128>>>(scale);
    out_mma_kernel<<<512, 256>>>(bo, out);
}

// round 13
// speedup vs baseline: 1.9243x; 1.0060x over previous
#include <cuda_runtime.h>
#include <cstdint>

#define BB 4
#define TT 2048
#define DD 512
#define HH 8
#define DK 64
#define BHN (BB*HH)          // 32
#define NTW (TT/64)          // 32 k-tiles
#define MROWS (BB*TT)        // 8192
#define SROW 40              // smem row stride (bf16 units) = 80B
#define QKV_BUF 46080        // one qkv stage: A planes 30720 + W 15360
#define OUT_BUF 25600        // one out stage: A 10240 + W 15360

// ---------------- scratch (proven ~17 MB footprint) ----------------
__device__ unsigned long long g_qb[BHN*TT];
__device__ unsigned long long g_kb[BHN*TT];
__device__ unsigned long long g_vb[BHN*TT];
__device__ unsigned long long g_vT[BHN*DK*NTW];      // [bh][d][w]
__device__ unsigned long long g_kT[BHN*DK*NTW];      // [bh][j][w]
__device__ unsigned char      g_xs[BB*TT*DD];
__device__ unsigned short     g_wsp[4*3*512*512];    // pre-split W (6 MB)
__device__ unsigned char      g_kv[BHN*NTW*64*64];   // KV tiles s8 (4 MB)

// ---------------- helpers ----------------
__device__ __forceinline__ unsigned expand4(unsigned x) {
    return (x * 0x00204081u) & 0x01010101u;
}
__device__ __forceinline__ void mma_s8(int* c, unsigned a0, unsigned a1, unsigned a2,
                                       unsigned a3, unsigned b0, unsigned b1) {
    asm volatile(
        "mma.sync.aligned.m16n8k32.row.col.s32.s8.s8.s32 "
        "{%0,%1,%2,%3}, {%4,%5,%6,%7}, {%8,%9}, {%0,%1,%2,%3};"
        : "+r"(c[0]), "+r"(c[1]), "+r"(c[2]), "+r"(c[3])
        : "r"(a0), "r"(a1), "r"(a2), "r"(a3), "r"(b0), "r"(b1));
}
__device__ __forceinline__ void mma_bf16(float* c, unsigned a0, unsigned a1,
                                         unsigned a2, unsigned a3,
                                         unsigned b0, unsigned b1) {
    asm volatile(
        "mma.sync.aligned.m16n8k16.row.col.f32.bf16.bf16.f32 "
        "{%0,%1,%2,%3}, {%4,%5,%6,%7}, {%8,%9}, {%0,%1,%2,%3};"
        : "+f"(c[0]), "+f"(c[1]), "+f"(c[2]), "+f"(c[3])
        : "r"(a0), "r"(a1), "r"(a2), "r"(a3), "r"(b0), "r"(b1));
}
__device__ __forceinline__ void split3(float a, unsigned short& s0,
                                       unsigned short& s1, unsigned short& s2) {
    unsigned u0 = __float_as_uint(a);
    s0 = (unsigned short)(u0 >> 16);
    float r1 = a - __uint_as_float(u0 & 0xFFFF0000u);
    unsigned u1 = __float_as_uint(r1);
    s1 = (unsigned short)(u1 >> 16);
    float r2 = r1 - __uint_as_float(u1 & 0xFFFF0000u);
    s2 = (unsigned short)(__float_as_uint(r2) >> 16);
}
__device__ __forceinline__ unsigned prmt7632(unsigned a, unsigned b) {
    unsigned r;
    asm("prmt.b32 %0, %1, %2, 0x7632;" : "=r"(r) : "r"(a), "r"(b));
    return r;
}
__device__ __forceinline__ float trunchi(float a) {
    return __uint_as_float(__float_as_uint(a) & 0xFFFF0000u);
}
__device__ __forceinline__ void ldsm4(unsigned& r0, unsigned& r1, unsigned& r2,
                                      unsigned& r3, unsigned addr) {
    asm volatile("ldmatrix.sync.aligned.m8n8.x4.shared.b16 {%0,%1,%2,%3}, [%4];"
                 : "=r"(r0), "=r"(r1), "=r"(r2), "=r"(r3) : "r"(addr));
}
__device__ __forceinline__ void cpa16(unsigned dst, const void* src) {
    asm volatile("cp.async.cg.shared.global [%0], [%1], 16;" :: "r"(dst), "l"(src));
}
#define CP_COMMIT() asm volatile("cp.async.commit_group;")
#define CP_WAIT(n)  asm volatile("cp.async.wait_group %0;" :: "n"(n) : "memory")

// =====================================================================
// prep: split W (transposed to [n][k]) into g_wsp.
// =====================================================================
__global__ void prep_w_kernel(const float* __restrict__ Wq, const float* __restrict__ Wk,
                              const float* __restrict__ Wv, const float* __restrict__ Wo)
{
    __shared__ float sh[64][68];
    int w = blockIdx.z;
    const float* W = (w == 0) ? Wq : (w == 1) ? Wk : (w == 2) ? Wv : Wo;
    int k0 = blockIdx.x * 64, n0 = blockIdx.y * 64;
    int t = threadIdx.x;
#pragma unroll
    for (int r = 0; r < 4; r++) {
        int row = (t >> 4) * 4 + r;
        int col = (t & 15) * 4;
        float4 v = *(const float4*)&W[(size_t)(k0 + row) * DD + n0 + col];
        sh[row][col] = v.x; sh[row][col+1] = v.y; sh[row][col+2] = v.z; sh[row][col+3] = v.w;
    }
    __syncthreads();
#pragma unroll
    for (int r = 0; r < 4; r++) {
        int n = (t >> 4) * 4 + r;
        int k4 = (t & 15) * 4;
        unsigned short a0, a1, a2, b0, b1, b2, c0, c1, c2, d0, d1, d2;
        split3(sh[k4 + 0][n], a0, a1, a2);
        split3(sh[k4 + 1][n], b0, b1, b2);
        split3(sh[k4 + 2][n], c0, c1, c2);
        split3(sh[k4 + 3][n], d0, d1, d2);
        size_t base = ((size_t)(w * 3) * 512 + (n0 + n)) * 512 + k0 + k4;
        const size_t P = (size_t)512 * 512;
        *(uint2*)&g_wsp[base] =
            make_uint2((unsigned)a0 | ((unsigned)b0 << 16),
                       (unsigned)c0 | ((unsigned)d0 << 16));
        *(uint2*)&g_wsp[base + P] =
            make_uint2((unsigned)a1 | ((unsigned)b1 << 16),
                       (unsigned)c1 | ((unsigned)d1 << 16));
        *(uint2*)&g_wsp[base + 2 * P] =
            make_uint2((unsigned)a2 | ((unsigned)b2 << 16),
                       (unsigned)c2 | ((unsigned)d2 << 16));
    }
}

// =====================================================================
// qkv GEMM: 2-stage smem double buffer, 1 barrier/chunk.
// =====================================================================
#define QKV_LOAD_A(K0)                                                        \
    do {                                                                      \
        if (which != 2) {                                                     \
            const float4* ap = (const float4*)(A + (size_t)(m0 + arow) * DD + (K0) + akh); \
            float4 x0 = ap[0], x1 = ap[1], x2 = ap[2], x3 = ap[3];            \
            pv0=x0.x; pv1=x0.y; pv2=x0.z; pv3=x0.w;                           \
            pv4=x1.x; pv5=x1.y; pv6=x1.z; pv7=x1.w;                           \
            pv8=x2.x; pv9=x2.y; pva=x2.z; pvb=x2.w;                           \
            pvc=x3.x; pvd=x3.y; pve=x3.z; pvf=x3.w;                           \
        } else {                                                              \
            const float* ar = A + (size_t)(m0 + arow) * KA;                   \
            int kb = (K0) + akh;                                              \
            pv0 = (kb+0 < KA) ? ar[kb+0] : 0.f;  pv1 = (kb+1 < KA) ? ar[kb+1] : 0.f; \
            pv2 = (kb+2 < KA) ? ar[kb+2] : 0.f;  pv3 = (kb+3 < KA) ? ar[kb+3] : 0.f; \
            pv4 = (kb+4 < KA) ? ar[kb+4] : 0.f;  pv5 = (kb+5 < KA) ? ar[kb+5] : 0.f; \
            pv6 = (kb+6 < KA) ? ar[kb+6] : 0.f;  pv7 = (kb+7 < KA) ? ar[kb+7] : 0.f; \
            pv8 = (kb+8 < KA) ? ar[kb+8] : 0.f;  pv9 = (kb+9 < KA) ? ar[kb+9] : 0.f; \
            pva = (kb+10 < KA) ? ar[kb+10] : 0.f; pvb = (kb+11 < KA) ? ar[kb+11] : 0.f; \
            pvc = (kb+12 < KA) ? ar[kb+12] : 0.f; pvd = (kb+13 < KA) ? ar[kb+13] : 0.f; \
            pve = (kb+14 < KA) ? ar[kb+14] : 0.f; pvf = (kb+15 < KA) ? ar[kb+15] : 0.f; \
        }                                                                     \
    } while (0)

#define QKV_LOAD_W(K0)                                                        \
    do {                                                                      \
        pwa = *(const uint4*)(gW + ((size_t)0 * 512 + n0 + wrow) * 512 + (K0) + wpart * 8); \
        pwb = *(const uint4*)(gW + ((size_t)1 * 512 + n0 + wrow) * 512 + (K0) + wpart * 8); \
        pwc = *(const uint4*)(gW + ((size_t)2 * 512 + n0 + wrow) * 512 + (K0) + wpart * 8); \
    } while (0)

#define SPLITPAIR(I, VA, VB)                                                  \
    do {                                                                      \
        float ra_ = (VA), rb_ = (VB);                                         \
        p0_[I] = prmt7632(__float_as_uint(ra_), __float_as_uint(rb_));        \
        ra_ -= trunchi(ra_); rb_ -= trunchi(rb_);                             \
        p1_[I] = prmt7632(__float_as_uint(ra_), __float_as_uint(rb_));        \
        ra_ -= trunchi(ra_); rb_ -= trunchi(rb_);                             \
        p2_[I] = prmt7632(__float_as_uint(ra_), __float_as_uint(rb_));        \
    } while (0)

// split regs + store A and W into the stage at byte offset BUFOFF
#define QKV_STAGE_STS(BUFOFF)                                                 \
    do {                                                                      \
        char* bufc = smemraw + (BUFOFF);                                      \
        {                                                                     \
            unsigned p0_[8], p1_[8], p2_[8];                                  \
            SPLITPAIR(0, pv0, pv1); SPLITPAIR(1, pv2, pv3);                   \
            SPLITPAIR(2, pv4, pv5); SPLITPAIR(3, pv6, pv7);                   \
            SPLITPAIR(4, pv8, pv9); SPLITPAIR(5, pva, pvb);                   \
            SPLITPAIR(6, pvc, pvd); SPLITPAIR(7, pve, pvf);                   \
            unsigned short* base0 = (unsigned short*)bufc + arow * SROW + akh; \
            const int PL = 128 * SROW;                                        \
            *(uint4*)(base0)              = make_uint4(p0_[0], p0_[1], p0_[2], p0_[3]); \
            *(uint4*)(base0 + 8)          = make_uint4(p0_[4], p0_[5], p0_[6], p0_[7]); \
            *(uint4*)(base0 + PL)         = make_uint4(p1_[0], p1_[1], p1_[2], p1_[3]); \
            *(uint4*)(base0 + PL + 8)     = make_uint4(p1_[4], p1_[5], p1_[6], p1_[7]); \
            *(uint4*)(base0 + 2 * PL)     = make_uint4(p2_[0], p2_[1], p2_[2], p2_[3]); \
            *(uint4*)(base0 + 2 * PL + 8) = make_uint4(p2_[4], p2_[5], p2_[6], p2_[7]); \
        }                                                                     \
        {                                                                     \
            char* wd = bufc + 30720;                                          \
            *(uint4*)(wd + (((0 * 64 + wrow) * SROW) + wpart * 8) * 2) = pwa; \
            *(uint4*)(wd + (((1 * 64 + wrow) * SROW) + wpart * 8) * 2) = pwb; \
            *(uint4*)(wd + (((2 * 64 + wrow) * SROW) + wpart * 8) * 2) = pwc; \
        }                                                                     \
    } while (0)

__global__ __launch_bounds__(256, 2) void qkv_mma_kernel(
    const float* __restrict__ Aq, const float* __restrict__ Ak,
    const float* __restrict__ Av,
    const float* __restrict__ bq, const float* __restrict__ bk,
    const float* __restrict__ bv, int DIN)
{
    extern __shared__ char smemraw[];          // 2 x QKV_BUF

    const int tid  = threadIdx.x;
    const int lane = tid & 31;
    const int g    = lane >> 2, tg = lane & 3;
    const int wrp  = tid >> 5;
    const int mw   = wrp >> 1, nw = wrp & 1;

    int idx = blockIdx.x;
    int which = idx >> 9;                      // 0=k,1=v,2=q
    int s2 = idx & 511;
    int n0 = (s2 & 7) * 64, m0 = (s2 >> 3) * 128;

    const float* A    = (which == 0) ? Ak : (which == 1) ? Av : Aq;
    const float* bias = (which == 0) ? bk : (which == 1) ? bv : bq;
    const int KA = DIN;
    const int KS = (which == 2) ? 128 : DD;
    const int wsel = (which == 0) ? 1 : (which == 1) ? 2 : 0;
    const unsigned short* gW = g_wsp + (size_t)wsel * 3 * 512 * 512;

    const unsigned sbase0 = (unsigned)__cvta_generic_to_shared(smemraw);

    float C[2][4][4];
#pragma unroll
    for (int mt = 0; mt < 2; mt++)
#pragma unroll
        for (int nt = 0; nt < 4; nt++)
#pragma unroll
            for (int r = 0; r < 4; r++) C[mt][nt][r] = 0.f;

    const int arow = tid >> 1, akh = (tid & 1) * 16;
    const int arow_l = lane & 15;
    const int ak8 = (lane >> 4) * 8;
    const int brow = (lane & 7) + ((lane & 16) >> 1);
    const int bk8 = (lane & 8);
    const int wrow = (tid >> 2) & 63, wpart = tid & 3;

    float pv0,pv1,pv2,pv3,pv4,pv5,pv6,pv7,pv8,pv9,pva,pvb,pvc,pvd,pve,pvf;
    uint4 pwa, pwb, pwc;

    const int nch = KS >> 5;

    // ---- prologue: fill stage 0, prefetch chunk 1 regs ----
    QKV_LOAD_A(0);
    QKV_LOAD_W(0);
    QKV_STAGE_STS(0);
    if (nch > 1) { QKV_LOAD_A(32); QKV_LOAD_W(32); }
    __syncthreads();

    for (int ch = 0; ch < nch; ++ch) {
        // stage (ch+1): split+STS the prefetched regs into the other buffer
        if (ch + 1 < nch) {
            QKV_STAGE_STS(((ch + 1) & 1) * QKV_BUF);
        }
        // prefetch regs for chunk ch+2 (overlaps with MMA below)
        if (ch + 2 < nch) {
            QKV_LOAD_A((ch + 2) << 5);
            QKV_LOAD_W((ch + 2) << 5);
        }
        // ---- MMA on stage ch ----
        const unsigned abuf = sbase0 + (unsigned)((ch & 1) * QKV_BUF);
        const unsigned wbuf = abuf + 30720;
#pragma unroll
        for (int s = 0; s < 2; ++s) {
            unsigned af[3][2][4];
#pragma unroll
            for (int sp = 0; sp < 3; sp++)
#pragma unroll
                for (int mt = 0; mt < 2; mt++) {
                    unsigned a = abuf +
                        (((sp * 128 + mw * 32 + mt * 16 + arow_l) * SROW) +
                         s * 16 + ak8) * 2;
                    ldsm4(af[sp][mt][0], af[sp][mt][1], af[sp][mt][2], af[sp][mt][3], a);
                }
#pragma unroll
            for (int j = 0; j < 3; j++) {
                unsigned bfr[2][4];
#pragma unroll
                for (int np = 0; np < 2; np++) {
                    unsigned a = wbuf +
                        (((j * 64 + nw * 32 + np * 16 + brow) * SROW) +
                         s * 16 + bk8) * 2;
                    ldsm4(bfr[np][0], bfr[np][1], bfr[np][2], bfr[np][3], a);
                }
#pragma unroll
                for (int i = 0; i < 3; i++) {
                    if (i + j > 2) break;
#pragma unroll
                    for (int mt = 0; mt < 2; mt++)
#pragma unroll
                        for (int np = 0; np < 2; np++) {
                            mma_bf16(C[mt][np * 2], af[i][mt][0], af[i][mt][1],
                                     af[i][mt][2], af[i][mt][3],
                                     bfr[np][0], bfr[np][1]);
                            mma_bf16(C[mt][np * 2 + 1], af[i][mt][0], af[i][mt][1],
                                     af[i][mt][2], af[i][mt][3],
                                     bfr[np][2], bfr[np][3]);
                        }
                }
            }
        }
        __syncthreads();
    }

    // ---- epilogue: bias + spike -> bytes (overlay smem) -> bitpack ----
    unsigned char* sbyte = (unsigned char*)smemraw;
#pragma unroll
    for (int mt = 0; mt < 2; mt++)
#pragma unroll
        for (int nt = 0; nt < 4; nt++) {
            int row = mw * 32 + mt * 16 + g;
            int col = nw * 32 + nt * 8 + tg * 2;
            float2 bb = *(const float2*)&bias[n0 + col];
            sbyte[row * 64 + col]           = (C[mt][nt][0] + bb.x >= 1.0f) ? 1 : 0;
            sbyte[row * 64 + col + 1]       = (C[mt][nt][1] + bb.y >= 1.0f) ? 1 : 0;
            sbyte[(row + 8) * 64 + col]     = (C[mt][nt][2] + bb.x >= 1.0f) ? 1 : 0;
            sbyte[(row + 8) * 64 + col + 1] = (C[mt][nt][3] + bb.y >= 1.0f) ? 1 : 0;
        }
    __syncthreads();
    if (tid < 128) {
        unsigned long long bits = 0ull;
#pragma unroll
        for (int q = 0; q < 8; q++) {
            unsigned long long u = *(const unsigned long long*)&sbyte[tid * 64 + 8 * q];
#pragma unroll
            for (int j = 0; j < 8; j++)
                bits |= ((u >> (8 * j)) & 1ull) << (8 * q + j);
        }
        int m = m0 + tid;
        int b = m >> 11, t = m & 2047;
        int head = n0 >> 6;
        unsigned long long* dst = (which == 2) ? g_qb : (which == 0) ? g_kb : g_vb;
        dst[(size_t)((b << 3) + head) * TT + t] = bits;
    }
}

// ---------------- bit transpose for k and v ----------------
__global__ void trans_kernel()
{
    int bx = blockIdx.x;
    int which = bx >> 10;
    int idx = bx & 1023;
    int bh = idx >> 5, w = idx & 31;
    int tid = threadIdx.x;
    int lane = tid & 31, warp = tid >> 5;
    __shared__ unsigned sh[64][2];
    const unsigned long long* src = (which == 0) ? g_vb : g_kb;
    unsigned long long* dst = (which == 0) ? g_vT : g_kT;
    unsigned long long r = src[(size_t)bh * TT + w * 64 + tid];
#pragma unroll 8
    for (int d = 0; d < 64; d++) {
        unsigned b = __ballot_sync(0xffffffffu, (unsigned)((r >> d) & 1ull));
        if (lane == 0) sh[d][warp] = b;
    }
    __syncthreads();
    dst[(size_t)(bh * 64 + tid) * 32 + w] =
        (unsigned long long)sh[tid][0] | ((unsigned long long)sh[tid][1] << 32);
}

// =====================================================================
// KV precompute (unchanged).
// =====================================================================
__global__ __launch_bounds__(128) void kvprod_kernel()
{
    const int tid = threadIdx.x;
    const int lane = tid & 31;
    const int g = lane >> 2, tg = lane & 3;
    const int wr16 = (tid >> 5) * 16;

    int bh = blockIdx.x >> 5, w = blockIdx.x & 31;

    unsigned long long vd0 = g_vT[((size_t)bh * 64 + wr16 + g) * 32 + w];
    unsigned long long vd1 = g_vT[((size_t)bh * 64 + wr16 + 8 + g) * 32 + w];
    unsigned long long kt[8];
#pragma unroll
    for (int nt = 0; nt < 8; nt++)
        kt[nt] = g_kT[((size_t)bh * 64 + nt * 8 + g) * 32 + w];

    int acc[8][4];
#pragma unroll
    for (int nt = 0; nt < 8; nt++)
#pragma unroll
        for (int r = 0; r < 4; r++) acc[nt][r] = 0;

#pragma unroll
    for (int s = 0; s < 2; s++) {
        unsigned l0 = (unsigned)(vd0 >> (32 * s));
        unsigned l1 = (unsigned)(vd1 >> (32 * s));
        unsigned a0 = expand4((l0 >> (4 * tg)) & 0xFu);
        unsigned a1 = expand4((l1 >> (4 * tg)) & 0xFu);
        unsigned a2 = expand4((l0 >> (16 + 4 * tg)) & 0xFu);
        unsigned a3 = expand4((l1 >> (16 + 4 * tg)) & 0xFu);
#pragma unroll
        for (int nt = 0; nt < 8; nt++) {
            unsigned kl = (unsigned)(kt[nt] >> (32 * s));
            unsigned b0 = expand4((kl >> (4 * tg)) & 0xFu);
            unsigned b1 = expand4((kl >> (16 + 4 * tg)) & 0xFu);
            mma_s8(acc[nt], a0, a1, a2, a3, b0, b1);
        }
    }

    unsigned char* dst = g_kv + ((size_t)(bh * 32 + w) * 64) * 64;
#pragma unroll
    for (int nt = 0; nt < 8; nt++) {
        int j0 = nt * 8 + 2 * tg;
        *(unsigned short*)(dst + (wr16 + g) * 64 + j0) =
            (unsigned short)((acc[nt][0] & 0xFF) | ((acc[nt][1] & 0xFF) << 8));
        *(unsigned short*)(dst + (wr16 + 8 + g) * 64 + j0) =
            (unsigned short)((acc[nt][2] & 0xFF) | ((acc[nt][3] & 0xFF) << 8));
    }
}

// =====================================================================
// Attention (unchanged from 275us run).
// =====================================================================
__global__ __launch_bounds__(128) void attn_kernel(const float* __restrict__ scale_p)
{
    __shared__ __align__(16) unsigned char KVsh[2][64 * 80];
    __shared__ unsigned char csh[64 * 68];
    __shared__ unsigned long long ksh[64];

    const int tid = threadIdx.x;
    const int lane = tid & 31;
    const int g = lane >> 2, tg = lane & 3;
    const int wr16 = (tid >> 5) * 16;
    const int rowA = wr16 + g;

    int bx = blockIdx.x;
    int bh = bx & 31;
    int tq = 31 - (bx >> 5);

    const float scale = *scale_p;
    const size_t base = (size_t)bh * TT;
    const unsigned char* KVg = g_kv + (size_t)bh * 32 * 64 * 64;

    unsigned long long q0 = g_qb[base + (size_t)tq * 64 + rowA];
    unsigned long long q1 = g_qb[base + (size_t)tq * 64 + rowA + 8];
    unsigned qa[2][4];
#pragma unroll
    for (int s = 0; s < 2; s++) {
        unsigned l0 = (unsigned)(q0 >> (32 * s));
        unsigned l1 = (unsigned)(q1 >> (32 * s));
        qa[s][0] = expand4((l0 >> (4 * tg)) & 0xFu);
        qa[s][1] = expand4((l1 >> (4 * tg)) & 0xFu);
        qa[s][2] = expand4((l0 >> (16 + 4 * tg)) & 0xFu);
        qa[s][3] = expand4((l1 >> (16 + 4 * tg)) & 0xFu);
    }

    int acc[8][4];
#pragma unroll
    for (int nt = 0; nt < 8; nt++)
#pragma unroll
        for (int r = 0; r < 4; r++) acc[nt][r] = 0;

    const int kvrow0 = tid >> 2, kvp0 = tid & 3;
    const int kvrow1 = (tid + 128) >> 2, kvp1 = tid & 3;
    const unsigned kvb0 = (unsigned)__cvta_generic_to_shared(&KVsh[0][0]);
    const unsigned kvb1 = (unsigned)__cvta_generic_to_shared(&KVsh[1][0]);

    if (tq > 0) {
        cpa16(kvb0 + kvrow0 * 80 + kvp0 * 16, KVg + 0 * 4096 + kvrow0 * 64 + kvp0 * 16);
        cpa16(kvb0 + kvrow1 * 80 + kvp1 * 16, KVg + 0 * 4096 + kvrow1 * 64 + kvp1 * 16);
        CP_COMMIT();
    }
    for (int w = 0; w < tq; ++w) {
        __syncthreads();
        if (w + 1 < tq) {
            unsigned kb = ((w + 1) & 1) ? kvb1 : kvb0;
            const unsigned char* src = KVg + (size_t)(w + 1) * 4096;
            cpa16(kb + kvrow0 * 80 + kvp0 * 16, src + kvrow0 * 64 + kvp0 * 16);
            cpa16(kb + kvrow1 * 80 + kvp1 * 16, src + kvrow1 * 64 + kvp1 * 16);
            CP_COMMIT();
            CP_WAIT(1);
        } else {
            CP_WAIT(0);
        }
        __syncthreads();
        const unsigned char* kb = KVsh[w & 1];
#pragma unroll
        for (int s = 0; s < 2; s++)
#pragma unroll
            for (int nt = 0; nt < 8; nt++) {
                unsigned b0 = *(const unsigned*)(kb + (nt * 8 + g) * 80 + s * 32 + tg * 4);
                unsigned b1 = *(const unsigned*)(kb + (nt * 8 + g) * 80 + s * 32 + 16 + tg * 4);
                mma_s8(acc[nt], qa[s][0], qa[s][1], qa[s][2], qa[s][3], b0, b1);
            }
    }

    if (tid < 64) ksh[tid] = g_kb[base + (size_t)tq * 64 + tid];
    unsigned long long vt[8];
#pragma unroll
    for (int nt = 0; nt < 8; nt++)
        vt[nt] = g_vT[((size_t)bh * 64 + nt * 8 + g) * 32 + tq];
    __syncthreads();

    {
        unsigned long long kk[8];
#pragma unroll
        for (int nt = 0; nt < 8; nt++) kk[nt] = ksh[nt * 8 + g];
        int qcc[8][4];
#pragma unroll
        for (int nt = 0; nt < 8; nt++)
#pragma unroll
            for (int r = 0; r < 4; r++) qcc[nt][r] = 0;
#pragma unroll
        for (int s = 0; s < 2; s++)
#pragma unroll
            for (int nt = 0; nt < 8; nt++) {
                unsigned kl = (unsigned)(kk[nt] >> (32 * s));
                unsigned b0 = expand4((kl >> (4 * tg)) & 0xFu);
                unsigned b1 = expand4((kl >> (16 + 4 * tg)) & 0xFu);
                mma_s8(qcc[nt], qa[s][0], qa[s][1], qa[s][2], qa[s][3], b0, b1);
            }
        int t0 = rowA, t1 = rowA + 8;
#pragma unroll
        for (int nt = 0; nt < 8; nt++) {
            int kc = nt * 8 + 2 * tg;
            unsigned v00 = (kc <= t0) ? (qcc[nt][0] & 0xFF) : 0u;
            unsigned v01 = (kc + 1 <= t0) ? (qcc[nt][1] & 0xFF) : 0u;
            unsigned v10 = (kc <= t1) ? (qcc[nt][2] & 0xFF) : 0u;
            unsigned v11 = (kc + 1 <= t1) ? (qcc[nt][3] & 0xFF) : 0u;
            *(unsigned short*)&csh[t0 * 68 + kc] = (unsigned short)(v00 | (v01 << 8));
            *(unsigned short*)&csh[t1 * 68 + kc] = (unsigned short)(v10 | (v11 << 8));
        }
        __syncwarp();
#pragma unroll
        for (int s = 0; s < 2; s++) {
            unsigned a0 = *(const unsigned*)&csh[rowA * 68 + s * 32 + tg * 4];
            unsigned a1 = *(const unsigned*)&csh[(rowA + 8) * 68 + s * 32 + tg * 4];
            unsigned a2 = *(const unsigned*)&csh[rowA * 68 + s * 32 + 16 + tg * 4];
            unsigned a3 = *(const unsigned*)&csh[(rowA + 8) * 68 + s * 32 + 16 + tg * 4];
#pragma unroll
            for (int nt = 0; nt < 8; nt++) {
                unsigned b0 = expand4((unsigned)(vt[nt] >> (s * 32 + tg * 4)) & 0xFu);
                unsigned b1 = expand4((unsigned)(vt[nt] >> (s * 32 + 16 + tg * 4)) & 0xFu);
                mma_s8(acc[nt], a0, a1, a2, a3, b0, b1);
            }
        }
    }

    __syncthreads();
#pragma unroll
    for (int nt = 0; nt < 8; ++nt) {
        int d0 = nt * 8 + tg * 2;
        csh[d0 * 68 + rowA]           = ((float)acc[nt][0] * scale >= 1.0f) ? 1 : 0;
        csh[(d0 + 1) * 68 + rowA]     = ((float)acc[nt][1] * scale >= 1.0f) ? 1 : 0;
        csh[d0 * 68 + rowA + 8]       = ((float)acc[nt][2] * scale >= 1.0f) ? 1 : 0;
        csh[(d0 + 1) * 68 + rowA + 8] = ((float)acc[nt][3] * scale >= 1.0f) ? 1 : 0;
    }
    __syncthreads();
    {
        int d = tid >> 1, hf = tid & 1;
        size_t b = (size_t)(bh >> 3), h = (size_t)(bh & 7);
        size_t off = (b << 20) + (h << 17) + ((size_t)d << 11)
                   + (size_t)tq * 64 + (size_t)hf * 32;
#pragma unroll
        for (int q4 = 0; q4 < 32; q4 += 4) {
            unsigned v = *(const unsigned*)&csh[d * 68 + hf * 32 + q4];
            *(unsigned*)(g_xs + off + q4) = v;
        }
    }
}

// =====================================================================
// Output projection: 2-stage smem double buffer, 1 barrier/chunk.
// Stage layout: A at +0 (10240 B), W at +10240 (15360 B).
// =====================================================================
#define OUT_STAGE_STS(BUFOFF)                                                 \
    do {                                                                      \
        char* bufc = smemraw + (BUFOFF);                                      \
        {                                                                     \
            unsigned w0 = pa.x, w1 = pa.y, w2 = pa.z, w3 = pa.w;              \
            uint4 o0, o1;                                                     \
            o0.x = ((w0 & 1u) ? 0x3F80u : 0u) | ((w0 & 0x100u) ? 0x3F800000u : 0u); \
            o0.y = (((w0 >> 16) & 1u) ? 0x3F80u : 0u) | ((w0 & 0x1000000u) ? 0x3F800000u : 0u); \
            o0.z = ((w1 & 1u) ? 0x3F80u : 0u) | ((w1 & 0x100u) ? 0x3F800000u : 0u); \
            o0.w = (((w1 >> 16) & 1u) ? 0x3F80u : 0u) | ((w1 & 0x1000000u) ? 0x3F800000u : 0u); \
            o1.x = ((w2 & 1u) ? 0x3F80u : 0u) | ((w2 & 0x100u) ? 0x3F800000u : 0u); \
            o1.y = (((w2 >> 16) & 1u) ? 0x3F80u : 0u) | ((w2 & 0x1000000u) ? 0x3F800000u : 0u); \
            o1.z = ((w3 & 1u) ? 0x3F80u : 0u) | ((w3 & 0x100u) ? 0x3F800000u : 0u); \
            o1.w = (((w3 >> 16) & 1u) ? 0x3F80u : 0u) | ((w3 & 0x1000000u) ? 0x3F800000u : 0u); \
            unsigned short* dstp = (unsigned short*)bufc + xrow * SROW + xhalf * 16; \
            *(uint4*)dstp       = o0;                                         \
            *(uint4*)(dstp + 8) = o1;                                         \
        }                                                                     \
        {                                                                     \
            unsigned short* wd = (unsigned short*)(bufc + 10240);             \
            *(uint4*)&wd[(0 * 64 + wrow) * SROW + wpart * 8] = pwa;           \
            *(uint4*)&wd[(1 * 64 + wrow) * SROW + wpart * 8] = pwb;           \
            *(uint4*)&wd[(2 * 64 + wrow) * SROW + wpart * 8] = pwc;           \
        }                                                                     \
    } while (0)

#define OUT_LOAD(K0)                                                          \
    do {                                                                      \
        pa  = *(const uint4*)(g_xs + (size_t)(m0 + xrow) * DD + (K0) + xhalf * 16); \
        pwa = *(const uint4*)(gW + ((size_t)0 * 512 + n0 + wrow) * 512 + (K0) + wpart * 8); \
        pwb = *(const uint4*)(gW + ((size_t)1 * 512 + n0 + wrow) * 512 + (K0) + wpart * 8); \
        pwc = *(const uint4*)(gW + ((size_t)2 * 512 + n0 + wrow) * 512 + (K0) + wpart * 8); \
    } while (0)

__global__ __launch_bounds__(256, 2) void out_mma_kernel(
    const float* __restrict__ bias, float* __restrict__ out)
{
    extern __shared__ char smemraw[];          // 2 x OUT_BUF

    const int tid  = threadIdx.x;
    const int lane = tid & 31;
    const int g    = lane >> 2, tg = lane & 3;
    const int wrp  = tid >> 5;
    const int mw   = wrp >> 1, nw = wrp & 1;

    int s2 = blockIdx.x;
    int n0 = (s2 & 7) * 64, m0 = (s2 >> 3) * 128;

    const unsigned short* gW = g_wsp + (size_t)3 * 3 * 512 * 512;
    const unsigned sbase0 = (unsigned)__cvta_generic_to_shared(smemraw);

    float C[2][4][4];
#pragma unroll
    for (int mt = 0; mt < 2; mt++)
#pragma unroll
        for (int nt = 0; nt < 4; nt++)
#pragma unroll
            for (int r = 0; r < 4; r++) C[mt][nt][r] = 0.f;

    const int arow_l = lane & 15;
    const int ak8 = (lane >> 4) * 8;
    const int brow = (lane & 7) + ((lane & 16) >> 1);
    const int bk8 = (lane & 8);
    const int xrow = tid >> 1, xhalf = tid & 1;
    const int wrow = (tid >> 2) & 63, wpart = tid & 3;

    uint4 pa, pwa, pwb, pwc;

    OUT_LOAD(0);
    OUT_STAGE_STS(0);
    OUT_LOAD(32);
    __syncthreads();

    for (int ch = 0; ch < 16; ++ch) {
        if (ch + 1 < 16) OUT_STAGE_STS(((ch + 1) & 1) * OUT_BUF);
        if (ch + 2 < 16) OUT_LOAD((ch + 2) << 5);

        const unsigned abuf = sbase0 + (unsigned)((ch & 1) * OUT_BUF);
        const unsigned wbuf = abuf + 10240;
#pragma unroll
        for (int s = 0; s < 2; ++s) {
            unsigned af[2][4];
#pragma unroll
            for (int mt = 0; mt < 2; mt++) {
                unsigned a = abuf +
                    (((mw * 32 + mt * 16 + arow_l) * SROW) + s * 16 + ak8) * 2;
                ldsm4(af[mt][0], af[mt][1], af[mt][2], af[mt][3], a);
            }
#pragma unroll
            for (int j = 0; j < 3; j++) {
                unsigned bfr[2][4];
#pragma unroll
                for (int np = 0; np < 2; np++) {
                    unsigned a = wbuf +
                        (((j * 64 + nw * 32 + np * 16 + brow) * SROW) +
                         s * 16 + bk8) * 2;
                    ldsm4(bfr[np][0], bfr[np][1], bfr[np][2], bfr[np][3], a);
                }
#pragma unroll
                for (int mt = 0; mt < 2; mt++)
#pragma unroll
                    for (int np = 0; np < 2; np++) {
                        mma_bf16(C[mt][np * 2], af[mt][0], af[mt][1], af[mt][2],
                                 af[mt][3], bfr[np][0], bfr[np][1]);
                        mma_bf16(C[mt][np * 2 + 1], af[mt][0], af[mt][1], af[mt][2],
                                 af[mt][3], bfr[np][2], bfr[np][3]);
                    }
            }
        }
        __syncthreads();
    }

#pragma unroll
    for (int mt = 0; mt < 2; mt++)
#pragma unroll
        for (int nt = 0; nt < 4; nt++) {
            int row = m0 + mw * 32 + mt * 16 + g;
            int col = n0 + nw * 32 + nt * 8 + tg * 2;
            float2 bb = *(const float2*)&bias[col];
            float2 r0, r1;
            r0.x = (C[mt][nt][0] + bb.x >= 1.0f) ? 1.0f : 0.0f;
            r0.y = (C[mt][nt][1] + bb.y >= 1.0f) ? 1.0f : 0.0f;
            r1.x = (C[mt][nt][2] + bb.x >= 1.0f) ? 1.0f : 0.0f;
            r1.y = (C[mt][nt][3] + bb.y >= 1.0f) ? 1.0f : 0.0f;
            *(float2*)&out[(size_t)row * DD + col] = r0;
            *(float2*)&out[(size_t)(row + 8) * DD + col] = r1;
        }
}

// ---------------- launch ----------------
extern "C" void kernel_launch(void* const* d_in, const int* in_sizes, int n_in,
                              void* d_out, int out_size)
{
    const float* query = (const float*)d_in[0];
    const float* key   = (const float*)d_in[1];
    const float* value = (const float*)d_in[2];
    const float* scale = (const float*)d_in[3];
    const float* Wq = (const float*)d_in[4];  const float* bq = (const float*)d_in[5];
    const float* Wk = (const float*)d_in[6];  const float* bk = (const float*)d_in[7];
    const float* Wv = (const float*)d_in[8];  const float* bv = (const float*)d_in[9];
    const float* Wo = (const float*)d_in[10]; const float* bo = (const float*)d_in[11];
    float* out = (float*)d_out;

    const int DIN = in_sizes[0] / MROWS;   // 100

    cudaFuncSetAttribute(qkv_mma_kernel,
                         cudaFuncAttributeMaxDynamicSharedMemorySize, 2 * QKV_BUF);
    cudaFuncSetAttribute(out_mma_kernel,
                         cudaFuncAttributeMaxDynamicSharedMemorySize, 2 * OUT_BUF);

    prep_w_kernel<<<dim3(8, 8, 4), 256>>>(Wq, Wk, Wv, Wo);
    qkv_mma_kernel<<<1536, 256, 2 * QKV_BUF>>>(query, key, value, bq, bk, bv, DIN);
    trans_kernel<<<2048, 64>>>();
    kvprod_kernel<<<BHN * NTW, 128>>>();
    attn_kernel<<<BHN * NTW, 128>>>(scale);
    out_mma_kernel<<<512, 256, 2 * OUT_BUF>>>(bo, out);
}

// round 15
// speedup vs baseline: 1.9897x; 1.0340x over previous
#include <cuda_runtime.h>
#include <cstdint>

#define BB 4
#define TT 2048
#define DD 512
#define HH 8
#define DK 64
#define BHN (BB*HH)          // 32
#define NTW (TT/64)          // 32 k-tiles
#define MROWS (BB*TT)        // 8192
#define SROW 40              // smem row stride (bf16 units) = 80B (out_mma)
#define OUT_BUF 25600        // one out stage: A 10240 + W 15360
#define QSTG 49152           // qkv stage: A 3x8192 + W 3x8192
#define QKV_SMEM (3*QSTG)    // 144 KB, occupancy 1

// ---------------- scratch (proven ~17 MB footprint) ----------------
__device__ unsigned long long g_qb[BHN*TT];
__device__ unsigned long long g_kb[BHN*TT];
__device__ unsigned long long g_vb[BHN*TT];
__device__ unsigned long long g_vT[BHN*DK*NTW];      // [bh][d][w]
__device__ unsigned long long g_kT[BHN*DK*NTW];      // [bh][j][w]
__device__ unsigned char      g_xs[BB*TT*DD];
__device__ unsigned short     g_wsp[4*3*512*512];    // pre-split W (6 MB)
__device__ unsigned char      g_kv[BHN*NTW*64*64];   // KV tiles s8 (4 MB)

// ---------------- helpers ----------------
__device__ __forceinline__ unsigned expand4(unsigned x) {
    return (x * 0x00204081u) & 0x01010101u;
}
__device__ __forceinline__ void mma_s8(int* c, unsigned a0, unsigned a1, unsigned a2,
                                       unsigned a3, unsigned b0, unsigned b1) {
    asm volatile(
        "mma.sync.aligned.m16n8k32.row.col.s32.s8.s8.s32 "
        "{%0,%1,%2,%3}, {%4,%5,%6,%7}, {%8,%9}, {%0,%1,%2,%3};"
        : "+r"(c[0]), "+r"(c[1]), "+r"(c[2]), "+r"(c[3])
        : "r"(a0), "r"(a1), "r"(a2), "r"(a3), "r"(b0), "r"(b1));
}
__device__ __forceinline__ void mma_bf16(float* c, unsigned a0, unsigned a1,
                                         unsigned a2, unsigned a3,
                                         unsigned b0, unsigned b1) {
    asm volatile(
        "mma.sync.aligned.m16n8k16.row.col.f32.bf16.bf16.f32 "
        "{%0,%1,%2,%3}, {%4,%5,%6,%7}, {%8,%9}, {%0,%1,%2,%3};"
        : "+f"(c[0]), "+f"(c[1]), "+f"(c[2]), "+f"(c[3])
        : "r"(a0), "r"(a1), "r"(a2), "r"(a3), "r"(b0), "r"(b1));
}
__device__ __forceinline__ void split3(float a, unsigned short& s0,
                                       unsigned short& s1, unsigned short& s2) {
    unsigned u0 = __float_as_uint(a);
    s0 = (unsigned short)(u0 >> 16);
    float r1 = a - __uint_as_float(u0 & 0xFFFF0000u);
    unsigned u1 = __float_as_uint(r1);
    s1 = (unsigned short)(u1 >> 16);
    float r2 = r1 - __uint_as_float(u1 & 0xFFFF0000u);
    s2 = (unsigned short)(__float_as_uint(r2) >> 16);
}
__device__ __forceinline__ unsigned prmt7632(unsigned a, unsigned b) {
    unsigned r;
    asm("prmt.b32 %0, %1, %2, 0x7632;" : "=r"(r) : "r"(a), "r"(b));
    return r;
}
__device__ __forceinline__ float trunchi(float a) {
    return __uint_as_float(__float_as_uint(a) & 0xFFFF0000u);
}
__device__ __forceinline__ void ldsm4(unsigned& r0, unsigned& r1, unsigned& r2,
                                      unsigned& r3, unsigned addr) {
    asm volatile("ldmatrix.sync.aligned.m8n8.x4.shared.b16 {%0,%1,%2,%3}, [%4];"
                 : "=r"(r0), "=r"(r1), "=r"(r2), "=r"(r3) : "r"(addr));
}
__device__ __forceinline__ void cpa16(unsigned dst, const void* src) {
    asm volatile("cp.async.cg.shared.global [%0], [%1], 16;" :: "r"(dst), "l"(src));
}
#define CP_COMMIT() asm volatile("cp.async.commit_group;")
#define CP_WAIT(n)  asm volatile("cp.async.wait_group %0;" :: "n"(n) : "memory")
#define SW64OFF(x) ((x) ^ (((x) >> 3) & 0x30))

// =====================================================================
// prep: split W (transposed to [n][k]) into g_wsp.
// =====================================================================
__global__ void prep_w_kernel(const float* __restrict__ Wq, const float* __restrict__ Wk,
                              const float* __restrict__ Wv, const float* __restrict__ Wo)
{
    __shared__ float sh[64][68];
    int w = blockIdx.z;
    const float* W = (w == 0) ? Wq : (w == 1) ? Wk : (w == 2) ? Wv : Wo;
    int k0 = blockIdx.x * 64, n0 = blockIdx.y * 64;
    int t = threadIdx.x;
#pragma unroll
    for (int r = 0; r < 4; r++) {
        int row = (t >> 4) * 4 + r;
        int col = (t & 15) * 4;
        float4 v = *(const float4*)&W[(size_t)(k0 + row) * DD + n0 + col];
        sh[row][col] = v.x; sh[row][col+1] = v.y; sh[row][col+2] = v.z; sh[row][col+3] = v.w;
    }
    __syncthreads();
#pragma unroll
    for (int r = 0; r < 4; r++) {
        int n = (t >> 4) * 4 + r;
        int k4 = (t & 15) * 4;
        unsigned short a0, a1, a2, b0, b1, b2, c0, c1, c2, d0, d1, d2;
        split3(sh[k4 + 0][n], a0, a1, a2);
        split3(sh[k4 + 1][n], b0, b1, b2);
        split3(sh[k4 + 2][n], c0, c1, c2);
        split3(sh[k4 + 3][n], d0, d1, d2);
        size_t base = ((size_t)(w * 3) * 512 + (n0 + n)) * 512 + k0 + k4;
        const size_t P = (size_t)512 * 512;
        *(uint2*)&g_wsp[base] =
            make_uint2((unsigned)a0 | ((unsigned)b0 << 16),
                       (unsigned)c0 | ((unsigned)d0 << 16));
        *(uint2*)&g_wsp[base + P] =
            make_uint2((unsigned)a1 | ((unsigned)b1 << 16),
                       (unsigned)c1 | ((unsigned)d1 << 16));
        *(uint2*)&g_wsp[base + 2 * P] =
            make_uint2((unsigned)a2 | ((unsigned)b2 << 16),
                       (unsigned)c2 | ((unsigned)d2 << 16));
    }
}

// =====================================================================
// qkv GEMM: 128m x 128n block, 8 warps (4m x 2n), warp 32m x 64n.
// W via cp.async from pre-split planes; A split in registers + STS.
// 3-stage SW64 smem ring, occupancy 1. Accum order (s,j,i) unchanged.
// =====================================================================
#define QKV_LOAD_A(K0)                                                        \
    do {                                                                      \
        if (which != 2) {                                                     \
            const float4* ap = (const float4*)(A + (size_t)(m0 + arow) * DD + (K0) + akh); \
            float4 x0 = ap[0], x1 = ap[1], x2 = ap[2], x3 = ap[3];            \
            pv0=x0.x; pv1=x0.y; pv2=x0.z; pv3=x0.w;                           \
            pv4=x1.x; pv5=x1.y; pv6=x1.z; pv7=x1.w;                           \
            pv8=x2.x; pv9=x2.y; pva=x2.z; pvb=x2.w;                           \
            pvc=x3.x; pvd=x3.y; pve=x3.z; pvf=x3.w;                           \
        } else {                                                              \
            const float* ar = A + (size_t)(m0 + arow) * KA;                   \
            int kb = (K0) + akh;                                              \
            pv0 = (kb+0 < KA) ? ar[kb+0] : 0.f;  pv1 = (kb+1 < KA) ? ar[kb+1] : 0.f; \
            pv2 = (kb+2 < KA) ? ar[kb+2] : 0.f;  pv3 = (kb+3 < KA) ? ar[kb+3] : 0.f; \
            pv4 = (kb+4 < KA) ? ar[kb+4] : 0.f;  pv5 = (kb+5 < KA) ? ar[kb+5] : 0.f; \
            pv6 = (kb+6 < KA) ? ar[kb+6] : 0.f;  pv7 = (kb+7 < KA) ? ar[kb+7] : 0.f; \
            pv8 = (kb+8 < KA) ? ar[kb+8] : 0.f;  pv9 = (kb+9 < KA) ? ar[kb+9] : 0.f; \
            pva = (kb+10 < KA) ? ar[kb+10] : 0.f; pvb = (kb+11 < KA) ? ar[kb+11] : 0.f; \
            pvc = (kb+12 < KA) ? ar[kb+12] : 0.f; pvd = (kb+13 < KA) ? ar[kb+13] : 0.f; \
            pve = (kb+14 < KA) ? ar[kb+14] : 0.f; pvf = (kb+15 < KA) ? ar[kb+15] : 0.f; \
        }                                                                     \
    } while (0)

#define SPLITPAIR(I, VA, VB)                                                  \
    do {                                                                      \
        float ra_ = (VA), rb_ = (VB);                                         \
        p0_[I] = prmt7632(__float_as_uint(ra_), __float_as_uint(rb_));        \
        ra_ -= trunchi(ra_); rb_ -= trunchi(rb_);                             \
        p1_[I] = prmt7632(__float_as_uint(ra_), __float_as_uint(rb_));        \
        ra_ -= trunchi(ra_); rb_ -= trunchi(rb_);                             \
        p2_[I] = prmt7632(__float_as_uint(ra_), __float_as_uint(rb_));        \
    } while (0)

// A split + STS into stage (SW64, 64B rows, planes 8 KB apart)
#define QKV_STSA(STG)                                                         \
    do {                                                                      \
        char* bufc = smemraw + (size_t)(STG) * QSTG;                          \
        unsigned p0_[8], p1_[8], p2_[8];                                      \
        SPLITPAIR(0, pv0, pv1); SPLITPAIR(1, pv2, pv3);                       \
        SPLITPAIR(2, pv4, pv5); SPLITPAIR(3, pv6, pv7);                       \
        SPLITPAIR(4, pv8, pv9); SPLITPAIR(5, pva, pvb);                       \
        SPLITPAIR(6, pvc, pvd); SPLITPAIR(7, pve, pvf);                       \
        unsigned aoff = (unsigned)(arow * 64 + akh * 2);                      \
        unsigned alo = SW64OFF(aoff), ahi = SW64OFF(aoff + 16);               \
        *(uint4*)(bufc + alo)         = make_uint4(p0_[0], p0_[1], p0_[2], p0_[3]); \
        *(uint4*)(bufc + ahi)         = make_uint4(p0_[4], p0_[5], p0_[6], p0_[7]); \
        *(uint4*)(bufc + 8192 + alo)  = make_uint4(p1_[0], p1_[1], p1_[2], p1_[3]); \
        *(uint4*)(bufc + 8192 + ahi)  = make_uint4(p1_[4], p1_[5], p1_[6], p1_[7]); \
        *(uint4*)(bufc + 16384 + alo) = make_uint4(p2_[0], p2_[1], p2_[2], p2_[3]); \
        *(uint4*)(bufc + 16384 + ahi) = make_uint4(p2_[4], p2_[5], p2_[6], p2_[7]); \
    } while (0)

// W cp.async for chunk CH into stage STG: 6 x 16B per thread + commit
#define QKV_CPW(CH, STG)                                                      \
    do {                                                                      \
        unsigned wb = sb + (unsigned)((STG) * QSTG + 24576);                  \
        const int kk0 = (CH) << 5;                                            \
        _Pragma("unroll")                                                     \
        for (int i_ = 0; i_ < 6; i_++) {                                      \
            int u_ = tid + 256 * i_;                                          \
            int sp_ = u_ >> 9, row_ = (u_ >> 2) & 127, c_ = u_ & 3;           \
            unsigned d_ = wb + sp_ * 8192 +                                   \
                          SW64OFF((unsigned)(row_ * 64 + c_ * 16));           \
            cpa16(d_, gW + ((size_t)sp_ * 512 + n0 + row_) * 512 + kk0 + c_ * 8); \
        }                                                                     \
        CP_COMMIT();                                                          \
    } while (0)

__global__ __launch_bounds__(256, 1) void qkv_mma_kernel(
    const float* __restrict__ Aq, const float* __restrict__ Ak,
    const float* __restrict__ Av,
    const float* __restrict__ bq, const float* __restrict__ bk,
    const float* __restrict__ bv, int DIN)
{
    extern __shared__ char smemraw[];   // 3 x QSTG

    const int tid  = threadIdx.x;
    const int lane = tid & 31;
    const int g    = lane >> 2, tg = lane & 3;
    const int wrp  = tid >> 5;
    const int mw   = wrp >> 1, nw = wrp & 1;

    int idx = blockIdx.x;
    int which = idx >> 8;                      // 0=k,1=v,2=q
    int s2 = idx & 255;
    int n0 = (s2 & 3) * 128, m0 = (s2 >> 2) * 128;

    const float* A    = (which == 0) ? Ak : (which == 1) ? Av : Aq;
    const float* bias = (which == 0) ? bk : (which == 1) ? bv : bq;
    const int KA = DIN;
    const int KS = (which == 2) ? 128 : DD;
    const int wsel = (which == 0) ? 1 : (which == 1) ? 2 : 0;
    const unsigned short* gW = g_wsp + (size_t)wsel * 3 * 512 * 512;

    const unsigned sb = (unsigned)__cvta_generic_to_shared(smemraw);

    float C[2][8][4];
#pragma unroll
    for (int mt = 0; mt < 2; mt++)
#pragma unroll
        for (int nt = 0; nt < 8; nt++)
#pragma unroll
            for (int r = 0; r < 4; r++) C[mt][nt][r] = 0.f;

    const int arow = tid >> 1, akh = (tid & 1) * 16;
    const int arow_l = lane & 15;
    const int ak16b = (lane >> 4) * 16;              // byte offset within row
    const int brow = (lane & 7) + ((lane & 16) >> 1);
    const int bk16b = (lane & 8) * 2;                // 0 or 16 bytes

    float pv0,pv1,pv2,pv3,pv4,pv5,pv6,pv7,pv8,pv9,pva,pvb,pvc,pvd,pve,pvf;

    const int nch = KS >> 5;

    // ---- prologue: stages 0,1 staged; A regs for chunk 2; W groups 0,1 ----
    QKV_LOAD_A(0);
    QKV_CPW(0, 0);
    QKV_STSA(0);
    if (nch > 1) {
        QKV_LOAD_A(32);
        QKV_CPW(1, 1);
        QKV_STSA(1);
    }
    if (nch > 2) QKV_LOAD_A(64);

    for (int ch = 0; ch < nch; ++ch) {
        const int stg = ch % 3;
        if (ch + 1 < nch) { CP_WAIT(1); } else { CP_WAIT(0); }
        __syncthreads();                   // stage stg ready (A STS + W async)
        if (ch + 2 < nch) {
            QKV_CPW(ch + 2, (ch + 2) % 3);
            QKV_STSA((ch + 2) % 3);
            if (ch + 3 < nch) QKV_LOAD_A((ch + 3) << 5);
        }
        // ---- MMA on stage stg ----
        const unsigned abuf = sb + (unsigned)(stg * QSTG);
        const unsigned wbuf = abuf + 24576;
#pragma unroll
        for (int s = 0; s < 2; ++s) {
            unsigned af[3][2][4];
#pragma unroll
            for (int sp = 0; sp < 3; sp++)
#pragma unroll
                for (int mt = 0; mt < 2; mt++) {
                    unsigned a = abuf + sp * 8192 +
                        SW64OFF((unsigned)((mw * 32 + mt * 16 + arow_l) * 64 +
                                           s * 32 + ak16b));
                    ldsm4(af[sp][mt][0], af[sp][mt][1], af[sp][mt][2], af[sp][mt][3], a);
                }
#pragma unroll
            for (int j = 0; j < 3; j++) {
                unsigned bfr[4][4];
#pragma unroll
                for (int np = 0; np < 4; np++) {
                    unsigned a = wbuf + j * 8192 +
                        SW64OFF((unsigned)((nw * 64 + np * 16 + brow) * 64 +
                                           s * 32 + bk16b));
                    ldsm4(bfr[np][0], bfr[np][1], bfr[np][2], bfr[np][3], a);
                }
#pragma unroll
                for (int i = 0; i < 3; i++) {
                    if (i + j > 2) break;
#pragma unroll
                    for (int mt = 0; mt < 2; mt++)
#pragma unroll
                        for (int np = 0; np < 4; np++) {
                            mma_bf16(C[mt][np * 2], af[i][mt][0], af[i][mt][1],
                                     af[i][mt][2], af[i][mt][3],
                                     bfr[np][0], bfr[np][1]);
                            mma_bf16(C[mt][np * 2 + 1], af[i][mt][0], af[i][mt][1],
                                     af[i][mt][2], af[i][mt][3],
                                     bfr[np][2], bfr[np][3]);
                        }
                }
            }
        }
    }

    // ---- epilogue: bias + spike -> bytes (overlay stage 0) -> bitpack ----
    __syncthreads();
    unsigned char* sbyte = (unsigned char*)smemraw;   // [128][128]
#pragma unroll
    for (int mt = 0; mt < 2; mt++)
#pragma unroll
        for (int nt = 0; nt < 8; nt++) {
            int row = mw * 32 + mt * 16 + g;
            int col = nw * 64 + nt * 8 + tg * 2;
            float2 bb = *(const float2*)&bias[n0 + col];
            sbyte[row * 128 + col]           = (C[mt][nt][0] + bb.x >= 1.0f) ? 1 : 0;
            sbyte[row * 128 + col + 1]       = (C[mt][nt][1] + bb.y >= 1.0f) ? 1 : 0;
            sbyte[(row + 8) * 128 + col]     = (C[mt][nt][2] + bb.x >= 1.0f) ? 1 : 0;
            sbyte[(row + 8) * 128 + col + 1] = (C[mt][nt][3] + bb.y >= 1.0f) ? 1 : 0;
        }
    __syncthreads();
    {
        int row = tid >> 1, hf = tid & 1;
        unsigned long long bits = 0ull;
#pragma unroll
        for (int q = 0; q < 8; q++) {
            unsigned long long u =
                *(const unsigned long long*)&sbyte[row * 128 + hf * 64 + 8 * q];
#pragma unroll
            for (int j = 0; j < 8; j++)
                bits |= ((u >> (8 * j)) & 1ull) << (8 * q + j);
        }
        int m = m0 + row;
        int b = m >> 11, t = m & 2047;
        int head = (n0 >> 6) + hf;
        unsigned long long* dst = (which == 2) ? g_qb : (which == 0) ? g_kb : g_vb;
        dst[(size_t)((b << 3) + head) * TT + t] = bits;
    }
}

// ---------------- bit transpose for k and v ----------------
__global__ void trans_kernel()
{
    int bx = blockIdx.x;
    int which = bx >> 10;
    int idx = bx & 1023;
    int bh = idx >> 5, w = idx & 31;
    int tid = threadIdx.x;
    int lane = tid & 31, warp = tid >> 5;
    __shared__ unsigned sh[64][2];
    const unsigned long long* src = (which == 0) ? g_vb : g_kb;
    unsigned long long* dst = (which == 0) ? g_vT : g_kT;
    unsigned long long r = src[(size_t)bh * TT + w * 64 + tid];
#pragma unroll 8
    for (int d = 0; d < 64; d++) {
        unsigned b = __ballot_sync(0xffffffffu, (unsigned)((r >> d) & 1ull));
        if (lane == 0) sh[d][warp] = b;
    }
    __syncthreads();
    dst[(size_t)(bh * 64 + tid) * 32 + w] =
        (unsigned long long)sh[tid][0] | ((unsigned long long)sh[tid][1] << 32);
}

// =====================================================================
// KV precompute (unchanged).
// =====================================================================
__global__ __launch_bounds__(128) void kvprod_kernel()
{
    const int tid = threadIdx.x;
    const int lane = tid & 31;
    const int g = lane >> 2, tg = lane & 3;
    const int wr16 = (tid >> 5) * 16;

    int bh = blockIdx.x >> 5, w = blockIdx.x & 31;

    unsigned long long vd0 = g_vT[((size_t)bh * 64 + wr16 + g) * 32 + w];
    unsigned long long vd1 = g_vT[((size_t)bh * 64 + wr16 + 8 + g) * 32 + w];
    unsigned long long kt[8];
#pragma unroll
    for (int nt = 0; nt < 8; nt++)
        kt[nt] = g_kT[((size_t)bh * 64 + nt * 8 + g) * 32 + w];

    int acc[8][4];
#pragma unroll
    for (int nt = 0; nt < 8; nt++)
#pragma unroll
        for (int r = 0; r < 4; r++) acc[nt][r] = 0;

#pragma unroll
    for (int s = 0; s < 2; s++) {
        unsigned l0 = (unsigned)(vd0 >> (32 * s));
        unsigned l1 = (unsigned)(vd1 >> (32 * s));
        unsigned a0 = expand4((l0 >> (4 * tg)) & 0xFu);
        unsigned a1 = expand4((l1 >> (4 * tg)) & 0xFu);
        unsigned a2 = expand4((l0 >> (16 + 4 * tg)) & 0xFu);
        unsigned a3 = expand4((l1 >> (16 + 4 * tg)) & 0xFu);
#pragma unroll
        for (int nt = 0; nt < 8; nt++) {
            unsigned kl = (unsigned)(kt[nt] >> (32 * s));
            unsigned b0 = expand4((kl >> (4 * tg)) & 0xFu);
            unsigned b1 = expand4((kl >> (16 + 4 * tg)) & 0xFu);
            mma_s8(acc[nt], a0, a1, a2, a3, b0, b1);
        }
    }

    unsigned char* dst = g_kv + ((size_t)(bh * 32 + w) * 64) * 64;
#pragma unroll
    for (int nt = 0; nt < 8; nt++) {
        int j0 = nt * 8 + 2 * tg;
        *(unsigned short*)(dst + (wr16 + g) * 64 + j0) =
            (unsigned short)((acc[nt][0] & 0xFF) | ((acc[nt][1] & 0xFF) << 8));
        *(unsigned short*)(dst + (wr16 + 8 + g) * 64 + j0) =
            (unsigned short)((acc[nt][2] & 0xFF) | ((acc[nt][3] & 0xFF) << 8));
    }
}

// =====================================================================
// Attention (unchanged from 272.8us run).
// =====================================================================
__global__ __launch_bounds__(128) void attn_kernel(const float* __restrict__ scale_p)
{
    __shared__ __align__(16) unsigned char KVsh[2][64 * 80];
    __shared__ unsigned char csh[64 * 68];
    __shared__ unsigned long long ksh[64];

    const int tid = threadIdx.x;
    const int lane = tid & 31;
    const int g = lane >> 2, tg = lane & 3;
    const int wr16 = (tid >> 5) * 16;
    const int rowA = wr16 + g;

    int bx = blockIdx.x;
    int bh = bx & 31;
    int tq = 31 - (bx >> 5);

    const float scale = *scale_p;
    const size_t base = (size_t)bh * TT;
    const unsigned char* KVg = g_kv + (size_t)bh * 32 * 64 * 64;

    unsigned long long q0 = g_qb[base + (size_t)tq * 64 + rowA];
    unsigned long long q1 = g_qb[base + (size_t)tq * 64 + rowA + 8];
    unsigned qa[2][4];
#pragma unroll
    for (int s = 0; s < 2; s++) {
        unsigned l0 = (unsigned)(q0 >> (32 * s));
        unsigned l1 = (unsigned)(q1 >> (32 * s));
        qa[s][0] = expand4((l0 >> (4 * tg)) & 0xFu);
        qa[s][1] = expand4((l1 >> (4 * tg)) & 0xFu);
        qa[s][2] = expand4((l0 >> (16 + 4 * tg)) & 0xFu);
        qa[s][3] = expand4((l1 >> (16 + 4 * tg)) & 0xFu);
    }

    int acc[8][4];
#pragma unroll
    for (int nt = 0; nt < 8; nt++)
#pragma unroll
        for (int r = 0; r < 4; r++) acc[nt][r] = 0;

    const int kvrow0 = tid >> 2, kvp0 = tid & 3;
    const int kvrow1 = (tid + 128) >> 2, kvp1 = tid & 3;
    const unsigned kvb0 = (unsigned)__cvta_generic_to_shared(&KVsh[0][0]);
    const unsigned kvb1 = (unsigned)__cvta_generic_to_shared(&KVsh[1][0]);

    if (tq > 0) {
        cpa16(kvb0 + kvrow0 * 80 + kvp0 * 16, KVg + 0 * 4096 + kvrow0 * 64 + kvp0 * 16);
        cpa16(kvb0 + kvrow1 * 80 + kvp1 * 16, KVg + 0 * 4096 + kvrow1 * 64 + kvp1 * 16);
        CP_COMMIT();
    }
    for (int w = 0; w < tq; ++w) {
        __syncthreads();
        if (w + 1 < tq) {
            unsigned kb = ((w + 1) & 1) ? kvb1 : kvb0;
            const unsigned char* src = KVg + (size_t)(w + 1) * 4096;
            cpa16(kb + kvrow0 * 80 + kvp0 * 16, src + kvrow0 * 64 + kvp0 * 16);
            cpa16(kb + kvrow1 * 80 + kvp1 * 16, src + kvrow1 * 64 + kvp1 * 16);
            CP_COMMIT();
            CP_WAIT(1);
        } else {
            CP_WAIT(0);
        }
        __syncthreads();
        const unsigned char* kb = KVsh[w & 1];
#pragma unroll
        for (int s = 0; s < 2; s++)
#pragma unroll
            for (int nt = 0; nt < 8; nt++) {
                unsigned b0 = *(const unsigned*)(kb + (nt * 8 + g) * 80 + s * 32 + tg * 4);
                unsigned b1 = *(const unsigned*)(kb + (nt * 8 + g) * 80 + s * 32 + 16 + tg * 4);
                mma_s8(acc[nt], qa[s][0], qa[s][1], qa[s][2], qa[s][3], b0, b1);
            }
    }

    if (tid < 64) ksh[tid] = g_kb[base + (size_t)tq * 64 + tid];
    unsigned long long vt[8];
#pragma unroll
    for (int nt = 0; nt < 8; nt++)
        vt[nt] = g_vT[((size_t)bh * 64 + nt * 8 + g) * 32 + tq];
    __syncthreads();

    {
        unsigned long long kk[8];
#pragma unroll
        for (int nt = 0; nt < 8; nt++) kk[nt] = ksh[nt * 8 + g];
        int qcc[8][4];
#pragma unroll
        for (int nt = 0; nt < 8; nt++)
#pragma unroll
            for (int r = 0; r < 4; r++) qcc[nt][r] = 0;
#pragma unroll
        for (int s = 0; s < 2; s++)
#pragma unroll
            for (int nt = 0; nt < 8; nt++) {
                unsigned kl = (unsigned)(kk[nt] >> (32 * s));
                unsigned b0 = expand4((kl >> (4 * tg)) & 0xFu);
                unsigned b1 = expand4((kl >> (16 + 4 * tg)) & 0xFu);
                mma_s8(qcc[nt], qa[s][0], qa[s][1], qa[s][2], qa[s][3], b0, b1);
            }
        int t0 = rowA, t1 = rowA + 8;
#pragma unroll
        for (int nt = 0; nt < 8; nt++) {
            int kc = nt * 8 + 2 * tg;
            unsigned v00 = (kc <= t0) ? (qcc[nt][0] & 0xFF) : 0u;
            unsigned v01 = (kc + 1 <= t0) ? (qcc[nt][1] & 0xFF) : 0u;
            unsigned v10 = (kc <= t1) ? (qcc[nt][2] & 0xFF) : 0u;
            unsigned v11 = (kc + 1 <= t1) ? (qcc[nt][3] & 0xFF) : 0u;
            *(unsigned short*)&csh[t0 * 68 + kc] = (unsigned short)(v00 | (v01 << 8));
            *(unsigned short*)&csh[t1 * 68 + kc] = (unsigned short)(v10 | (v11 << 8));
        }
        __syncwarp();
#pragma unroll
        for (int s = 0; s < 2; s++) {
            unsigned a0 = *(const unsigned*)&csh[rowA * 68 + s * 32 + tg * 4];
            unsigned a1 = *(const unsigned*)&csh[(rowA + 8) * 68 + s * 32 + tg * 4];
            unsigned a2 = *(const unsigned*)&csh[rowA * 68 + s * 32 + 16 + tg * 4];
            unsigned a3 = *(const unsigned*)&csh[(rowA + 8) * 68 + s * 32 + 16 + tg * 4];
#pragma unroll
            for (int nt = 0; nt < 8; nt++) {
                unsigned b0 = expand4((unsigned)(vt[nt] >> (s * 32 + tg * 4)) & 0xFu);
                unsigned b1 = expand4((unsigned)(vt[nt] >> (s * 32 + 16 + tg * 4)) & 0xFu);
                mma_s8(acc[nt], a0, a1, a2, a3, b0, b1);
            }
        }
    }

    __syncthreads();
#pragma unroll
    for (int nt = 0; nt < 8; ++nt) {
        int d0 = nt * 8 + tg * 2;
        csh[d0 * 68 + rowA]           = ((float)acc[nt][0] * scale >= 1.0f) ? 1 : 0;
        csh[(d0 + 1) * 68 + rowA]     = ((float)acc[nt][1] * scale >= 1.0f) ? 1 : 0;
        csh[d0 * 68 + rowA + 8]       = ((float)acc[nt][2] * scale >= 1.0f) ? 1 : 0;
        csh[(d0 + 1) * 68 + rowA + 8] = ((float)acc[nt][3] * scale >= 1.0f) ? 1 : 0;
    }
    __syncthreads();
    {
        int d = tid >> 1, hf = tid & 1;
        size_t b = (size_t)(bh >> 3), h = (size_t)(bh & 7);
        size_t off = (b << 20) + (h << 17) + ((size_t)d << 11)
                   + (size_t)tq * 64 + (size_t)hf * 32;
#pragma unroll
        for (int q4 = 0; q4 < 32; q4 += 4) {
            unsigned v = *(const unsigned*)&csh[d * 68 + hf * 32 + q4];
            *(unsigned*)(g_xs + off + q4) = v;
        }
    }
}

// =====================================================================
// Output projection (unchanged from 272.8us run): double-buffered.
// =====================================================================
#define OUT_STAGE_STS(BUFOFF)                                                 \
    do {                                                                      \
        char* bufc = smemraw + (BUFOFF);                                      \
        {                                                                     \
            unsigned w0 = pa.x, w1 = pa.y, w2 = pa.z, w3 = pa.w;              \
            uint4 o0, o1;                                                     \
            o0.x = ((w0 & 1u) ? 0x3F80u : 0u) | ((w0 & 0x100u) ? 0x3F800000u : 0u); \
            o0.y = (((w0 >> 16) & 1u) ? 0x3F80u : 0u) | ((w0 & 0x1000000u) ? 0x3F800000u : 0u); \
            o0.z = ((w1 & 1u) ? 0x3F80u : 0u) | ((w1 & 0x100u) ? 0x3F800000u : 0u); \
            o0.w = (((w1 >> 16) & 1u) ? 0x3F80u : 0u) | ((w1 & 0x1000000u) ? 0x3F800000u : 0u); \
            o1.x = ((w2 & 1u) ? 0x3F80u : 0u) | ((w2 & 0x100u) ? 0x3F800000u : 0u); \
            o1.y = (((w2 >> 16) & 1u) ? 0x3F80u : 0u) | ((w2 & 0x1000000u) ? 0x3F800000u : 0u); \
            o1.z = ((w3 & 1u) ? 0x3F80u : 0u) | ((w3 & 0x100u) ? 0x3F800000u : 0u); \
            o1.w = (((w3 >> 16) & 1u) ? 0x3F80u : 0u) | ((w3 & 0x1000000u) ? 0x3F800000u : 0u); \
            unsigned short* dstp = (unsigned short*)bufc + xrow * SROW + xhalf * 16; \
            *(uint4*)dstp       = o0;                                         \
            *(uint4*)(dstp + 8) = o1;                                         \
        }                                                                     \
        {                                                                     \
            unsigned short* wd = (unsigned short*)(bufc + 10240);             \
            *(uint4*)&wd[(0 * 64 + wrow) * SROW + wpart * 8] = pwa;           \
            *(uint4*)&wd[(1 * 64 + wrow) * SROW + wpart * 8] = pwb;           \
            *(uint4*)&wd[(2 * 64 + wrow) * SROW + wpart * 8] = pwc;           \
        }                                                                     \
    } while (0)

#define OUT_LOAD(K0)                                                          \
    do {                                                                      \
        pa  = *(const uint4*)(g_xs + (size_t)(m0 + xrow) * DD + (K0) + xhalf * 16); \
        pwa = *(const uint4*)(gW + ((size_t)0 * 512 + n0 + wrow) * 512 + (K0) + wpart * 8); \
        pwb = *(const uint4*)(gW + ((size_t)1 * 512 + n0 + wrow) * 512 + (K0) + wpart * 8); \
        pwc = *(const uint4*)(gW + ((size_t)2 * 512 + n0 + wrow) * 512 + (K0) + wpart * 8); \
    } while (0)

__global__ __launch_bounds__(256, 2) void out_mma_kernel(
    const float* __restrict__ bias, float* __restrict__ out)
{
    extern __shared__ char smemraw[];          // 2 x OUT_BUF

    const int tid  = threadIdx.x;
    const int lane = tid & 31;
    const int g    = lane >> 2, tg = lane & 3;
    const int wrp  = tid >> 5;
    const int mw   = wrp >> 1, nw = wrp & 1;

    int s2 = blockIdx.x;
    int n0 = (s2 & 7) * 64, m0 = (s2 >> 3) * 128;

    const unsigned short* gW = g_wsp + (size_t)3 * 3 * 512 * 512;
    const unsigned sbase0 = (unsigned)__cvta_generic_to_shared(smemraw);

    float C[2][4][4];
#pragma unroll
    for (int mt = 0; mt < 2; mt++)
#pragma unroll
        for (int nt = 0; nt < 4; nt++)
#pragma unroll
            for (int r = 0; r < 4; r++) C[mt][nt][r] = 0.f;

    const int arow_l = lane & 15;
    const int ak8 = (lane >> 4) * 8;
    const int brow = (lane & 7) + ((lane & 16) >> 1);
    const int bk8 = (lane & 8);
    const int xrow = tid >> 1, xhalf = tid & 1;
    const int wrow = (tid >> 2) & 63, wpart = tid & 3;

    uint4 pa, pwa, pwb, pwc;

    OUT_LOAD(0);
    OUT_STAGE_STS(0);
    OUT_LOAD(32);
    __syncthreads();

    for (int ch = 0; ch < 16; ++ch) {
        if (ch + 1 < 16) OUT_STAGE_STS(((ch + 1) & 1) * OUT_BUF);
        if (ch + 2 < 16) OUT_LOAD((ch + 2) << 5);

        const unsigned abuf = sbase0 + (unsigned)((ch & 1) * OUT_BUF);
        const unsigned wbuf = abuf + 10240;
#pragma unroll
        for (int s = 0; s < 2; ++s) {
            unsigned af[2][4];
#pragma unroll
            for (int mt = 0; mt < 2; mt++) {
                unsigned a = abuf +
                    (((mw * 32 + mt * 16 + arow_l) * SROW) + s * 16 + ak8) * 2;
                ldsm4(af[mt][0], af[mt][1], af[mt][2], af[mt][3], a);
            }
#pragma unroll
            for (int j = 0; j < 3; j++) {
                unsigned bfr[2][4];
#pragma unroll
                for (int np = 0; np < 2; np++) {
                    unsigned a = wbuf +
                        (((j * 64 + nw * 32 + np * 16 + brow) * SROW) +
                         s * 16 + bk8) * 2;
                    ldsm4(bfr[np][0], bfr[np][1], bfr[np][2], bfr[np][3], a);
                }
#pragma unroll
                for (int mt = 0; mt < 2; mt++)
#pragma unroll
                    for (int np = 0; np < 2; np++) {
                        mma_bf16(C[mt][np * 2], af[mt][0], af[mt][1], af[mt][2],
                                 af[mt][3], bfr[np][0], bfr[np][1]);
                        mma_bf16(C[mt][np * 2 + 1], af[mt][0], af[mt][1], af[mt][2],
                                 af[mt][3], bfr[np][2], bfr[np][3]);
                    }
            }
        }
        __syncthreads();
    }

#pragma unroll
    for (int mt = 0; mt < 2; mt++)
#pragma unroll
        for (int nt = 0; nt < 4; nt++) {
            int row = m0 + mw * 32 + mt * 16 + g;
            int col = n0 + nw * 32 + nt * 8 + tg * 2;
            float2 bb = *(const float2*)&bias[col];
            float2 r0, r1;
            r0.x = (C[mt][nt][0] + bb.x >= 1.0f) ? 1.0f : 0.0f;
            r0.y = (C[mt][nt][1] + bb.y >= 1.0f) ? 1.0f : 0.0f;
            r1.x = (C[mt][nt][2] + bb.x >= 1.0f) ? 1.0f : 0.0f;
            r1.y = (C[mt][nt][3] + bb.y >= 1.0f) ? 1.0f : 0.0f;
            *(float2*)&out[(size_t)row * DD + col] = r0;
            *(float2*)&out[(size_t)(row + 8) * DD + col] = r1;
        }
}

// ---------------- launch ----------------
extern "C" void kernel_launch(void* const* d_in, const int* in_sizes, int n_in,
                              void* d_out, int out_size)
{
    const float* query = (const float*)d_in[0];
    const float* key   = (const float*)d_in[1];
    const float* value = (const float*)d_in[2];
    const float* scale = (const float*)d_in[3];
    const float* Wq = (const float*)d_in[4];  const float* bq = (const float*)d_in[5];
    const float* Wk = (const float*)d_in[6];  const float* bk = (const float*)d_in[7];
    const float* Wv = (const float*)d_in[8];  const float* bv = (const float*)d_in[9];
    const float* Wo = (const float*)d_in[10]; const float* bo = (const float*)d_in[11];
    float* out = (float*)d_out;

    const int DIN = in_sizes[0] / MROWS;   // 100

    cudaFuncSetAttribute(qkv_mma_kernel,
                         cudaFuncAttributeMaxDynamicSharedMemorySize, QKV_SMEM);
    cudaFuncSetAttribute(out_mma_kernel,
                         cudaFuncAttributeMaxDynamicSharedMemorySize, 2 * OUT_BUF);

    prep_w_kernel<<<dim3(8, 8, 4), 256>>>(Wq, Wk, Wv, Wo);
    qkv_mma_kernel<<<768, 256, QKV_SMEM>>>(query, key, value, bq, bk, bv, DIN);
    trans_kernel<<<2048, 64>>>();
    kvprod_kernel<<<BHN * NTW, 128>>>();
    attn_kernel<<<BHN * NTW, 128>>>(scale);
    out_mma_kernel<<<512, 256, 2 * OUT_BUF>>>(bo, out);
}

// round 16
// speedup vs baseline: 2.0186x; 1.0145x over previous
#include <cuda_runtime.h>
#include <cstdint>

#define BB 4
#define TT 2048
#define DD 512
#define HH 8
#define DK 64
#define BHN (BB*HH)          // 32
#define NTW (TT/64)          // 32 k-tiles
#define MROWS (BB*TT)        // 8192
#define QSTG 49152           // qkv stage: A 3x8192 + W 3x8192
#define QKV_SMEM (3*QSTG)    // 144 KB
#define OSTG 32768           // out stage: A 8192 + W 3x8192
#define OUT_SMEM (3*OSTG)    // 96 KB

// ---------------- scratch ----------------
__device__ unsigned long long g_qb[BHN*TT];
__device__ unsigned long long g_kb[BHN*TT];
__device__ unsigned long long g_vb[BHN*TT];
__device__ unsigned long long g_vT[BHN*DK*NTW];      // [bh][d][w]
__device__ unsigned char      g_xs[BB*TT*DD];
__device__ unsigned short     g_wsp[4*3*512*512];    // pre-split W (6 MB)
__device__ unsigned char      g_kv[BHN*NTW*64*64];   // KV tiles s8 (4 MB)

// ---------------- helpers ----------------
__device__ __forceinline__ unsigned expand4(unsigned x) {
    return (x * 0x00204081u) & 0x01010101u;
}
__device__ __forceinline__ void mma_s8(int* c, unsigned a0, unsigned a1, unsigned a2,
                                       unsigned a3, unsigned b0, unsigned b1) {
    asm volatile(
        "mma.sync.aligned.m16n8k32.row.col.s32.s8.s8.s32 "
        "{%0,%1,%2,%3}, {%4,%5,%6,%7}, {%8,%9}, {%0,%1,%2,%3};"
        : "+r"(c[0]), "+r"(c[1]), "+r"(c[2]), "+r"(c[3])
        : "r"(a0), "r"(a1), "r"(a2), "r"(a3), "r"(b0), "r"(b1));
}
__device__ __forceinline__ void mma_bf16(float* c, unsigned a0, unsigned a1,
                                         unsigned a2, unsigned a3,
                                         unsigned b0, unsigned b1) {
    asm volatile(
        "mma.sync.aligned.m16n8k16.row.col.f32.bf16.bf16.f32 "
        "{%0,%1,%2,%3}, {%4,%5,%6,%7}, {%8,%9}, {%0,%1,%2,%3};"
        : "+f"(c[0]), "+f"(c[1]), "+f"(c[2]), "+f"(c[3])
        : "r"(a0), "r"(a1), "r"(a2), "r"(a3), "r"(b0), "r"(b1));
}
__device__ __forceinline__ void split3(float a, unsigned short& s0,
                                       unsigned short& s1, unsigned short& s2) {
    unsigned u0 = __float_as_uint(a);
    s0 = (unsigned short)(u0 >> 16);
    float r1 = a - __uint_as_float(u0 & 0xFFFF0000u);
    unsigned u1 = __float_as_uint(r1);
    s1 = (unsigned short)(u1 >> 16);
    float r2 = r1 - __uint_as_float(u1 & 0xFFFF0000u);
    s2 = (unsigned short)(__float_as_uint(r2) >> 16);
}
__device__ __forceinline__ unsigned prmt7632(unsigned a, unsigned b) {
    unsigned r;
    asm("prmt.b32 %0, %1, %2, 0x7632;" : "=r"(r) : "r"(a), "r"(b));
    return r;
}
__device__ __forceinline__ float trunchi(float a) {
    return __uint_as_float(__float_as_uint(a) & 0xFFFF0000u);
}
__device__ __forceinline__ void ldsm4(unsigned& r0, unsigned& r1, unsigned& r2,
                                      unsigned& r3, unsigned addr) {
    asm volatile("ldmatrix.sync.aligned.m8n8.x4.shared.b16 {%0,%1,%2,%3}, [%4];"
                 : "=r"(r0), "=r"(r1), "=r"(r2), "=r"(r3) : "r"(addr));
}
__device__ __forceinline__ void cpa16(unsigned dst, const void* src) {
    asm volatile("cp.async.cg.shared.global [%0], [%1], 16;" :: "r"(dst), "l"(src));
}
#define CP_COMMIT() asm volatile("cp.async.commit_group;")
#define CP_WAIT(n)  asm volatile("cp.async.wait_group %0;" :: "n"(n) : "memory")
#define SW64OFF(x) ((x) ^ (((x) >> 3) & 0x30))

// =====================================================================
// prep: split W (transposed to [n][k]) into g_wsp.
// =====================================================================
__global__ void prep_w_kernel(const float* __restrict__ Wq, const float* __restrict__ Wk,
                              const float* __restrict__ Wv, const float* __restrict__ Wo)
{
    __shared__ float sh[64][68];
    int w = blockIdx.z;
    const float* W = (w == 0) ? Wq : (w == 1) ? Wk : (w == 2) ? Wv : Wo;
    int k0 = blockIdx.x * 64, n0 = blockIdx.y * 64;
    int t = threadIdx.x;
#pragma unroll
    for (int r = 0; r < 4; r++) {
        int row = (t >> 4) * 4 + r;
        int col = (t & 15) * 4;
        float4 v = *(const float4*)&W[(size_t)(k0 + row) * DD + n0 + col];
        sh[row][col] = v.x; sh[row][col+1] = v.y; sh[row][col+2] = v.z; sh[row][col+3] = v.w;
    }
    __syncthreads();
#pragma unroll
    for (int r = 0; r < 4; r++) {
        int n = (t >> 4) * 4 + r;
        int k4 = (t & 15) * 4;
        unsigned short a0, a1, a2, b0, b1, b2, c0, c1, c2, d0, d1, d2;
        split3(sh[k4 + 0][n], a0, a1, a2);
        split3(sh[k4 + 1][n], b0, b1, b2);
        split3(sh[k4 + 2][n], c0, c1, c2);
        split3(sh[k4 + 3][n], d0, d1, d2);
        size_t base = ((size_t)(w * 3) * 512 + (n0 + n)) * 512 + k0 + k4;
        const size_t P = (size_t)512 * 512;
        *(uint2*)&g_wsp[base] =
            make_uint2((unsigned)a0 | ((unsigned)b0 << 16),
                       (unsigned)c0 | ((unsigned)d0 << 16));
        *(uint2*)&g_wsp[base + P] =
            make_uint2((unsigned)a1 | ((unsigned)b1 << 16),
                       (unsigned)c1 | ((unsigned)d1 << 16));
        *(uint2*)&g_wsp[base + 2 * P] =
            make_uint2((unsigned)a2 | ((unsigned)b2 << 16),
                       (unsigned)c2 | ((unsigned)d2 << 16));
    }
}

// =====================================================================
// qkv GEMM (verbatim from the 263.9us run): 128x128 tile, 3-stage ring.
// =====================================================================
#define QKV_LOAD_A(K0)                                                        \
    do {                                                                      \
        if (which != 2) {                                                     \
            const float4* ap = (const float4*)(A + (size_t)(m0 + arow) * DD + (K0) + akh); \
            float4 x0 = ap[0], x1 = ap[1], x2 = ap[2], x3 = ap[3];            \
            pv0=x0.x; pv1=x0.y; pv2=x0.z; pv3=x0.w;                           \
            pv4=x1.x; pv5=x1.y; pv6=x1.z; pv7=x1.w;                           \
            pv8=x2.x; pv9=x2.y; pva=x2.z; pvb=x2.w;                           \
            pvc=x3.x; pvd=x3.y; pve=x3.z; pvf=x3.w;                           \
        } else {                                                              \
            const float* ar = A + (size_t)(m0 + arow) * KA;                   \
            int kb = (K0) + akh;                                              \
            pv0 = (kb+0 < KA) ? ar[kb+0] : 0.f;  pv1 = (kb+1 < KA) ? ar[kb+1] : 0.f; \
            pv2 = (kb+2 < KA) ? ar[kb+2] : 0.f;  pv3 = (kb+3 < KA) ? ar[kb+3] : 0.f; \
            pv4 = (kb+4 < KA) ? ar[kb+4] : 0.f;  pv5 = (kb+5 < KA) ? ar[kb+5] : 0.f; \
            pv6 = (kb+6 < KA) ? ar[kb+6] : 0.f;  pv7 = (kb+7 < KA) ? ar[kb+7] : 0.f; \
            pv8 = (kb+8 < KA) ? ar[kb+8] : 0.f;  pv9 = (kb+9 < KA) ? ar[kb+9] : 0.f; \
            pva = (kb+10 < KA) ? ar[kb+10] : 0.f; pvb = (kb+11 < KA) ? ar[kb+11] : 0.f; \
            pvc = (kb+12 < KA) ? ar[kb+12] : 0.f; pvd = (kb+13 < KA) ? ar[kb+13] : 0.f; \
            pve = (kb+14 < KA) ? ar[kb+14] : 0.f; pvf = (kb+15 < KA) ? ar[kb+15] : 0.f; \
        }                                                                     \
    } while (0)

#define SPLITPAIR(I, VA, VB)                                                  \
    do {                                                                      \
        float ra_ = (VA), rb_ = (VB);                                         \
        p0_[I] = prmt7632(__float_as_uint(ra_), __float_as_uint(rb_));        \
        ra_ -= trunchi(ra_); rb_ -= trunchi(rb_);                             \
        p1_[I] = prmt7632(__float_as_uint(ra_), __float_as_uint(rb_));        \
        ra_ -= trunchi(ra_); rb_ -= trunchi(rb_);                             \
        p2_[I] = prmt7632(__float_as_uint(ra_), __float_as_uint(rb_));        \
    } while (0)

#define QKV_STSA(STG)                                                         \
    do {                                                                      \
        char* bufc = smemraw + (size_t)(STG) * QSTG;                          \
        unsigned p0_[8], p1_[8], p2_[8];                                      \
        SPLITPAIR(0, pv0, pv1); SPLITPAIR(1, pv2, pv3);                       \
        SPLITPAIR(2, pv4, pv5); SPLITPAIR(3, pv6, pv7);                       \
        SPLITPAIR(4, pv8, pv9); SPLITPAIR(5, pva, pvb);                       \
        SPLITPAIR(6, pvc, pvd); SPLITPAIR(7, pve, pvf);                       \
        unsigned aoff = (unsigned)(arow * 64 + akh * 2);                      \
        unsigned alo = SW64OFF(aoff), ahi = SW64OFF(aoff + 16);               \
        *(uint4*)(bufc + alo)         = make_uint4(p0_[0], p0_[1], p0_[2], p0_[3]); \
        *(uint4*)(bufc + ahi)         = make_uint4(p0_[4], p0_[5], p0_[6], p0_[7]); \
        *(uint4*)(bufc + 8192 + alo)  = make_uint4(p1_[0], p1_[1], p1_[2], p1_[3]); \
        *(uint4*)(bufc + 8192 + ahi)  = make_uint4(p1_[4], p1_[5], p1_[6], p1_[7]); \
        *(uint4*)(bufc + 16384 + alo) = make_uint4(p2_[0], p2_[1], p2_[2], p2_[3]); \
        *(uint4*)(bufc + 16384 + ahi) = make_uint4(p2_[4], p2_[5], p2_[6], p2_[7]); \
    } while (0)

#define QKV_CPW(CH, STG)                                                      \
    do {                                                                      \
        unsigned wb = sb + (unsigned)((STG) * QSTG + 24576);                  \
        const int kk0 = (CH) << 5;                                            \
        _Pragma("unroll")                                                     \
        for (int i_ = 0; i_ < 6; i_++) {                                      \
            int u_ = tid + 256 * i_;                                          \
            int sp_ = u_ >> 9, row_ = (u_ >> 2) & 127, c_ = u_ & 3;           \
            unsigned d_ = wb + sp_ * 8192 +                                   \
                          SW64OFF((unsigned)(row_ * 64 + c_ * 16));           \
            cpa16(d_, gW + ((size_t)sp_ * 512 + n0 + row_) * 512 + kk0 + c_ * 8); \
        }                                                                     \
        CP_COMMIT();                                                          \
    } while (0)

__global__ __launch_bounds__(256, 1) void qkv_mma_kernel(
    const float* __restrict__ Aq, const float* __restrict__ Ak,
    const float* __restrict__ Av,
    const float* __restrict__ bq, const float* __restrict__ bk,
    const float* __restrict__ bv, int DIN)
{
    extern __shared__ char smemraw[];   // 3 x QSTG

    const int tid  = threadIdx.x;
    const int lane = tid & 31;
    const int g    = lane >> 2, tg = lane & 3;
    const int wrp  = tid >> 5;
    const int mw   = wrp >> 1, nw = wrp & 1;

    int idx = blockIdx.x;
    int which = idx >> 8;                      // 0=k,1=v,2=q
    int s2 = idx & 255;
    int n0 = (s2 & 3) * 128, m0 = (s2 >> 2) * 128;

    const float* A    = (which == 0) ? Ak : (which == 1) ? Av : Aq;
    const float* bias = (which == 0) ? bk : (which == 1) ? bv : bq;
    const int KA = DIN;
    const int KS = (which == 2) ? 128 : DD;
    const int wsel = (which == 0) ? 1 : (which == 1) ? 2 : 0;
    const unsigned short* gW = g_wsp + (size_t)wsel * 3 * 512 * 512;

    const unsigned sb = (unsigned)__cvta_generic_to_shared(smemraw);

    float C[2][8][4];
#pragma unroll
    for (int mt = 0; mt < 2; mt++)
#pragma unroll
        for (int nt = 0; nt < 8; nt++)
#pragma unroll
            for (int r = 0; r < 4; r++) C[mt][nt][r] = 0.f;

    const int arow = tid >> 1, akh = (tid & 1) * 16;
    const int arow_l = lane & 15;
    const int ak16b = (lane >> 4) * 16;
    const int brow = (lane & 7) + ((lane & 16) >> 1);
    const int bk16b = (lane & 8) * 2;

    float pv0,pv1,pv2,pv3,pv4,pv5,pv6,pv7,pv8,pv9,pva,pvb,pvc,pvd,pve,pvf;

    const int nch = KS >> 5;

    QKV_LOAD_A(0);
    QKV_CPW(0, 0);
    QKV_STSA(0);
    if (nch > 1) {
        QKV_LOAD_A(32);
        QKV_CPW(1, 1);
        QKV_STSA(1);
    }
    if (nch > 2) QKV_LOAD_A(64);

    for (int ch = 0; ch < nch; ++ch) {
        const int stg = ch % 3;
        if (ch + 1 < nch) { CP_WAIT(1); } else { CP_WAIT(0); }
        __syncthreads();
        if (ch + 2 < nch) {
            QKV_CPW(ch + 2, (ch + 2) % 3);
            QKV_STSA((ch + 2) % 3);
            if (ch + 3 < nch) QKV_LOAD_A((ch + 3) << 5);
        }
        const unsigned abuf = sb + (unsigned)(stg * QSTG);
        const unsigned wbuf = abuf + 24576;
#pragma unroll
        for (int s = 0; s < 2; ++s) {
            unsigned af[3][2][4];
#pragma unroll
            for (int sp = 0; sp < 3; sp++)
#pragma unroll
                for (int mt = 0; mt < 2; mt++) {
                    unsigned a = abuf + sp * 8192 +
                        SW64OFF((unsigned)((mw * 32 + mt * 16 + arow_l) * 64 +
                                           s * 32 + ak16b));
                    ldsm4(af[sp][mt][0], af[sp][mt][1], af[sp][mt][2], af[sp][mt][3], a);
                }
#pragma unroll
            for (int j = 0; j < 3; j++) {
                unsigned bfr[4][4];
#pragma unroll
                for (int np = 0; np < 4; np++) {
                    unsigned a = wbuf + j * 8192 +
                        SW64OFF((unsigned)((nw * 64 + np * 16 + brow) * 64 +
                                           s * 32 + bk16b));
                    ldsm4(bfr[np][0], bfr[np][1], bfr[np][2], bfr[np][3], a);
                }
#pragma unroll
                for (int i = 0; i < 3; i++) {
                    if (i + j > 2) break;
#pragma unroll
                    for (int mt = 0; mt < 2; mt++)
#pragma unroll
                        for (int np = 0; np < 4; np++) {
                            mma_bf16(C[mt][np * 2], af[i][mt][0], af[i][mt][1],
                                     af[i][mt][2], af[i][mt][3],
                                     bfr[np][0], bfr[np][1]);
                            mma_bf16(C[mt][np * 2 + 1], af[i][mt][0], af[i][mt][1],
                                     af[i][mt][2], af[i][mt][3],
                                     bfr[np][2], bfr[np][3]);
                        }
                }
            }
        }
    }

    __syncthreads();
    unsigned char* sbyte = (unsigned char*)smemraw;   // [128][128]
#pragma unroll
    for (int mt = 0; mt < 2; mt++)
#pragma unroll
        for (int nt = 0; nt < 8; nt++) {
            int row = mw * 32 + mt * 16 + g;
            int col = nw * 64 + nt * 8 + tg * 2;
            float2 bb = *(const float2*)&bias[n0 + col];
            sbyte[row * 128 + col]           = (C[mt][nt][0] + bb.x >= 1.0f) ? 1 : 0;
            sbyte[row * 128 + col + 1]       = (C[mt][nt][1] + bb.y >= 1.0f) ? 1 : 0;
            sbyte[(row + 8) * 128 + col]     = (C[mt][nt][2] + bb.x >= 1.0f) ? 1 : 0;
            sbyte[(row + 8) * 128 + col + 1] = (C[mt][nt][3] + bb.y >= 1.0f) ? 1 : 0;
        }
    __syncthreads();
    {
        int row = tid >> 1, hf = tid & 1;
        unsigned long long bits = 0ull;
#pragma unroll
        for (int q = 0; q < 8; q++) {
            unsigned long long u =
                *(const unsigned long long*)&sbyte[row * 128 + hf * 64 + 8 * q];
#pragma unroll
            for (int j = 0; j < 8; j++)
                bits |= ((u >> (8 * j)) & 1ull) << (8 * q + j);
        }
        int m = m0 + row;
        int b = m >> 11, t = m & 2047;
        int head = (n0 >> 6) + hf;
        unsigned long long* dst = (which == 2) ? g_qb : (which == 0) ? g_kb : g_vb;
        dst[(size_t)((b << 3) + head) * TT + t] = bits;
    }
}

// =====================================================================
// Fused bit-transpose + KV precompute: block (bh, w), 128 threads.
// Warps 0-1 transpose v rows, warps 2-3 transpose k rows; then all
// compute KV[d][j] via IMMA from smem. Same math as before.
// =====================================================================
__global__ __launch_bounds__(128) void transkv_kernel()
{
    __shared__ unsigned sh[2][64][2];
    __shared__ unsigned long long vTs[64], kTs[64];

    const int tid = threadIdx.x;
    const int lane = tid & 31;
    int bh = blockIdx.x >> 5, w = blockIdx.x & 31;

    // ---- transpose phase ----
    {
        int which = tid >> 6;               // 0=v, 1=k
        int r = tid & 63;
        int half = (tid >> 5) & 1;
        const unsigned long long* src = which ? g_kb : g_vb;
        unsigned long long row = src[(size_t)bh * TT + w * 64 + r];
#pragma unroll 8
        for (int d = 0; d < 64; d++) {
            unsigned b = __ballot_sync(0xffffffffu, (unsigned)((row >> d) & 1ull));
            if (lane == 0) sh[which][d][half] = b;
        }
        __syncthreads();
        unsigned long long val = (unsigned long long)sh[which][r][0] |
                                 ((unsigned long long)sh[which][r][1] << 32);
        if (which == 0) {
            vTs[r] = val;
            g_vT[((size_t)bh * 64 + r) * 32 + w] = val;
        } else {
            kTs[r] = val;
        }
    }
    __syncthreads();

    // ---- KV product phase (identical math to old kvprod) ----
    const int g = lane >> 2, tg = lane & 3;
    const int wr16 = (tid >> 5) * 16;

    unsigned long long vd0 = vTs[wr16 + g];
    unsigned long long vd1 = vTs[wr16 + 8 + g];
    unsigned long long kt[8];
#pragma unroll
    for (int nt = 0; nt < 8; nt++) kt[nt] = kTs[nt * 8 + g];

    int acc[8][4];
#pragma unroll
    for (int nt = 0; nt < 8; nt++)
#pragma unroll
        for (int r = 0; r < 4; r++) acc[nt][r] = 0;

#pragma unroll
    for (int s = 0; s < 2; s++) {
        unsigned l0 = (unsigned)(vd0 >> (32 * s));
        unsigned l1 = (unsigned)(vd1 >> (32 * s));
        unsigned a0 = expand4((l0 >> (4 * tg)) & 0xFu);
        unsigned a1 = expand4((l1 >> (4 * tg)) & 0xFu);
        unsigned a2 = expand4((l0 >> (16 + 4 * tg)) & 0xFu);
        unsigned a3 = expand4((l1 >> (16 + 4 * tg)) & 0xFu);
#pragma unroll
        for (int nt = 0; nt < 8; nt++) {
            unsigned kl = (unsigned)(kt[nt] >> (32 * s));
            unsigned b0 = expand4((kl >> (4 * tg)) & 0xFu);
            unsigned b1 = expand4((kl >> (16 + 4 * tg)) & 0xFu);
            mma_s8(acc[nt], a0, a1, a2, a3, b0, b1);
        }
    }

    unsigned char* dst = g_kv + ((size_t)(bh * 32 + w) * 64) * 64;
#pragma unroll
    for (int nt = 0; nt < 8; nt++) {
        int j0 = nt * 8 + 2 * tg;
        *(unsigned short*)(dst + (wr16 + g) * 64 + j0) =
            (unsigned short)((acc[nt][0] & 0xFF) | ((acc[nt][1] & 0xFF) << 8));
        *(unsigned short*)(dst + (wr16 + 8 + g) * 64 + j0) =
            (unsigned short)((acc[nt][2] & 0xFF) | ((acc[nt][3] & 0xFF) << 8));
    }
}

// =====================================================================
// Attention (unchanged from 263.9us run).
// =====================================================================
__global__ __launch_bounds__(128) void attn_kernel(const float* __restrict__ scale_p)
{
    __shared__ __align__(16) unsigned char KVsh[2][64 * 80];
    __shared__ unsigned char csh[64 * 68];
    __shared__ unsigned long long ksh[64];

    const int tid = threadIdx.x;
    const int lane = tid & 31;
    const int g = lane >> 2, tg = lane & 3;
    const int wr16 = (tid >> 5) * 16;
    const int rowA = wr16 + g;

    int bx = blockIdx.x;
    int bh = bx & 31;
    int tq = 31 - (bx >> 5);

    const float scale = *scale_p;
    const size_t base = (size_t)bh * TT;
    const unsigned char* KVg = g_kv + (size_t)bh * 32 * 64 * 64;

    unsigned long long q0 = g_qb[base + (size_t)tq * 64 + rowA];
    unsigned long long q1 = g_qb[base + (size_t)tq * 64 + rowA + 8];
    unsigned qa[2][4];
#pragma unroll
    for (int s = 0; s < 2; s++) {
        unsigned l0 = (unsigned)(q0 >> (32 * s));
        unsigned l1 = (unsigned)(q1 >> (32 * s));
        qa[s][0] = expand4((l0 >> (4 * tg)) & 0xFu);
        qa[s][1] = expand4((l1 >> (4 * tg)) & 0xFu);
        qa[s][2] = expand4((l0 >> (16 + 4 * tg)) & 0xFu);
        qa[s][3] = expand4((l1 >> (16 + 4 * tg)) & 0xFu);
    }

    int acc[8][4];
#pragma unroll
    for (int nt = 0; nt < 8; nt++)
#pragma unroll
        for (int r = 0; r < 4; r++) acc[nt][r] = 0;

    const int kvrow0 = tid >> 2, kvp0 = tid & 3;
    const int kvrow1 = (tid + 128) >> 2, kvp1 = tid & 3;
    const unsigned kvb0 = (unsigned)__cvta_generic_to_shared(&KVsh[0][0]);
    const unsigned kvb1 = (unsigned)__cvta_generic_to_shared(&KVsh[1][0]);

    if (tq > 0) {
        cpa16(kvb0 + kvrow0 * 80 + kvp0 * 16, KVg + 0 * 4096 + kvrow0 * 64 + kvp0 * 16);
        cpa16(kvb0 + kvrow1 * 80 + kvp1 * 16, KVg + 0 * 4096 + kvrow1 * 64 + kvp1 * 16);
        CP_COMMIT();
    }
    for (int w = 0; w < tq; ++w) {
        __syncthreads();
        if (w + 1 < tq) {
            unsigned kb = ((w + 1) & 1) ? kvb1 : kvb0;
            const unsigned char* src = KVg + (size_t)(w + 1) * 4096;
            cpa16(kb + kvrow0 * 80 + kvp0 * 16, src + kvrow0 * 64 + kvp0 * 16);
            cpa16(kb + kvrow1 * 80 + kvp1 * 16, src + kvrow1 * 64 + kvp1 * 16);
            CP_COMMIT();
            CP_WAIT(1);
        } else {
            CP_WAIT(0);
        }
        __syncthreads();
        const unsigned char* kb = KVsh[w & 1];
#pragma unroll
        for (int s = 0; s < 2; s++)
#pragma unroll
            for (int nt = 0; nt < 8; nt++) {
                unsigned b0 = *(const unsigned*)(kb + (nt * 8 + g) * 80 + s * 32 + tg * 4);
                unsigned b1 = *(const unsigned*)(kb + (nt * 8 + g) * 80 + s * 32 + 16 + tg * 4);
                mma_s8(acc[nt], qa[s][0], qa[s][1], qa[s][2], qa[s][3], b0, b1);
            }
    }

    if (tid < 64) ksh[tid] = g_kb[base + (size_t)tq * 64 + tid];
    unsigned long long vt[8];
#pragma unroll
    for (int nt = 0; nt < 8; nt++)
        vt[nt] = g_vT[((size_t)bh * 64 + nt * 8 + g) * 32 + tq];
    __syncthreads();

    {
        unsigned long long kk[8];
#pragma unroll
        for (int nt = 0; nt < 8; nt++) kk[nt] = ksh[nt * 8 + g];
        int qcc[8][4];
#pragma unroll
        for (int nt = 0; nt < 8; nt++)
#pragma unroll
            for (int r = 0; r < 4; r++) qcc[nt][r] = 0;
#pragma unroll
        for (int s = 0; s < 2; s++)
#pragma unroll
            for (int nt = 0; nt < 8; nt++) {
                unsigned kl = (unsigned)(kk[nt] >> (32 * s));
                unsigned b0 = expand4((kl >> (4 * tg)) & 0xFu);
                unsigned b1 = expand4((kl >> (16 + 4 * tg)) & 0xFu);
                mma_s8(qcc[nt], qa[s][0], qa[s][1], qa[s][2], qa[s][3], b0, b1);
            }
        int t0 = rowA, t1 = rowA + 8;
#pragma unroll
        for (int nt = 0; nt < 8; nt++) {
            int kc = nt * 8 + 2 * tg;
            unsigned v00 = (kc <= t0) ? (qcc[nt][0] & 0xFF) : 0u;
            unsigned v01 = (kc + 1 <= t0) ? (qcc[nt][1] & 0xFF) : 0u;
            unsigned v10 = (kc <= t1) ? (qcc[nt][2] & 0xFF) : 0u;
            unsigned v11 = (kc + 1 <= t1) ? (qcc[nt][3] & 0xFF) : 0u;
            *(unsigned short*)&csh[t0 * 68 + kc] = (unsigned short)(v00 | (v01 << 8));
            *(unsigned short*)&csh[t1 * 68 + kc] = (unsigned short)(v10 | (v11 << 8));
        }
        __syncwarp();
#pragma unroll
        for (int s = 0; s < 2; s++) {
            unsigned a0 = *(const unsigned*)&csh[rowA * 68 + s * 32 + tg * 4];
            unsigned a1 = *(const unsigned*)&csh[(rowA + 8) * 68 + s * 32 + tg * 4];
            unsigned a2 = *(const unsigned*)&csh[rowA * 68 + s * 32 + 16 + tg * 4];
            unsigned a3 = *(const unsigned*)&csh[(rowA + 8) * 68 + s * 32 + 16 + tg * 4];
#pragma unroll
            for (int nt = 0; nt < 8; nt++) {
                unsigned b0 = expand4((unsigned)(vt[nt] >> (s * 32 + tg * 4)) & 0xFu);
                unsigned b1 = expand4((unsigned)(vt[nt] >> (s * 32 + 16 + tg * 4)) & 0xFu);
                mma_s8(acc[nt], a0, a1, a2, a3, b0, b1);
            }
        }
    }

    __syncthreads();
#pragma unroll
    for (int nt = 0; nt < 8; ++nt) {
        int d0 = nt * 8 + tg * 2;
        csh[d0 * 68 + rowA]           = ((float)acc[nt][0] * scale >= 1.0f) ? 1 : 0;
        csh[(d0 + 1) * 68 + rowA]     = ((float)acc[nt][1] * scale >= 1.0f) ? 1 : 0;
        csh[d0 * 68 + rowA + 8]       = ((float)acc[nt][2] * scale >= 1.0f) ? 1 : 0;
        csh[(d0 + 1) * 68 + rowA + 8] = ((float)acc[nt][3] * scale >= 1.0f) ? 1 : 0;
    }
    __syncthreads();
    {
        int d = tid >> 1, hf = tid & 1;
        size_t b = (size_t)(bh >> 3), h = (size_t)(bh & 7);
        size_t off = (b << 20) + (h << 17) + ((size_t)d << 11)
                   + (size_t)tq * 64 + (size_t)hf * 32;
#pragma unroll
        for (int q4 = 0; q4 < 32; q4 += 4) {
            unsigned v = *(const unsigned*)&csh[d * 68 + hf * 32 + q4];
            *(unsigned*)(g_xs + off + q4) = v;
        }
    }
}

// =====================================================================
// Output projection: 128m x 128n tile, 3-stage SW64 ring, cp.async W.
// A binary (1 plane) x W 3-split; per-output op order unchanged.
// =====================================================================
#define OUT_LOAD_A(K0)                                                        \
    do {                                                                      \
        pa = *(const uint4*)(g_xs + (size_t)(m0 + xrow) * DD + (K0) + xhalf * 16); \
    } while (0)

#define OUT_STSA(STG)                                                         \
    do {                                                                      \
        char* bufc = smemraw + (size_t)(STG) * OSTG;                          \
        unsigned w0 = pa.x, w1 = pa.y, w2 = pa.z, w3 = pa.w;                  \
        uint4 o0, o1;                                                         \
        o0.x = ((w0 & 1u) ? 0x3F80u : 0u) | ((w0 & 0x100u) ? 0x3F800000u : 0u); \
        o0.y = (((w0 >> 16) & 1u) ? 0x3F80u : 0u) | ((w0 & 0x1000000u) ? 0x3F800000u : 0u); \
        o0.z = ((w1 & 1u) ? 0x3F80u : 0u) | ((w1 & 0x100u) ? 0x3F800000u : 0u); \
        o0.w = (((w1 >> 16) & 1u) ? 0x3F80u : 0u) | ((w1 & 0x1000000u) ? 0x3F800000u : 0u); \
        o1.x = ((w2 & 1u) ? 0x3F80u : 0u) | ((w2 & 0x100u) ? 0x3F800000u : 0u); \
        o1.y = (((w2 >> 16) & 1u) ? 0x3F80u : 0u) | ((w2 & 0x1000000u) ? 0x3F800000u : 0u); \
        o1.z = ((w3 & 1u) ? 0x3F80u : 0u) | ((w3 & 0x100u) ? 0x3F800000u : 0u); \
        o1.w = (((w3 >> 16) & 1u) ? 0x3F80u : 0u) | ((w3 & 0x1000000u) ? 0x3F800000u : 0u); \
        unsigned base_ = (unsigned)(xrow * 64 + xhalf * 32);                  \
        *(uint4*)(bufc + SW64OFF(base_))      = o0;                           \
        *(uint4*)(bufc + SW64OFF(base_ + 16)) = o1;                           \
    } while (0)

#define OUT_CPW(CH, STG)                                                      \
    do {                                                                      \
        unsigned wb = sb + (unsigned)((STG) * OSTG + 8192);                   \
        const int kk0 = (CH) << 5;                                            \
        _Pragma("unroll")                                                     \
        for (int i_ = 0; i_ < 6; i_++) {                                      \
            int u_ = tid + 256 * i_;                                          \
            int sp_ = u_ >> 9, row_ = (u_ >> 2) & 127, c_ = u_ & 3;           \
            unsigned d_ = wb + sp_ * 8192 +                                   \
                          SW64OFF((unsigned)(row_ * 64 + c_ * 16));           \
            cpa16(d_, gW + ((size_t)sp_ * 512 + n0 + row_) * 512 + kk0 + c_ * 8); \
        }                                                                     \
        CP_COMMIT();                                                          \
    } while (0)

__global__ __launch_bounds__(256, 1) void out_mma_kernel(
    const float* __restrict__ bias, float* __restrict__ out)
{
    extern __shared__ char smemraw[];   // 3 x OSTG

    const int tid  = threadIdx.x;
    const int lane = tid & 31;
    const int g    = lane >> 2, tg = lane & 3;
    const int wrp  = tid >> 5;
    const int mw   = wrp >> 1, nw = wrp & 1;

    int s2 = blockIdx.x;
    int n0 = (s2 & 3) * 128, m0 = (s2 >> 2) * 128;

    const unsigned short* gW = g_wsp + (size_t)3 * 3 * 512 * 512;   // Wo
    const unsigned sb = (unsigned)__cvta_generic_to_shared(smemraw);

    float C[2][8][4];
#pragma unroll
    for (int mt = 0; mt < 2; mt++)
#pragma unroll
        for (int nt = 0; nt < 8; nt++)
#pragma unroll
            for (int r = 0; r < 4; r++) C[mt][nt][r] = 0.f;

    const int xrow = tid >> 1, xhalf = tid & 1;
    const int arow_l = lane & 15;
    const int ak16b = (lane >> 4) * 16;
    const int brow = (lane & 7) + ((lane & 16) >> 1);
    const int bk16b = (lane & 8) * 2;

    uint4 pa;

    OUT_LOAD_A(0);
    OUT_CPW(0, 0);
    OUT_STSA(0);
    OUT_LOAD_A(32);
    OUT_CPW(1, 1);
    OUT_STSA(1);
    OUT_LOAD_A(64);

    for (int ch = 0; ch < 16; ++ch) {
        const int stg = ch % 3;
        if (ch + 1 < 16) { CP_WAIT(1); } else { CP_WAIT(0); }
        __syncthreads();
        if (ch + 2 < 16) {
            OUT_CPW(ch + 2, (ch + 2) % 3);
            OUT_STSA((ch + 2) % 3);
            if (ch + 3 < 16) OUT_LOAD_A((ch + 3) << 5);
        }
        const unsigned abuf = sb + (unsigned)(stg * OSTG);
        const unsigned wbuf = abuf + 8192;
#pragma unroll
        for (int s = 0; s < 2; ++s) {
            unsigned af[2][4];
#pragma unroll
            for (int mt = 0; mt < 2; mt++) {
                unsigned a = abuf +
                    SW64OFF((unsigned)((mw * 32 + mt * 16 + arow_l) * 64 +
                                       s * 32 + ak16b));
                ldsm4(af[mt][0], af[mt][1], af[mt][2], af[mt][3], a);
            }
#pragma unroll
            for (int j = 0; j < 3; j++) {
                unsigned bfr[4][4];
#pragma unroll
                for (int np = 0; np < 4; np++) {
                    unsigned a = wbuf + j * 8192 +
                        SW64OFF((unsigned)((nw * 64 + np * 16 + brow) * 64 +
                                           s * 32 + bk16b));
                    ldsm4(bfr[np][0], bfr[np][1], bfr[np][2], bfr[np][3], a);
                }
#pragma unroll
                for (int mt = 0; mt < 2; mt++)
#pragma unroll
                    for (int np = 0; np < 4; np++) {
                        mma_bf16(C[mt][np * 2], af[mt][0], af[mt][1], af[mt][2],
                                 af[mt][3], bfr[np][0], bfr[np][1]);
                        mma_bf16(C[mt][np * 2 + 1], af[mt][0], af[mt][1], af[mt][2],
                                 af[mt][3], bfr[np][2], bfr[np][3]);
                    }
            }
        }
    }

    // ---- epilogue: bias + spike -> fp32 out ----
#pragma unroll
    for (int mt = 0; mt < 2; mt++)
#pragma unroll
        for (int nt = 0; nt < 8; nt++) {
            int row = m0 + mw * 32 + mt * 16 + g;
            int col = n0 + nw * 64 + nt * 8 + tg * 2;
            float2 bb = *(const float2*)&bias[col];
            float2 r0, r1;
            r0.x = (C[mt][nt][0] + bb.x >= 1.0f) ? 1.0f : 0.0f;
            r0.y = (C[mt][nt][1] + bb.y >= 1.0f) ? 1.0f : 0.0f;
            r1.x = (C[mt][nt][2] + bb.x >= 1.0f) ? 1.0f : 0.0f;
            r1.y = (C[mt][nt][3] + bb.y >= 1.0f) ? 1.0f : 0.0f;
            *(float2*)&out[(size_t)row * DD + col] = r0;
            *(float2*)&out[(size_t)(row + 8) * DD + col] = r1;
        }
}

// ---------------- launch ----------------
extern "C" void kernel_launch(void* const* d_in, const int* in_sizes, int n_in,
                              void* d_out, int out_size)
{
    const float* query = (const float*)d_in[0];
    const float* key   = (const float*)d_in[1];
    const float* value = (const float*)d_in[2];
    const float* scale = (const float*)d_in[3];
    const float* Wq = (const float*)d_in[4];  const float* bq = (const float*)d_in[5];
    const float* Wk = (const float*)d_in[6];  const float* bk = (const float*)d_in[7];
    const float* Wv = (const float*)d_in[8];  const float* bv = (const float*)d_in[9];
    const float* Wo = (const float*)d_in[10]; const float* bo = (const float*)d_in[11];
    float* out = (float*)d_out;

    const int DIN = in_sizes[0] / MROWS;   // 100

    cudaFuncSetAttribute(qkv_mma_kernel,
                         cudaFuncAttributeMaxDynamicSharedMemorySize, QKV_SMEM);
    cudaFuncSetAttribute(out_mma_kernel,
                         cudaFuncAttributeMaxDynamicSharedMemorySize, OUT_SMEM);

    prep_w_kernel<<<dim3(8, 8, 4), 256>>>(Wq, Wk, Wv, Wo);
    qkv_mma_kernel<<<768, 256, QKV_SMEM>>>(query, key, value, bq, bk, bv, DIN);
    transkv_kernel<<<BHN * NTW, 128>>>();
    attn_kernel<<<BHN * NTW, 128>>>(scale);
    out_mma_kernel<<<256, 256, OUT_SMEM>>>(bo, out);
}

// round 17
// speedup vs baseline: 2.0437x; 1.0125x over previous
#include <cuda_runtime.h>
#include <cstdint>

#define BB 4
#define TT 2048
#define DD 512
#define HH 8
#define DK 64
#define BHN (BB*HH)          // 32
#define NTW (TT/64)          // 32 k-tiles
#define MROWS (BB*TT)        // 8192
#define QSTG 49152           // qkv stage: A 3x8192 + W 3x8192
#define QKV_SMEM (3*QSTG)    // 144 KB
#define OSTG 32768           // out stage: A 8192 + W 3x8192
#define OUT_SMEM (3*OSTG)    // 96 KB

// ---------------- scratch ----------------
__device__ unsigned long long g_qb[BHN*TT];
__device__ unsigned long long g_kb[BHN*TT];
__device__ unsigned long long g_vb[BHN*TT];
__device__ unsigned long long g_vT[BHN*DK*NTW];      // [bh][d][w]
__device__ unsigned char      g_xs[BB*TT*DD];
__device__ unsigned short     g_wsp[4*3*512*512];    // pre-split W (6 MB)
__device__ unsigned char      g_kv[BHN*NTW*64*64];   // KV tiles s8 (4 MB)

// ---------------- helpers ----------------
__device__ __forceinline__ unsigned expand4(unsigned x) {
    return (x * 0x00204081u) & 0x01010101u;
}
__device__ __forceinline__ void mma_s8(int* c, unsigned a0, unsigned a1, unsigned a2,
                                       unsigned a3, unsigned b0, unsigned b1) {
    asm volatile(
        "mma.sync.aligned.m16n8k32.row.col.s32.s8.s8.s32 "
        "{%0,%1,%2,%3}, {%4,%5,%6,%7}, {%8,%9}, {%0,%1,%2,%3};"
        : "+r"(c[0]), "+r"(c[1]), "+r"(c[2]), "+r"(c[3])
        : "r"(a0), "r"(a1), "r"(a2), "r"(a3), "r"(b0), "r"(b1));
}
__device__ __forceinline__ void mma_bf16(float* c, unsigned a0, unsigned a1,
                                         unsigned a2, unsigned a3,
                                         unsigned b0, unsigned b1) {
    asm volatile(
        "mma.sync.aligned.m16n8k16.row.col.f32.bf16.bf16.f32 "
        "{%0,%1,%2,%3}, {%4,%5,%6,%7}, {%8,%9}, {%0,%1,%2,%3};"
        : "+f"(c[0]), "+f"(c[1]), "+f"(c[2]), "+f"(c[3])
        : "r"(a0), "r"(a1), "r"(a2), "r"(a3), "r"(b0), "r"(b1));
}
__device__ __forceinline__ void split3(float a, unsigned short& s0,
                                       unsigned short& s1, unsigned short& s2) {
    unsigned u0 = __float_as_uint(a);
    s0 = (unsigned short)(u0 >> 16);
    float r1 = a - __uint_as_float(u0 & 0xFFFF0000u);
    unsigned u1 = __float_as_uint(r1);
    s1 = (unsigned short)(u1 >> 16);
    float r2 = r1 - __uint_as_float(u1 & 0xFFFF0000u);
    s2 = (unsigned short)(__float_as_uint(r2) >> 16);
}
__device__ __forceinline__ unsigned prmt7632(unsigned a, unsigned b) {
    unsigned r;
    asm("prmt.b32 %0, %1, %2, 0x7632;" : "=r"(r) : "r"(a), "r"(b));
    return r;
}
__device__ __forceinline__ float trunchi(float a) {
    return __uint_as_float(__float_as_uint(a) & 0xFFFF0000u);
}
__device__ __forceinline__ void ldsm4(unsigned& r0, unsigned& r1, unsigned& r2,
                                      unsigned& r3, unsigned addr) {
    asm volatile("ldmatrix.sync.aligned.m8n8.x4.shared.b16 {%0,%1,%2,%3}, [%4];"
                 : "=r"(r0), "=r"(r1), "=r"(r2), "=r"(r3) : "r"(addr));
}
__device__ __forceinline__ void cpa16(unsigned dst, const void* src) {
    asm volatile("cp.async.cg.shared.global [%0], [%1], 16;" :: "r"(dst), "l"(src));
}
#define CP_COMMIT() asm volatile("cp.async.commit_group;")
#define CP_WAIT(n)  asm volatile("cp.async.wait_group %0;" :: "n"(n) : "memory")
#define SW64OFF(x) ((x) ^ (((x) >> 3) & 0x30))

// =====================================================================
// prep: split W (transposed to [n][k]) into g_wsp.
// =====================================================================
__global__ void prep_w_kernel(const float* __restrict__ Wq, const float* __restrict__ Wk,
                              const float* __restrict__ Wv, const float* __restrict__ Wo)
{
    __shared__ float sh[64][68];
    int w = blockIdx.z;
    const float* W = (w == 0) ? Wq : (w == 1) ? Wk : (w == 2) ? Wv : Wo;
    int k0 = blockIdx.x * 64, n0 = blockIdx.y * 64;
    int t = threadIdx.x;
#pragma unroll
    for (int r = 0; r < 4; r++) {
        int row = (t >> 4) * 4 + r;
        int col = (t & 15) * 4;
        float4 v = *(const float4*)&W[(size_t)(k0 + row) * DD + n0 + col];
        sh[row][col] = v.x; sh[row][col+1] = v.y; sh[row][col+2] = v.z; sh[row][col+3] = v.w;
    }
    __syncthreads();
#pragma unroll
    for (int r = 0; r < 4; r++) {
        int n = (t >> 4) * 4 + r;
        int k4 = (t & 15) * 4;
        unsigned short a0, a1, a2, b0, b1, b2, c0, c1, c2, d0, d1, d2;
        split3(sh[k4 + 0][n], a0, a1, a2);
        split3(sh[k4 + 1][n], b0, b1, b2);
        split3(sh[k4 + 2][n], c0, c1, c2);
        split3(sh[k4 + 3][n], d0, d1, d2);
        size_t base = ((size_t)(w * 3) * 512 + (n0 + n)) * 512 + k0 + k4;
        const size_t P = (size_t)512 * 512;
        *(uint2*)&g_wsp[base] =
            make_uint2((unsigned)a0 | ((unsigned)b0 << 16),
                       (unsigned)c0 | ((unsigned)d0 << 16));
        *(uint2*)&g_wsp[base + P] =
            make_uint2((unsigned)a1 | ((unsigned)b1 << 16),
                       (unsigned)c1 | ((unsigned)d1 << 16));
        *(uint2*)&g_wsp[base + 2 * P] =
            make_uint2((unsigned)a2 | ((unsigned)b2 << 16),
                       (unsigned)c2 | ((unsigned)d2 << 16));
    }
}

// =====================================================================
// qkv GEMM (verbatim from the 260.1us run).
// =====================================================================
#define QKV_LOAD_A(K0)                                                        \
    do {                                                                      \
        if (which != 2) {                                                     \
            const float4* ap = (const float4*)(A + (size_t)(m0 + arow) * DD + (K0) + akh); \
            float4 x0 = ap[0], x1 = ap[1], x2 = ap[2], x3 = ap[3];            \
            pv0=x0.x; pv1=x0.y; pv2=x0.z; pv3=x0.w;                           \
            pv4=x1.x; pv5=x1.y; pv6=x1.z; pv7=x1.w;                           \
            pv8=x2.x; pv9=x2.y; pva=x2.z; pvb=x2.w;                           \
            pvc=x3.x; pvd=x3.y; pve=x3.z; pvf=x3.w;                           \
        } else {                                                              \
            const float* ar = A + (size_t)(m0 + arow) * KA;                   \
            int kb = (K0) + akh;                                              \
            pv0 = (kb+0 < KA) ? ar[kb+0] : 0.f;  pv1 = (kb+1 < KA) ? ar[kb+1] : 0.f; \
            pv2 = (kb+2 < KA) ? ar[kb+2] : 0.f;  pv3 = (kb+3 < KA) ? ar[kb+3] : 0.f; \
            pv4 = (kb+4 < KA) ? ar[kb+4] : 0.f;  pv5 = (kb+5 < KA) ? ar[kb+5] : 0.f; \
            pv6 = (kb+6 < KA) ? ar[kb+6] : 0.f;  pv7 = (kb+7 < KA) ? ar[kb+7] : 0.f; \
            pv8 = (kb+8 < KA) ? ar[kb+8] : 0.f;  pv9 = (kb+9 < KA) ? ar[kb+9] : 0.f; \
            pva = (kb+10 < KA) ? ar[kb+10] : 0.f; pvb = (kb+11 < KA) ? ar[kb+11] : 0.f; \
            pvc = (kb+12 < KA) ? ar[kb+12] : 0.f; pvd = (kb+13 < KA) ? ar[kb+13] : 0.f; \
            pve = (kb+14 < KA) ? ar[kb+14] : 0.f; pvf = (kb+15 < KA) ? ar[kb+15] : 0.f; \
        }                                                                     \
    } while (0)

#define SPLITPAIR(I, VA, VB)                                                  \
    do {                                                                      \
        float ra_ = (VA), rb_ = (VB);                                         \
        p0_[I] = prmt7632(__float_as_uint(ra_), __float_as_uint(rb_));        \
        ra_ -= trunchi(ra_); rb_ -= trunchi(rb_);                             \
        p1_[I] = prmt7632(__float_as_uint(ra_), __float_as_uint(rb_));        \
        ra_ -= trunchi(ra_); rb_ -= trunchi(rb_);                             \
        p2_[I] = prmt7632(__float_as_uint(ra_), __float_as_uint(rb_));        \
    } while (0)

#define QKV_STSA(STG)                                                         \
    do {                                                                      \
        char* bufc = smemraw + (size_t)(STG) * QSTG;                          \
        unsigned p0_[8], p1_[8], p2_[8];                                      \
        SPLITPAIR(0, pv0, pv1); SPLITPAIR(1, pv2, pv3);                       \
        SPLITPAIR(2, pv4, pv5); SPLITPAIR(3, pv6, pv7);                       \
        SPLITPAIR(4, pv8, pv9); SPLITPAIR(5, pva, pvb);                       \
        SPLITPAIR(6, pvc, pvd); SPLITPAIR(7, pve, pvf);                       \
        unsigned aoff = (unsigned)(arow * 64 + akh * 2);                      \
        unsigned alo = SW64OFF(aoff), ahi = SW64OFF(aoff + 16);               \
        *(uint4*)(bufc + alo)         = make_uint4(p0_[0], p0_[1], p0_[2], p0_[3]); \
        *(uint4*)(bufc + ahi)         = make_uint4(p0_[4], p0_[5], p0_[6], p0_[7]); \
        *(uint4*)(bufc + 8192 + alo)  = make_uint4(p1_[0], p1_[1], p1_[2], p1_[3]); \
        *(uint4*)(bufc + 8192 + ahi)  = make_uint4(p1_[4], p1_[5], p1_[6], p1_[7]); \
        *(uint4*)(bufc + 16384 + alo) = make_uint4(p2_[0], p2_[1], p2_[2], p2_[3]); \
        *(uint4*)(bufc + 16384 + ahi) = make_uint4(p2_[4], p2_[5], p2_[6], p2_[7]); \
    } while (0)

#define QKV_CPW(CH, STG)                                                      \
    do {                                                                      \
        unsigned wb = sb + (unsigned)((STG) * QSTG + 24576);                  \
        const int kk0 = (CH) << 5;                                            \
        _Pragma("unroll")                                                     \
        for (int i_ = 0; i_ < 6; i_++) {                                      \
            int u_ = tid + 256 * i_;                                          \
            int sp_ = u_ >> 9, row_ = (u_ >> 2) & 127, c_ = u_ & 3;           \
            unsigned d_ = wb + sp_ * 8192 +                                   \
                          SW64OFF((unsigned)(row_ * 64 + c_ * 16));           \
            cpa16(d_, gW + ((size_t)sp_ * 512 + n0 + row_) * 512 + kk0 + c_ * 8); \
        }                                                                     \
        CP_COMMIT();                                                          \
    } while (0)

__global__ __launch_bounds__(256, 1) void qkv_mma_kernel(
    const float* __restrict__ Aq, const float* __restrict__ Ak,
    const float* __restrict__ Av,
    const float* __restrict__ bq, const float* __restrict__ bk,
    const float* __restrict__ bv, int DIN)
{
    extern __shared__ char smemraw[];   // 3 x QSTG

    const int tid  = threadIdx.x;
    const int lane = tid & 31;
    const int g    = lane >> 2, tg = lane & 3;
    const int wrp  = tid >> 5;
    const int mw   = wrp >> 1, nw = wrp & 1;

    int idx = blockIdx.x;
    int which = idx >> 8;                      // 0=k,1=v,2=q
    int s2 = idx & 255;
    int n0 = (s2 & 3) * 128, m0 = (s2 >> 2) * 128;

    const float* A    = (which == 0) ? Ak : (which == 1) ? Av : Aq;
    const float* bias = (which == 0) ? bk : (which == 1) ? bv : bq;
    const int KA = DIN;
    const int KS = (which == 2) ? 128 : DD;
    const int wsel = (which == 0) ? 1 : (which == 1) ? 2 : 0;
    const unsigned short* gW = g_wsp + (size_t)wsel * 3 * 512 * 512;

    const unsigned sb = (unsigned)__cvta_generic_to_shared(smemraw);

    float C[2][8][4];
#pragma unroll
    for (int mt = 0; mt < 2; mt++)
#pragma unroll
        for (int nt = 0; nt < 8; nt++)
#pragma unroll
            for (int r = 0; r < 4; r++) C[mt][nt][r] = 0.f;

    const int arow = tid >> 1, akh = (tid & 1) * 16;
    const int arow_l = lane & 15;
    const int ak16b = (lane >> 4) * 16;
    const int brow = (lane & 7) + ((lane & 16) >> 1);
    const int bk16b = (lane & 8) * 2;

    float pv0,pv1,pv2,pv3,pv4,pv5,pv6,pv7,pv8,pv9,pva,pvb,pvc,pvd,pve,pvf;

    const int nch = KS >> 5;

    QKV_LOAD_A(0);
    QKV_CPW(0, 0);
    QKV_STSA(0);
    if (nch > 1) {
        QKV_LOAD_A(32);
        QKV_CPW(1, 1);
        QKV_STSA(1);
    }
    if (nch > 2) QKV_LOAD_A(64);

    for (int ch = 0; ch < nch; ++ch) {
        const int stg = ch % 3;
        if (ch + 1 < nch) { CP_WAIT(1); } else { CP_WAIT(0); }
        __syncthreads();
        if (ch + 2 < nch) {
            QKV_CPW(ch + 2, (ch + 2) % 3);
            QKV_STSA((ch + 2) % 3);
            if (ch + 3 < nch) QKV_LOAD_A((ch + 3) << 5);
        }
        const unsigned abuf = sb + (unsigned)(stg * QSTG);
        const unsigned wbuf = abuf + 24576;
#pragma unroll
        for (int s = 0; s < 2; ++s) {
            unsigned af[3][2][4];
#pragma unroll
            for (int sp = 0; sp < 3; sp++)
#pragma unroll
                for (int mt = 0; mt < 2; mt++) {
                    unsigned a = abuf + sp * 8192 +
                        SW64OFF((unsigned)((mw * 32 + mt * 16 + arow_l) * 64 +
                                           s * 32 + ak16b));
                    ldsm4(af[sp][mt][0], af[sp][mt][1], af[sp][mt][2], af[sp][mt][3], a);
                }
#pragma unroll
            for (int j = 0; j < 3; j++) {
                unsigned bfr[4][4];
#pragma unroll
                for (int np = 0; np < 4; np++) {
                    unsigned a = wbuf + j * 8192 +
                        SW64OFF((unsigned)((nw * 64 + np * 16 + brow) * 64 +
                                           s * 32 + bk16b));
                    ldsm4(bfr[np][0], bfr[np][1], bfr[np][2], bfr[np][3], a);
                }
#pragma unroll
                for (int i = 0; i < 3; i++) {
                    if (i + j > 2) break;
#pragma unroll
                    for (int mt = 0; mt < 2; mt++)
#pragma unroll
                        for (int np = 0; np < 4; np++) {
                            mma_bf16(C[mt][np * 2], af[i][mt][0], af[i][mt][1],
                                     af[i][mt][2], af[i][mt][3],
                                     bfr[np][0], bfr[np][1]);
                            mma_bf16(C[mt][np * 2 + 1], af[i][mt][0], af[i][mt][1],
                                     af[i][mt][2], af[i][mt][3],
                                     bfr[np][2], bfr[np][3]);
                        }
                }
            }
        }
    }

    __syncthreads();
    unsigned char* sbyte = (unsigned char*)smemraw;   // [128][128]
#pragma unroll
    for (int mt = 0; mt < 2; mt++)
#pragma unroll
        for (int nt = 0; nt < 8; nt++) {
            int row = mw * 32 + mt * 16 + g;
            int col = nw * 64 + nt * 8 + tg * 2;
            float2 bb = *(const float2*)&bias[n0 + col];
            sbyte[row * 128 + col]           = (C[mt][nt][0] + bb.x >= 1.0f) ? 1 : 0;
            sbyte[row * 128 + col + 1]       = (C[mt][nt][1] + bb.y >= 1.0f) ? 1 : 0;
            sbyte[(row + 8) * 128 + col]     = (C[mt][nt][2] + bb.x >= 1.0f) ? 1 : 0;
            sbyte[(row + 8) * 128 + col + 1] = (C[mt][nt][3] + bb.y >= 1.0f) ? 1 : 0;
        }
    __syncthreads();
    {
        int row = tid >> 1, hf = tid & 1;
        unsigned long long bits = 0ull;
#pragma unroll
        for (int q = 0; q < 8; q++) {
            unsigned long long u =
                *(const unsigned long long*)&sbyte[row * 128 + hf * 64 + 8 * q];
#pragma unroll
            for (int j = 0; j < 8; j++)
                bits |= ((u >> (8 * j)) & 1ull) << (8 * q + j);
        }
        int m = m0 + row;
        int b = m >> 11, t = m & 2047;
        int head = (n0 >> 6) + hf;
        unsigned long long* dst = (which == 2) ? g_qb : (which == 0) ? g_kb : g_vb;
        dst[(size_t)((b << 3) + head) * TT + t] = bits;
    }
}

// =====================================================================
// Fused bit-transpose + KV precompute (verbatim from 260.1us run).
// =====================================================================
__global__ __launch_bounds__(128) void transkv_kernel()
{
    __shared__ unsigned sh[2][64][2];
    __shared__ unsigned long long vTs[64], kTs[64];

    const int tid = threadIdx.x;
    const int lane = tid & 31;
    int bh = blockIdx.x >> 5, w = blockIdx.x & 31;

    {
        int which = tid >> 6;               // 0=v, 1=k
        int r = tid & 63;
        int half = (tid >> 5) & 1;
        const unsigned long long* src = which ? g_kb : g_vb;
        unsigned long long row = src[(size_t)bh * TT + w * 64 + r];
#pragma unroll 8
        for (int d = 0; d < 64; d++) {
            unsigned b = __ballot_sync(0xffffffffu, (unsigned)((row >> d) & 1ull));
            if (lane == 0) sh[which][d][half] = b;
        }
        __syncthreads();
        unsigned long long val = (unsigned long long)sh[which][r][0] |
                                 ((unsigned long long)sh[which][r][1] << 32);
        if (which == 0) {
            vTs[r] = val;
            g_vT[((size_t)bh * 64 + r) * 32 + w] = val;
        } else {
            kTs[r] = val;
        }
    }
    __syncthreads();

    const int g = lane >> 2, tg = lane & 3;
    const int wr16 = (tid >> 5) * 16;

    unsigned long long vd0 = vTs[wr16 + g];
    unsigned long long vd1 = vTs[wr16 + 8 + g];
    unsigned long long kt[8];
#pragma unroll
    for (int nt = 0; nt < 8; nt++) kt[nt] = kTs[nt * 8 + g];

    int acc[8][4];
#pragma unroll
    for (int nt = 0; nt < 8; nt++)
#pragma unroll
        for (int r = 0; r < 4; r++) acc[nt][r] = 0;

#pragma unroll
    for (int s = 0; s < 2; s++) {
        unsigned l0 = (unsigned)(vd0 >> (32 * s));
        unsigned l1 = (unsigned)(vd1 >> (32 * s));
        unsigned a0 = expand4((l0 >> (4 * tg)) & 0xFu);
        unsigned a1 = expand4((l1 >> (4 * tg)) & 0xFu);
        unsigned a2 = expand4((l0 >> (16 + 4 * tg)) & 0xFu);
        unsigned a3 = expand4((l1 >> (16 + 4 * tg)) & 0xFu);
#pragma unroll
        for (int nt = 0; nt < 8; nt++) {
            unsigned kl = (unsigned)(kt[nt] >> (32 * s));
            unsigned b0 = expand4((kl >> (4 * tg)) & 0xFu);
            unsigned b1 = expand4((kl >> (16 + 4 * tg)) & 0xFu);
            mma_s8(acc[nt], a0, a1, a2, a3, b0, b1);
        }
    }

    unsigned char* dst = g_kv + ((size_t)(bh * 32 + w) * 64) * 64;
#pragma unroll
    for (int nt = 0; nt < 8; nt++) {
        int j0 = nt * 8 + 2 * tg;
        *(unsigned short*)(dst + (wr16 + g) * 64 + j0) =
            (unsigned short)((acc[nt][0] & 0xFF) | ((acc[nt][1] & 0xFF) << 8));
        *(unsigned short*)(dst + (wr16 + 8 + g) * 64 + j0) =
            (unsigned short)((acc[nt][2] & 0xFF) | ((acc[nt][3] & 0xFF) << 8));
    }
}

// =====================================================================
// Attention: TWO q-tiles (2p, 2p+1) per block sharing the KV stream.
// Integer-exact (s32 accumulation) -> order-free, bit-identical results.
// =====================================================================
#define QA_FRAGS(QA, R0, R1)                                                  \
    do {                                                                      \
        _Pragma("unroll")                                                     \
        for (int s_ = 0; s_ < 2; s_++) {                                      \
            unsigned l0_ = (unsigned)((R0) >> (32 * s_));                     \
            unsigned l1_ = (unsigned)((R1) >> (32 * s_));                     \
            QA[s_][0] = expand4((l0_ >> (4 * tg)) & 0xFu);                    \
            QA[s_][1] = expand4((l1_ >> (4 * tg)) & 0xFu);                    \
            QA[s_][2] = expand4((l0_ >> (16 + 4 * tg)) & 0xFu);               \
            QA[s_][3] = expand4((l1_ >> (16 + 4 * tg)) & 0xFu);               \
        }                                                                     \
    } while (0)

#define ATTN_DIAG(TQ, QA, ACC)                                                \
    do {                                                                      \
        __syncthreads();                                                      \
        if (tid < 64) ksh[tid] = g_kb[base + (size_t)(TQ) * 64 + tid];        \
        unsigned long long vt_[8];                                            \
        _Pragma("unroll")                                                     \
        for (int nt = 0; nt < 8; nt++)                                        \
            vt_[nt] = g_vT[((size_t)bh * 64 + nt * 8 + g) * 32 + (TQ)];       \
        __syncthreads();                                                      \
        unsigned long long kk[8];                                             \
        _Pragma("unroll")                                                     \
        for (int nt = 0; nt < 8; nt++) kk[nt] = ksh[nt * 8 + g];              \
        int qcc[8][4];                                                        \
        _Pragma("unroll")                                                     \
        for (int nt = 0; nt < 8; nt++)                                        \
            { qcc[nt][0]=0; qcc[nt][1]=0; qcc[nt][2]=0; qcc[nt][3]=0; }       \
        _Pragma("unroll")                                                     \
        for (int s = 0; s < 2; s++)                                           \
            _Pragma("unroll")                                                 \
            for (int nt = 0; nt < 8; nt++) {                                  \
                unsigned kl = (unsigned)(kk[nt] >> (32 * s));                 \
                unsigned b0 = expand4((kl >> (4 * tg)) & 0xFu);               \
                unsigned b1 = expand4((kl >> (16 + 4 * tg)) & 0xFu);          \
                mma_s8(qcc[nt], QA[s][0], QA[s][1], QA[s][2], QA[s][3], b0, b1); \
            }                                                                 \
        int t0_ = rowA, t1_ = rowA + 8;                                       \
        _Pragma("unroll")                                                     \
        for (int nt = 0; nt < 8; nt++) {                                      \
            int kc = nt * 8 + 2 * tg;                                         \
            unsigned v00 = (kc <= t0_) ? (qcc[nt][0] & 0xFF) : 0u;            \
            unsigned v01 = (kc + 1 <= t0_) ? (qcc[nt][1] & 0xFF) : 0u;        \
            unsigned v10 = (kc <= t1_) ? (qcc[nt][2] & 0xFF) : 0u;            \
            unsigned v11 = (kc + 1 <= t1_) ? (qcc[nt][3] & 0xFF) : 0u;        \
            *(unsigned short*)&csh[t0_ * 68 + kc] = (unsigned short)(v00 | (v01 << 8)); \
            *(unsigned short*)&csh[t1_ * 68 + kc] = (unsigned short)(v10 | (v11 << 8)); \
        }                                                                     \
        __syncwarp();                                                         \
        _Pragma("unroll")                                                     \
        for (int s = 0; s < 2; s++) {                                         \
            unsigned a0 = *(const unsigned*)&csh[rowA * 68 + s * 32 + tg * 4]; \
            unsigned a1 = *(const unsigned*)&csh[(rowA + 8) * 68 + s * 32 + tg * 4]; \
            unsigned a2 = *(const unsigned*)&csh[rowA * 68 + s * 32 + 16 + tg * 4]; \
            unsigned a3 = *(const unsigned*)&csh[(rowA + 8) * 68 + s * 32 + 16 + tg * 4]; \
            _Pragma("unroll")                                                 \
            for (int nt = 0; nt < 8; nt++) {                                  \
                unsigned b0 = expand4((unsigned)(vt_[nt] >> (s * 32 + tg * 4)) & 0xFu); \
                unsigned b1 = expand4((unsigned)(vt_[nt] >> (s * 32 + 16 + tg * 4)) & 0xFu); \
                mma_s8(ACC[nt], a0, a1, a2, a3, b0, b1);                      \
            }                                                                 \
        }                                                                     \
    } while (0)

#define ATTN_EPI(TQ, ACC)                                                     \
    do {                                                                      \
        __syncthreads();                                                      \
        _Pragma("unroll")                                                     \
        for (int nt = 0; nt < 8; ++nt) {                                      \
            int d0 = nt * 8 + tg * 2;                                         \
            csh[d0 * 68 + rowA]           = ((float)ACC[nt][0] * scale >= 1.0f) ? 1 : 0; \
            csh[(d0 + 1) * 68 + rowA]     = ((float)ACC[nt][1] * scale >= 1.0f) ? 1 : 0; \
            csh[d0 * 68 + rowA + 8]       = ((float)ACC[nt][2] * scale >= 1.0f) ? 1 : 0; \
            csh[(d0 + 1) * 68 + rowA + 8] = ((float)ACC[nt][3] * scale >= 1.0f) ? 1 : 0; \
        }                                                                     \
        __syncthreads();                                                      \
        {                                                                     \
            int d = tid >> 1, hf = tid & 1;                                   \
            size_t b_ = (size_t)(bh >> 3), h_ = (size_t)(bh & 7);             \
            size_t off = (b_ << 20) + (h_ << 17) + ((size_t)d << 11)          \
                       + (size_t)(TQ) * 64 + (size_t)hf * 32;                 \
            _Pragma("unroll")                                                 \
            for (int q4 = 0; q4 < 32; q4 += 4) {                              \
                unsigned v = *(const unsigned*)&csh[d * 68 + hf * 32 + q4];   \
                *(unsigned*)(g_xs + off + q4) = v;                            \
            }                                                                 \
        }                                                                     \
    } while (0)

__global__ __launch_bounds__(128) void attn_kernel(const float* __restrict__ scale_p)
{
    __shared__ __align__(16) unsigned char KVsh[2][64 * 80];
    __shared__ unsigned char csh[64 * 68];
    __shared__ unsigned long long ksh[64];

    const int tid = threadIdx.x;
    const int lane = tid & 31;
    const int g = lane >> 2, tg = lane & 3;
    const int wr16 = (tid >> 5) * 16;
    const int rowA = wr16 + g;

    int bx = blockIdx.x;                  // 512
    int bh = bx & 31;
    int p = 15 - (bx >> 5);               // big pairs first
    const int tq0 = 2 * p, tq1 = 2 * p + 1;

    const float scale = *scale_p;
    const size_t base = (size_t)bh * TT;
    const unsigned char* KVg = g_kv + (size_t)bh * 32 * 64 * 64;

    // q fragments for both tiles
    unsigned qa0[2][4], qa1[2][4];
    {
        unsigned long long r0 = g_qb[base + (size_t)tq0 * 64 + rowA];
        unsigned long long r1 = g_qb[base + (size_t)tq0 * 64 + rowA + 8];
        QA_FRAGS(qa0, r0, r1);
        r0 = g_qb[base + (size_t)tq1 * 64 + rowA];
        r1 = g_qb[base + (size_t)tq1 * 64 + rowA + 8];
        QA_FRAGS(qa1, r0, r1);
    }

    int acc0[8][4], acc1[8][4];
#pragma unroll
    for (int nt = 0; nt < 8; nt++)
#pragma unroll
        for (int r = 0; r < 4; r++) { acc0[nt][r] = 0; acc1[nt][r] = 0; }

    const int kvrow0 = tid >> 2, kvp0 = tid & 3;
    const int kvrow1 = (tid + 128) >> 2, kvp1 = tid & 3;
    const unsigned kvb0 = (unsigned)__cvta_generic_to_shared(&KVsh[0][0]);
    const unsigned kvb1 = (unsigned)__cvta_generic_to_shared(&KVsh[1][0]);

    // ---- shared off-diag stream: w = 0 .. tq1-1 (w=tq0 feeds acc1 only) ----
    {
        cpa16(kvb0 + kvrow0 * 80 + kvp0 * 16, KVg + kvrow0 * 64 + kvp0 * 16);
        cpa16(kvb0 + kvrow1 * 80 + kvp1 * 16, KVg + kvrow1 * 64 + kvp1 * 16);
        CP_COMMIT();
    }
    for (int w = 0; w < tq1; ++w) {
        __syncthreads();
        if (w + 1 < tq1) {
            unsigned kb = ((w + 1) & 1) ? kvb1 : kvb0;
            const unsigned char* src = KVg + (size_t)(w + 1) * 4096;
            cpa16(kb + kvrow0 * 80 + kvp0 * 16, src + kvrow0 * 64 + kvp0 * 16);
            cpa16(kb + kvrow1 * 80 + kvp1 * 16, src + kvrow1 * 64 + kvp1 * 16);
            CP_COMMIT();
            CP_WAIT(1);
        } else {
            CP_WAIT(0);
        }
        __syncthreads();
        const unsigned char* kb = KVsh[w & 1];
        const bool both = (w < tq0);
#pragma unroll
        for (int s = 0; s < 2; s++)
#pragma unroll
            for (int nt = 0; nt < 8; nt++) {
                unsigned b0 = *(const unsigned*)(kb + (nt * 8 + g) * 80 + s * 32 + tg * 4);
                unsigned b1 = *(const unsigned*)(kb + (nt * 8 + g) * 80 + s * 32 + 16 + tg * 4);
                mma_s8(acc1[nt], qa1[s][0], qa1[s][1], qa1[s][2], qa1[s][3], b0, b1);
                if (both)
                    mma_s8(acc0[nt], qa0[s][0], qa0[s][1], qa0[s][2], qa0[s][3], b0, b1);
            }
    }

    // ---- diagonals ----
    ATTN_DIAG(tq0, qa0, acc0);
    ATTN_DIAG(tq1, qa1, acc1);

    // ---- epilogues ----
    ATTN_EPI(tq0, acc0);
    ATTN_EPI(tq1, acc1);
}

// =====================================================================
// Output projection (verbatim from the 260.1us run).
// =====================================================================
#define OUT_LOAD_A(K0)                                                        \
    do {                                                                      \
        pa = *(const uint4*)(g_xs + (size_t)(m0 + xrow) * DD + (K0) + xhalf * 16); \
    } while (0)

#define OUT_STSA(STG)                                                         \
    do {                                                                      \
        char* bufc = smemraw + (size_t)(STG) * OSTG;                          \
        unsigned w0 = pa.x, w1 = pa.y, w2 = pa.z, w3 = pa.w;                  \
        uint4 o0, o1;                                                         \
        o0.x = ((w0 & 1u) ? 0x3F80u : 0u) | ((w0 & 0x100u) ? 0x3F800000u : 0u); \
        o0.y = (((w0 >> 16) & 1u) ? 0x3F80u : 0u) | ((w0 & 0x1000000u) ? 0x3F800000u : 0u); \
        o0.z = ((w1 & 1u) ? 0x3F80u : 0u) | ((w1 & 0x100u) ? 0x3F800000u : 0u); \
        o0.w = (((w1 >> 16) & 1u) ? 0x3F80u : 0u) | ((w1 & 0x1000000u) ? 0x3F800000u : 0u); \
        o1.x = ((w2 & 1u) ? 0x3F80u : 0u) | ((w2 & 0x100u) ? 0x3F800000u : 0u); \
        o1.y = (((w2 >> 16) & 1u) ? 0x3F80u : 0u) | ((w2 & 0x1000000u) ? 0x3F800000u : 0u); \
        o1.z = ((w3 & 1u) ? 0x3F80u : 0u) | ((w3 & 0x100u) ? 0x3F800000u : 0u); \
        o1.w = (((w3 >> 16) & 1u) ? 0x3F80u : 0u) | ((w3 & 0x1000000u) ? 0x3F800000u : 0u); \
        unsigned base_ = (unsigned)(xrow * 64 + xhalf * 32);                  \
        *(uint4*)(bufc + SW64OFF(base_))      = o0;                           \
        *(uint4*)(bufc + SW64OFF(base_ + 16)) = o1;                           \
    } while (0)

#define OUT_CPW(CH, STG)                                                      \
    do {                                                                      \
        unsigned wb = sb + (unsigned)((STG) * OSTG + 8192);                   \
        const int kk0 = (CH) << 5;                                            \
        _Pragma("unroll")                                                     \
        for (int i_ = 0; i_ < 6; i_++) {                                      \
            int u_ = tid + 256 * i_;                                          \
            int sp_ = u_ >> 9, row_ = (u_ >> 2) & 127, c_ = u_ & 3;           \
            unsigned d_ = wb + sp_ * 8192 +                                   \
                          SW64OFF((unsigned)(row_ * 64 + c_ * 16));           \
            cpa16(d_, gW + ((size_t)sp_ * 512 + n0 + row_) * 512 + kk0 + c_ * 8); \
        }                                                                     \
        CP_COMMIT();                                                          \
    } while (0)

__global__ __launch_bounds__(256, 1) void out_mma_kernel(
    const float* __restrict__ bias, float* __restrict__ out)
{
    extern __shared__ char smemraw[];   // 3 x OSTG

    const int tid  = threadIdx.x;
    const int lane = tid & 31;
    const int g    = lane >> 2, tg = lane & 3;
    const int wrp  = tid >> 5;
    const int mw   = wrp >> 1, nw = wrp & 1;

    int s2 = blockIdx.x;
    int n0 = (s2 & 3) * 128, m0 = (s2 >> 2) * 128;

    const unsigned short* gW = g_wsp + (size_t)3 * 3 * 512 * 512;   // Wo
    const unsigned sb = (unsigned)__cvta_generic_to_shared(smemraw);

    float C[2][8][4];
#pragma unroll
    for (int mt = 0; mt < 2; mt++)
#pragma unroll
        for (int nt = 0; nt < 8; nt++)
#pragma unroll
            for (int r = 0; r < 4; r++) C[mt][nt][r] = 0.f;

    const int xrow = tid >> 1, xhalf = tid & 1;
    const int arow_l = lane & 15;
    const int ak16b = (lane >> 4) * 16;
    const int brow = (lane & 7) + ((lane & 16) >> 1);
    const int bk16b = (lane & 8) * 2;

    uint4 pa;

    OUT_LOAD_A(0);
    OUT_CPW(0, 0);
    OUT_STSA(0);
    OUT_LOAD_A(32);
    OUT_CPW(1, 1);
    OUT_STSA(1);
    OUT_LOAD_A(64);

    for (int ch = 0; ch < 16; ++ch) {
        const int stg = ch % 3;
        if (ch + 1 < 16) { CP_WAIT(1); } else { CP_WAIT(0); }
        __syncthreads();
        if (ch + 2 < 16) {
            OUT_CPW(ch + 2, (ch + 2) % 3);
            OUT_STSA((ch + 2) % 3);
            if (ch + 3 < 16) OUT_LOAD_A((ch + 3) << 5);
        }
        const unsigned abuf = sb + (unsigned)(stg * OSTG);
        const unsigned wbuf = abuf + 8192;
#pragma unroll
        for (int s = 0; s < 2; ++s) {
            unsigned af[2][4];
#pragma unroll
            for (int mt = 0; mt < 2; mt++) {
                unsigned a = abuf +
                    SW64OFF((unsigned)((mw * 32 + mt * 16 + arow_l) * 64 +
                                       s * 32 + ak16b));
                ldsm4(af[mt][0], af[mt][1], af[mt][2], af[mt][3], a);
            }
#pragma unroll
            for (int j = 0; j < 3; j++) {
                unsigned bfr[4][4];
#pragma unroll
                for (int np = 0; np < 4; np++) {
                    unsigned a = wbuf + j * 8192 +
                        SW64OFF((unsigned)((nw * 64 + np * 16 + brow) * 64 +
                                           s * 32 + bk16b));
                    ldsm4(bfr[np][0], bfr[np][1], bfr[np][2], bfr[np][3], a);
                }
#pragma unroll
                for (int mt = 0; mt < 2; mt++)
#pragma unroll
                    for (int np = 0; np < 4; np++) {
                        mma_bf16(C[mt][np * 2], af[mt][0], af[mt][1], af[mt][2],
                                 af[mt][3], bfr[np][0], bfr[np][1]);
                        mma_bf16(C[mt][np * 2 + 1], af[mt][0], af[mt][1], af[mt][2],
                                 af[mt][3], bfr[np][2], bfr[np][3]);
                    }
            }
        }
    }

#pragma unroll
    for (int mt = 0; mt < 2; mt++)
#pragma unroll
        for (int nt = 0; nt < 8; nt++) {
            int row = m0 + mw * 32 + mt * 16 + g;
            int col = n0 + nw * 64 + nt * 8 + tg * 2;
            float2 bb = *(const float2*)&bias[col];
            float2 r0, r1;
            r0.x = (C[mt][nt][0] + bb.x >= 1.0f) ? 1.0f : 0.0f;
            r0.y = (C[mt][nt][1] + bb.y >= 1.0f) ? 1.0f : 0.0f;
            r1.x = (C[mt][nt][2] + bb.x >= 1.0f) ? 1.0f : 0.0f;
            r1.y = (C[mt][nt][3] + bb.y >= 1.0f) ? 1.0f : 0.0f;
            *(float2*)&out[(size_t)row * DD + col] = r0;
            *(float2*)&out[(size_t)(row + 8) * DD + col] = r1;
        }
}

// ---------------- launch ----------------
extern "C" void kernel_launch(void* const* d_in, const int* in_sizes, int n_in,
                              void* d_out, int out_size)
{
    const float* query = (const float*)d_in[0];
    const float* key   = (const float*)d_in[1];
    const float* value = (const float*)d_in[2];
    const float* scale = (const float*)d_in[3];
    const float* Wq = (const float*)d_in[4];  const float* bq = (const float*)d_in[5];
    const float* Wk = (const float*)d_in[6];  const float* bk = (const float*)d_in[7];
    const float* Wv = (const float*)d_in[8];  const float* bv = (const float*)d_in[9];
    const float* Wo = (const float*)d_in[10]; const float* bo = (const float*)d_in[11];
    float* out = (float*)d_out;

    const int DIN = in_sizes[0] / MROWS;   // 100

    cudaFuncSetAttribute(qkv_mma_kernel,
                         cudaFuncAttributeMaxDynamicSharedMemorySize, QKV_SMEM);
    cudaFuncSetAttribute(out_mma_kernel,
                         cudaFuncAttributeMaxDynamicSharedMemorySize, OUT_SMEM);

    prep_w_kernel<<<dim3(8, 8, 4), 256>>>(Wq, Wk, Wv, Wo);
    qkv_mma_kernel<<<768, 256, QKV_SMEM>>>(query, key, value, bq, bk, bv, DIN);
    transkv_kernel<<<BHN * NTW, 128>>>();
    attn_kernel<<<BHN * (NTW / 2), 128>>>(scale);
    out_mma_kernel<<<256, 256, OUT_SMEM>>>(bo, out);
}